// round 5
// baseline (speedup 1.0000x reference)
#include <cuda_runtime.h>
#include <cuda_bf16.h>
#include <math.h>
#include <float.h>
#include <stdint.h>

// ---------------- problem constants ----------------
#define DIMX 2048
#define NSEQ 2048
#define BATCH 2
#define HEADS 16
#define DHEAD 64
#define ROWS (BATCH*NSEQ)          // 4096
#define AINNER 1024
#define FFINNER 8192
#define FUSEDC 17536               // 1024+64+64+2*8192
#define FPAD 17664                 // 138*128
#define I0 1024
#define I1 1088
#define I2 1152

// ---------------- scratch (device globals) --------
__device__ float g_XN[(size_t)ROWS*DIMX];
__device__ float g_WF[(size_t)DIMX*FPAD];        // rounded+padded w_fused
__device__ float g_F[(size_t)ROWS*FPAD];
__device__ float g_XA[ROWS*24];
__device__ float g_Q[(size_t)ROWS*AINNER];
__device__ float g_K[(size_t)ROWS*DHEAD];
__device__ float g_V[(size_t)ROWS*DHEAD];
__device__ float g_OATTN[(size_t)ROWS*AINNER];
__device__ float g_WAO[(size_t)AINNER*DIMX];
__device__ float g_H[(size_t)ROWS*FFINNER];
__device__ float g_WFF[(size_t)FFINNER*DIMX];
__device__ float g_OA[ROWS*8];

// ---------------- small helpers ----------------
__device__ __forceinline__ float tf32r(float x) {
    uint32_t u;
    asm("cvt.rna.tf32.f32 %0, %1;" : "=r"(u) : "f"(x));
    return __uint_as_float(u);
}
__device__ __forceinline__ uint32_t smem_u32(const void* p) {
    uint32_t a;
    asm("{ .reg .u64 t; cvta.to.shared.u64 t, %1; cvt.u32.u64 %0, t; }" : "=r"(a) : "l"(p));
    return a;
}
__device__ __forceinline__ void cp16(uint32_t saddr, const void* g) {
    asm volatile("cp.async.cg.shared.global [%0], [%1], 16;" :: "r"(saddr), "l"(g) : "memory");
}
__device__ __forceinline__ void mma_tf32(float* d, const uint32_t* a, const uint32_t* b) {
    asm volatile(
        "mma.sync.aligned.m16n8k8.row.col.f32.tf32.tf32.f32 "
        "{%0,%1,%2,%3}, {%4,%5,%6,%7}, {%8,%9}, {%0,%1,%2,%3};"
        : "+f"(d[0]), "+f"(d[1]), "+f"(d[2]), "+f"(d[3])
        : "r"(a[0]), "r"(a[1]), "r"(a[2]), "r"(a[3]), "r"(b[0]), "r"(b[1]));
}

// ================= TF32 GEMM =================
// C[M,N] = A[M,K] @ B[K,N] (+= if accum). All fp32 memory (pre-rounded to tf32).
// 256x128x16 CTA tile, 256 thr, 8 warps (4m x 2n), warp tile 64x64, 3-stage cp.async.
#define GSTAGES 3
#define AST 20            // A smem row stride (words), row=m (256 rows x 16 k)
#define BST 136           // B smem row stride (words), row=k (16 rows x 128 n)
#define AWORDS (256*AST)  // 5120
#define BWORDS (16*BST)   // 2176
#define STW (AWORDS+BWORDS)   // 7296 words per stage
#define GSMEM (GSTAGES*STW*4) // 87552 bytes

__global__ __launch_bounds__(256, 1) void tf32_gemm(const float* __restrict__ A,
                                                    const float* __restrict__ B,
                                                    float* __restrict__ C,
                                                    int N, int K, int accum) {
    extern __shared__ float smem[];
    const int tid = threadIdx.x;
    const int wid = tid >> 5, lane = tid & 31;
    const int wm = (wid & 3) * 64, wn = (wid >> 2) * 64;
    const int m0 = blockIdx.x * 256, n0 = blockIdx.y * 128;
    const float* Ag = A + (size_t)m0 * K;
    const float* Bg = B + n0;
    const uint32_t sb = smem_u32(smem);

    const int arow = tid >> 2, ak4 = (tid & 3) * 4;
    const int brow = tid >> 5, bn4 = (tid & 31) * 4;
    const int NK = K >> 4;

    auto load_stage = [&](int kt, int s) {
        const uint32_t sa = sb + s * STW * 4;
        const uint32_t sB = sa + AWORDS * 4;
        const float* ag = Ag + kt * 16;
        const float* bg = Bg + (size_t)(kt * 16) * N;
#pragma unroll
        for (int i = 0; i < 4; i++) {
            int r = arow + i * 64;
            cp16(sa + (r * AST + ak4) * 4, ag + (size_t)r * K + ak4);
        }
#pragma unroll
        for (int i = 0; i < 2; i++) {
            int kr = brow + i * 8;
            cp16(sB + (kr * BST + bn4) * 4, bg + (size_t)kr * N + bn4);
        }
    };

    float acc[4][8][4];
#pragma unroll
    for (int mt = 0; mt < 4; mt++)
#pragma unroll
        for (int nt = 0; nt < 8; nt++)
#pragma unroll
            for (int i = 0; i < 4; i++) acc[mt][nt][i] = 0.f;

    load_stage(0, 0);
    asm volatile("cp.async.commit_group;" ::: "memory");
    load_stage(1, 1);
    asm volatile("cp.async.commit_group;" ::: "memory");

#pragma unroll 1
    for (int kt = 0; kt < NK; kt++) {
        asm volatile("cp.async.wait_group 1;" ::: "memory");
        __syncthreads();
        if (kt + 2 < NK) load_stage(kt + 2, (kt + 2) % GSTAGES);
        asm volatile("cp.async.commit_group;" ::: "memory");

        const int s = kt % GSTAGES;
        const float* As = smem + s * STW;
        const float* Bs = As + AWORDS;
#pragma unroll
        for (int c8 = 0; c8 < 2; c8++) {
            const int c = c8 * 8;
            uint32_t a[4][4], b[8][2];
            const int kk = c + (lane & 3);
#pragma unroll
            for (int mt = 0; mt < 4; mt++) {
                int r = wm + mt * 16 + (lane >> 2);
                a[mt][0] = __float_as_uint(As[r * AST + kk]);
                a[mt][1] = __float_as_uint(As[(r + 8) * AST + kk]);
                a[mt][2] = __float_as_uint(As[r * AST + kk + 4]);
                a[mt][3] = __float_as_uint(As[(r + 8) * AST + kk + 4]);
            }
#pragma unroll
            for (int nt = 0; nt < 8; nt++) {
                int n = wn + nt * 8 + (lane >> 2);
                b[nt][0] = __float_as_uint(Bs[kk * BST + n]);
                b[nt][1] = __float_as_uint(Bs[(kk + 4) * BST + n]);
            }
#pragma unroll
            for (int mt = 0; mt < 4; mt++)
#pragma unroll
                for (int nt = 0; nt < 8; nt++)
                    mma_tf32(acc[mt][nt], a[mt], b[nt]);
        }
    }

    // epilogue
    const int rbase = m0 + wm + (lane >> 2);
    const int cbase = n0 + wn + (lane & 3) * 2;
#pragma unroll
    for (int mt = 0; mt < 4; mt++) {
#pragma unroll
        for (int nt = 0; nt < 8; nt++) {
            int r = rbase + mt * 16;
            int cc = cbase + nt * 8;
            float2* p0 = (float2*)(C + (size_t)r * N + cc);
            float2* p1 = (float2*)(C + (size_t)(r + 8) * N + cc);
            float2 v0 = make_float2(acc[mt][nt][0], acc[mt][nt][1]);
            float2 v1 = make_float2(acc[mt][nt][2], acc[mt][nt][3]);
            if (accum) {
                float2 o0 = *p0, o1 = *p1;
                v0.x += o0.x; v0.y += o0.y; v1.x += o1.x; v1.y += o1.y;
            }
            *p0 = v0; *p1 = v1;
        }
    }
}

// ---------------- weight rounding (+ column pad) ----------------
__global__ void round_pad(const float* __restrict__ in, float* __restrict__ out,
                          int Nin4, int Nout4) {
    int row = blockIdx.y;
    int c4 = blockIdx.x * 256 + threadIdx.x;
    if (c4 >= Nout4) return;
    float4 v = make_float4(0.f, 0.f, 0.f, 0.f);
    if (c4 < Nin4) {
        v = ((const float4*)(in + (size_t)row * Nin4 * 4))[c4];
        v.x = tf32r(v.x); v.y = tf32r(v.y); v.z = tf32r(v.z); v.w = tf32r(v.w);
    }
    ((float4*)(out + (size_t)row * Nout4 * 4))[c4] = v;
}

// ---------------- layernorm (tf32-rounded out) ----------------
__global__ void ln_kernel(const float* __restrict__ x, const float* __restrict__ gamma,
                          float* __restrict__ xn) {
    int row = blockIdx.x;
    const float* xr = x + (size_t)row * DIMX;
    float s = 0.f, s2 = 0.f;
    for (int i = threadIdx.x; i < DIMX; i += 256) { float v = xr[i]; s += v; s2 += v * v; }
    for (int o = 16; o > 0; o >>= 1) {
        s  += __shfl_xor_sync(0xffffffff, s,  o);
        s2 += __shfl_xor_sync(0xffffffff, s2, o);
    }
    __shared__ float sh[16];
    int wid = threadIdx.x >> 5, lane = threadIdx.x & 31;
    if (lane == 0) { sh[wid] = s; sh[8 + wid] = s2; }
    __syncthreads();
    if (threadIdx.x == 0) {
        float S = 0.f, S2 = 0.f;
        for (int w = 0; w < 8; w++) { S += sh[w]; S2 += sh[8 + w]; }
        sh[0] = S; sh[8] = S2;
    }
    __syncthreads();
    float mu = sh[0] * (1.f / DIMX);
    float var = sh[8] * (1.f / DIMX) - mu * mu;
    float inv = rsqrtf(var + 1e-5f);
    float* o = xn + (size_t)row * DIMX;
    for (int i = threadIdx.x; i < DIMX; i += 256)
        o[i] = tf32r((xr[i] - mu) * inv * gamma[i]);
}

// ---------------- LoRA first stage ----------------
__global__ void lora_xa_kernel(const float* __restrict__ xn,
                               const float* __restrict__ aq,
                               const float* __restrict__ ak,
                               const float* __restrict__ av,
                               float* __restrict__ xa) {
    int row = blockIdx.x;
    const float* xr = xn + (size_t)row * DIMX;
    float acc[24];
#pragma unroll
    for (int m = 0; m < 24; m++) acc[m] = 0.f;
    for (int i = threadIdx.x; i < DIMX; i += 256) {
        float v = xr[i];
#pragma unroll
        for (int r = 0; r < 8; r++) {
            acc[r]      += v * aq[i * 8 + r];
            acc[8 + r]  += v * ak[i * 8 + r];
            acc[16 + r] += v * av[i * 8 + r];
        }
    }
    __shared__ float sh[8][24];
    int wid = threadIdx.x >> 5, lane = threadIdx.x & 31;
#pragma unroll
    for (int m = 0; m < 24; m++)
        for (int o = 16; o > 0; o >>= 1)
            acc[m] += __shfl_xor_sync(0xffffffff, acc[m], o);
    if (lane == 0)
#pragma unroll
        for (int m = 0; m < 24; m++) sh[wid][m] = acc[m];
    __syncthreads();
    if (threadIdx.x < 24) {
        float s = 0.f;
        for (int w = 0; w < 8; w++) s += sh[w][threadIdx.x];
        xa[row * 24 + threadIdx.x] = s;
    }
}

// ---------------- qkv prep ----------------
__global__ void qkv_prep(const float* __restrict__ F, const float* __restrict__ XA,
                         const float* __restrict__ bq, const float* __restrict__ bk,
                         const float* __restrict__ bv,
                         float* __restrict__ Q, float* __restrict__ Kv, float* __restrict__ V) {
    int row = blockIdx.x;
    int n = row % NSEQ;
    __shared__ float qs[AINNER];
    __shared__ float ks[DHEAD];
    const float* Fr = F + (size_t)row * FPAD;
    const float* xa = XA + row * 24;
    float lq[8], lk[8], lv[8];
#pragma unroll
    for (int r = 0; r < 8; r++) { lq[r] = xa[r]; lk[r] = xa[8 + r]; lv[r] = xa[16 + r]; }

    for (int c = threadIdx.x; c < AINNER; c += 256) {
        float v = Fr[c];
#pragma unroll
        for (int r = 0; r < 8; r++) v += lq[r] * bq[r * AINNER + c];
        qs[c] = v;
    }
    if (threadIdx.x < DHEAD) {
        int c = threadIdx.x;
        float v = Fr[I0 + c];
#pragma unroll
        for (int r = 0; r < 8; r++) v += lk[r] * bk[r * DHEAD + c];
        ks[c] = v;
        float vv = Fr[I1 + c];
#pragma unroll
        for (int r = 0; r < 8; r++) vv += lv[r] * bv[r * DHEAD + c];
        V[(size_t)row * DHEAD + c] = vv;
    }
    __syncthreads();

    const float ln10k_inv32 = 9.2103403719761836f / 32.f;
    const float scale = 0.125f;
    for (int c = threadIdx.x; c < AINNER; c += 256) {
        int h = c >> 6, d = c & 63;
        int fi = d & 31;
        float freq = (float)n * __expf(-(float)fi * ln10k_inv32);
        float cs = cosf(freq), sn = sinf(freq);
        float me = qs[c];
        float partner = (d < 32) ? -qs[h * 64 + d + 32] : qs[h * 64 + d - 32];
        Q[(size_t)row * AINNER + c] = (me * cs + partner * sn) * scale;
    }
    if (threadIdx.x < DHEAD) {
        int d = threadIdx.x;
        int fi = d & 31;
        float freq = (float)n * __expf(-(float)fi * ln10k_inv32);
        float cs = cosf(freq), sn = sinf(freq);
        float me = ks[d];
        float partner = (d < 32) ? -ks[d + 32] : ks[d - 32];
        Kv[(size_t)row * DHEAD + d] = me * cs + partner * sn;
    }
}

// ---------------- causal flash attention (vectorized LDS) ----------------
__global__ __launch_bounds__(512) void attn_kernel(const float* __restrict__ Q,
                                                   const float* __restrict__ Kk,
                                                   const float* __restrict__ V,
                                                   float* __restrict__ O) {
    int row = blockIdx.x;
    int n = row % NSEQ;
    int b = row / NSEQ;
    int wid = threadIdx.x >> 5;
    int lane = threadIdx.x & 31;

    __shared__ float Qs[HEADS][64];
    __shared__ float Ks[32][68];
    __shared__ float Vs[32][68];
    __shared__ float Ps[HEADS][32];

    for (int idx = threadIdx.x; idx < HEADS * DHEAD; idx += 512)
        Qs[idx >> 6][idx & 63] = Q[(size_t)row * AINNER + idx];

    const float* Kb = Kk + (size_t)b * NSEQ * DHEAD;
    const float* Vb = V + (size_t)b * NSEQ * DHEAD;

    float m = -FLT_MAX, l = 0.f, acc0 = 0.f, acc1 = 0.f;

    for (int j0 = 0; j0 <= n; j0 += 32) {
        int cnt = min(32, n + 1 - j0);
        __syncthreads();
        {
            int jj = threadIdx.x >> 4, d4 = (threadIdx.x & 15) * 4;
            float4 kv = make_float4(0, 0, 0, 0), vv = make_float4(0, 0, 0, 0);
            if (jj < cnt) {
                kv = *(const float4*)(Kb + (size_t)(j0 + jj) * DHEAD + d4);
                vv = *(const float4*)(Vb + (size_t)(j0 + jj) * DHEAD + d4);
            }
            *(float4*)&Ks[jj][d4] = kv;
            *(float4*)&Vs[jj][d4] = vv;
        }
        __syncthreads();

        float s = 0.f;
        {
            const float4* q4 = (const float4*)Qs[wid];
            const float4* k4 = (const float4*)Ks[lane];
#pragma unroll
            for (int d4 = 0; d4 < 16; d4++) {
                float4 qa = q4[d4], kb = k4[d4];
                s += qa.x * kb.x + qa.y * kb.y + qa.z * kb.z + qa.w * kb.w;
            }
        }
        if (lane >= cnt) s = -FLT_MAX;
        float smax = s;
        for (int o = 16; o > 0; o >>= 1) smax = fmaxf(smax, __shfl_xor_sync(0xffffffff, smax, o));
        float mnew = fmaxf(m, smax);
        float p = (lane < cnt) ? __expf(s - mnew) : 0.f;
        float ps = p;
        for (int o = 16; o > 0; o >>= 1) ps += __shfl_xor_sync(0xffffffff, ps, o);
        float corr = __expf(m - mnew);
        l = l * corr + ps;
        acc0 *= corr; acc1 *= corr;
        Ps[wid][lane] = p;
        __syncwarp();
        const float4* p4 = (const float4*)Ps[wid];
#pragma unroll
        for (int j4 = 0; j4 < 8; j4++) {
            float4 pj = p4[j4];
            float2 v0 = *(const float2*)&Vs[j4 * 4 + 0][lane * 2];
            float2 v1 = *(const float2*)&Vs[j4 * 4 + 1][lane * 2];
            float2 v2 = *(const float2*)&Vs[j4 * 4 + 2][lane * 2];
            float2 v3 = *(const float2*)&Vs[j4 * 4 + 3][lane * 2];
            acc0 += pj.x * v0.x + pj.y * v1.x + pj.z * v2.x + pj.w * v3.x;
            acc1 += pj.x * v0.y + pj.y * v1.y + pj.z * v2.y + pj.w * v3.y;
        }
        m = mnew;
    }
    float invl = 1.f / l;
    float2 o2 = make_float2(tf32r(acc0 * invl), tf32r(acc1 * invl));
    *(float2*)(O + (size_t)row * AINNER + wid * 64 + lane * 2) = o2;
}

// ---------------- OA[row,8] = OATTN_row @ a_o ----------------
__global__ void lora_oa_kernel(const float* __restrict__ oattn,
                               const float* __restrict__ ao,
                               float* __restrict__ oa) {
    int row = blockIdx.x;
    const float* xr = oattn + (size_t)row * AINNER;
    float acc[8];
#pragma unroll
    for (int r = 0; r < 8; r++) acc[r] = 0.f;
    for (int i = threadIdx.x; i < AINNER; i += 256) {
        float v = xr[i];
#pragma unroll
        for (int r = 0; r < 8; r++) acc[r] += v * ao[i * 8 + r];
    }
    __shared__ float sh[8][8];
    int wid = threadIdx.x >> 5, lane = threadIdx.x & 31;
#pragma unroll
    for (int r = 0; r < 8; r++)
        for (int o = 16; o > 0; o >>= 1)
            acc[r] += __shfl_xor_sync(0xffffffff, acc[r], o);
    if (lane == 0)
#pragma unroll
        for (int r = 0; r < 8; r++) sh[wid][r] = acc[r];
    __syncthreads();
    if (threadIdx.x < 8) {
        float s = 0.f;
        for (int w = 0; w < 8; w++) s += sh[w][threadIdx.x];
        oa[row * 8 + threadIdx.x] = s;
    }
}

// ---------------- H = tf32(silu(gate) * ff_x) ----------------
__global__ void hcombine(const float* __restrict__ F, float* __restrict__ H) {
    size_t idx = (size_t)blockIdx.x * blockDim.x + threadIdx.x;
    size_t row = idx / FFINNER;
    int c = (int)(idx % FFINNER);
    const float* Fr = F + row * FPAD;
    float g = Fr[I2 + FFINNER + c];
    float xx = Fr[I2 + c];
    H[idx] = tf32r(xx * g / (1.f + __expf(-g)));
}

// ---------------- out += OA @ b_o ----------------
__global__ void lora_o_add(const float* __restrict__ oa, const float* __restrict__ bo,
                           float* __restrict__ out) {
    int row = blockIdx.y;
    int c = blockIdx.x * 256 + threadIdx.x;
    float s = 0.f;
#pragma unroll
    for (int r = 0; r < 8; r++) s += oa[row * 8 + r] * bo[r * DIMX + c];
    out[(size_t)row * DIMX + c] += s;
}

// ---------------- launch ----------------
extern "C" void kernel_launch(void* const* d_in, const int* in_sizes, int n_in,
                              void* d_out, int out_size) {
    const float* x          = (const float*)d_in[0];
    const float* gamma      = (const float*)d_in[1];
    const float* w_fused    = (const float*)d_in[2];
    const float* w_attn_out = (const float*)d_in[3];
    const float* w_ff_out   = (const float*)d_in[4];
    const float* a_q        = (const float*)d_in[5];
    const float* b_q        = (const float*)d_in[6];
    const float* a_k        = (const float*)d_in[7];
    const float* b_k        = (const float*)d_in[8];
    const float* a_v        = (const float*)d_in[9];
    const float* b_v        = (const float*)d_in[10];
    const float* a_o        = (const float*)d_in[11];
    const float* b_o        = (const float*)d_in[12];
    float* out = (float*)d_out;

    float *XN, *WF, *F, *XA, *Q, *K, *V, *OATTN, *WAO, *H, *WFF, *OA;
    cudaGetSymbolAddress((void**)&XN, g_XN);
    cudaGetSymbolAddress((void**)&WF, g_WF);
    cudaGetSymbolAddress((void**)&F, g_F);
    cudaGetSymbolAddress((void**)&XA, g_XA);
    cudaGetSymbolAddress((void**)&Q, g_Q);
    cudaGetSymbolAddress((void**)&K, g_K);
    cudaGetSymbolAddress((void**)&V, g_V);
    cudaGetSymbolAddress((void**)&OATTN, g_OATTN);
    cudaGetSymbolAddress((void**)&WAO, g_WAO);
    cudaGetSymbolAddress((void**)&H, g_H);
    cudaGetSymbolAddress((void**)&WFF, g_WFF);
    cudaGetSymbolAddress((void**)&OA, g_OA);

    cudaFuncSetAttribute(tf32_gemm, cudaFuncAttributeMaxDynamicSharedMemorySize, GSMEM);

    // weight rounding (+pad for fused)
    round_pad<<<dim3((FPAD / 4 + 255) / 256, DIMX), 256>>>(w_fused, WF, FUSEDC / 4, FPAD / 4);
    round_pad<<<dim3((DIMX / 4 + 255) / 256, AINNER), 256>>>(w_attn_out, WAO, DIMX / 4, DIMX / 4);
    round_pad<<<dim3((DIMX / 4 + 255) / 256, FFINNER), 256>>>(w_ff_out, WFF, DIMX / 4, DIMX / 4);

    ln_kernel<<<ROWS, 256>>>(x, gamma, XN);
    tf32_gemm<<<dim3(ROWS / 256, FPAD / 128), 256, GSMEM>>>(XN, WF, F, FPAD, DIMX, 0);
    lora_xa_kernel<<<ROWS, 256>>>(XN, a_q, a_k, a_v, XA);
    qkv_prep<<<ROWS, 256>>>(F, XA, b_q, b_k, b_v, Q, K, V);
    attn_kernel<<<ROWS, 512>>>(Q, K, V, OATTN);
    tf32_gemm<<<dim3(ROWS / 256, DIMX / 128), 256, GSMEM>>>(OATTN, WAO, out, DIMX, AINNER, 0);
    lora_oa_kernel<<<ROWS, 256>>>(OATTN, a_o, OA);
    hcombine<<<(ROWS * (size_t)FFINNER) / 256, 256>>>(F, H);
    tf32_gemm<<<dim3(ROWS / 256, DIMX / 128), 256, GSMEM>>>(H, WFF, out, DIMX, FFINNER, 1);
    lora_o_add<<<dim3(DIMX / 256, ROWS), 256>>>(OA, b_o, out);
}

// round 6
// speedup vs baseline: 1.0249x; 1.0249x over previous
#include <cuda_runtime.h>
#include <cuda_bf16.h>
#include <math.h>
#include <float.h>
#include <stdint.h>

// ---------------- problem constants ----------------
#define DIMX 2048
#define NSEQ 2048
#define BATCH 2
#define HEADS 16
#define DHEAD 64
#define ROWS (BATCH*NSEQ)          // 4096
#define AINNER 1024
#define FFINNER 8192
#define FUSEDC 17536               // 1024+64+64+2*8192
#define FPAD 17664                 // 138*128 (permuted width)
#define FQKV 1280                  // qkv cols (1152) padded to 128-multiple
#define I0 1024
#define I1 1088
#define I2 1152

// ---------------- scratch (device globals) --------
__device__ float g_XN[(size_t)ROWS*DIMX];
__device__ float g_WF[(size_t)DIMX*FPAD];        // rounded + permuted w_fused
__device__ float g_F[(size_t)ROWS*FQKV];         // qkv part only
__device__ float g_XA[ROWS*24];
__device__ float g_Q[(size_t)ROWS*AINNER];
__device__ float g_K[(size_t)ROWS*DHEAD];
__device__ float g_V[(size_t)ROWS*DHEAD];
__device__ float g_OATTN[(size_t)ROWS*AINNER];
__device__ float g_WAO[(size_t)AINNER*DIMX];
__device__ float g_H[(size_t)ROWS*FFINNER];
__device__ float g_WFF[(size_t)FFINNER*DIMX];
__device__ float g_OA[ROWS*8];

// ---------------- small helpers ----------------
__device__ __forceinline__ float tf32r(float x) {
    uint32_t u;
    asm("cvt.rna.tf32.f32 %0, %1;" : "=r"(u) : "f"(x));
    return __uint_as_float(u);
}
__device__ __forceinline__ uint32_t smem_u32(const void* p) {
    uint32_t a;
    asm("{ .reg .u64 t; cvta.to.shared.u64 t, %1; cvt.u32.u64 %0, t; }" : "=r"(a) : "l"(p));
    return a;
}
__device__ __forceinline__ void cp16(uint32_t saddr, const void* g) {
    asm volatile("cp.async.cg.shared.global [%0], [%1], 16;" :: "r"(saddr), "l"(g) : "memory");
}
__device__ __forceinline__ void mma_tf32(float* d, const uint32_t* a, const uint32_t* b) {
    asm volatile(
        "mma.sync.aligned.m16n8k8.row.col.f32.tf32.tf32.f32 "
        "{%0,%1,%2,%3}, {%4,%5,%6,%7}, {%8,%9}, {%0,%1,%2,%3};"
        : "+f"(d[0]), "+f"(d[1]), "+f"(d[2]), "+f"(d[3])
        : "r"(a[0]), "r"(a[1]), "r"(a[2]), "r"(a[3]), "r"(b[0]), "r"(b[1]));
}

// ================= TF32 GEMM (R4-proven config) =================
// 128x128x16 CTA tile, 256 thr, 8 warps (4m x 2n), warp tile 32x64, 3-stage cp.async.
// fused=0: C[M,N] (+= if accum), ldc=N.
// fused=1: n0<FQKV -> write C (ldc=FQKV); n0>=FQKV -> columns are interleaved
//          (x,gate) pairs; write Ch[r][ (n-FQKV)/2 ] = tf32(x*silu(gate)), ldh=FFINNER.
#define GSTAGES 3
#define AST 20
#define BST 136
#define AWORDS (128*AST)  // 2560
#define BWORDS (16*BST)   // 2176
#define STW (AWORDS+BWORDS)   // 4736
#define GSMEM (GSTAGES*STW*4) // 56832 bytes

__global__ __launch_bounds__(256) void tf32_gemm(const float* __restrict__ A,
                                                 const float* __restrict__ B,
                                                 float* __restrict__ C,
                                                 float* __restrict__ Ch,
                                                 int N, int K, int accum, int fused) {
    extern __shared__ float smem[];
    const int tid = threadIdx.x;
    const int wid = tid >> 5, lane = tid & 31;
    const int wm = (wid & 3) * 32, wn = (wid >> 2) * 64;
    const int m0 = blockIdx.x * 128, n0 = blockIdx.y * 128;
    const float* Ag = A + (size_t)m0 * K;
    const float* Bg = B + n0;
    const uint32_t sb = smem_u32(smem);

    const int arow = tid >> 2, ak4 = (tid & 3) * 4;
    const int brow = tid >> 5, bn4 = (tid & 31) * 4;
    const int NK = K >> 4;

    auto load_stage = [&](int kt, int s) {
        const uint32_t sa = sb + s * STW * 4;
        const uint32_t sB = sa + AWORDS * 4;
        const float* ag = Ag + kt * 16;
        const float* bg = Bg + (size_t)(kt * 16) * N;
#pragma unroll
        for (int i = 0; i < 2; i++) {
            int r = arow + i * 64;
            cp16(sa + (r * AST + ak4) * 4, ag + (size_t)r * K + ak4);
            int kr = brow + i * 8;
            cp16(sB + (kr * BST + bn4) * 4, bg + (size_t)kr * N + bn4);
        }
    };

    float acc[2][8][4];
#pragma unroll
    for (int mt = 0; mt < 2; mt++)
#pragma unroll
        for (int nt = 0; nt < 8; nt++)
#pragma unroll
            for (int i = 0; i < 4; i++) acc[mt][nt][i] = 0.f;

    load_stage(0, 0);
    asm volatile("cp.async.commit_group;" ::: "memory");
    load_stage(1, 1);
    asm volatile("cp.async.commit_group;" ::: "memory");

#pragma unroll 1
    for (int kt = 0; kt < NK; kt++) {
        asm volatile("cp.async.wait_group 1;" ::: "memory");
        __syncthreads();
        if (kt + 2 < NK) load_stage(kt + 2, (kt + 2) % GSTAGES);
        asm volatile("cp.async.commit_group;" ::: "memory");

        const int s = kt % GSTAGES;
        const float* As = smem + s * STW;
        const float* Bs = As + AWORDS;
#pragma unroll
        for (int c8 = 0; c8 < 2; c8++) {
            const int c = c8 * 8;
            uint32_t a[2][4], b[8][2];
            const int kk = c + (lane & 3);
#pragma unroll
            for (int mt = 0; mt < 2; mt++) {
                int r = wm + mt * 16 + (lane >> 2);
                a[mt][0] = __float_as_uint(As[r * AST + kk]);
                a[mt][1] = __float_as_uint(As[(r + 8) * AST + kk]);
                a[mt][2] = __float_as_uint(As[r * AST + kk + 4]);
                a[mt][3] = __float_as_uint(As[(r + 8) * AST + kk + 4]);
            }
#pragma unroll
            for (int nt = 0; nt < 8; nt++) {
                int n = wn + nt * 8 + (lane >> 2);
                b[nt][0] = __float_as_uint(Bs[kk * BST + n]);
                b[nt][1] = __float_as_uint(Bs[(kk + 4) * BST + n]);
            }
#pragma unroll
            for (int mt = 0; mt < 2; mt++)
#pragma unroll
                for (int nt = 0; nt < 8; nt++)
                    mma_tf32(acc[mt][nt], a[mt], b[nt]);
        }
    }

    // epilogue
    const int rbase = m0 + wm + (lane >> 2);
    const int cbase = n0 + wn + (lane & 3) * 2;
    if (!fused || n0 < FQKV) {
        const int ldc = fused ? FQKV : N;
#pragma unroll
        for (int mt = 0; mt < 2; mt++) {
#pragma unroll
            for (int nt = 0; nt < 8; nt++) {
                int r = rbase + mt * 16;
                int cc = cbase + nt * 8;
                float2* p0 = (float2*)(C + (size_t)r * ldc + cc);
                float2* p1 = (float2*)(C + (size_t)(r + 8) * ldc + cc);
                float2 v0 = make_float2(acc[mt][nt][0], acc[mt][nt][1]);
                float2 v1 = make_float2(acc[mt][nt][2], acc[mt][nt][3]);
                if (accum) {
                    float2 o0 = *p0, o1 = *p1;
                    v0.x += o0.x; v0.y += o0.y; v1.x += o1.x; v1.y += o1.y;
                }
                *p0 = v0; *p1 = v1;
            }
        }
    } else {
        // ff region: (x, gate) pairs -> H = tf32(x * silu(gate))
#pragma unroll
        for (int mt = 0; mt < 2; mt++) {
#pragma unroll
            for (int nt = 0; nt < 8; nt++) {
                int r = rbase + mt * 16;
                int hc = (cbase + nt * 8 - FQKV) >> 1;
                float x0 = acc[mt][nt][0], gg0 = acc[mt][nt][1];
                float x1 = acc[mt][nt][2], gg1 = acc[mt][nt][3];
                Ch[(size_t)r * FFINNER + hc]       = tf32r(x0 * gg0 / (1.f + __expf(-gg0)));
                Ch[(size_t)(r + 8) * FFINNER + hc] = tf32r(x1 * gg1 / (1.f + __expf(-gg1)));
            }
        }
    }
}

// ---------------- weight rounding (+ column pad) ----------------
__global__ void round_pad(const float* __restrict__ in, float* __restrict__ out,
                          int Nin4, int Nout4) {
    int row = blockIdx.y;
    int c4 = blockIdx.x * 256 + threadIdx.x;
    if (c4 >= Nout4) return;
    float4 v = make_float4(0.f, 0.f, 0.f, 0.f);
    if (c4 < Nin4) {
        v = ((const float4*)(in + (size_t)row * Nin4 * 4))[c4];
        v.x = tf32r(v.x); v.y = tf32r(v.y); v.z = tf32r(v.z); v.w = tf32r(v.w);
    }
    ((float4*)(out + (size_t)row * Nout4 * 4))[c4] = v;
}

// ---------------- w_fused rounding + column permutation ----------------
// out col j: j<1152 -> src j ; 1152<=j<1280 -> 0 ; j>=1280: p=j-1280,
//   even p -> ff_x col p/2 (src I2+p/2), odd p -> ff_gate col p/2 (src I2+FFINNER+p/2).
__global__ void round_pad_perm(const float* __restrict__ in, float* __restrict__ out) {
    int row = blockIdx.y;
    int c4 = blockIdx.x * 256 + threadIdx.x;   // float4 index
    if (c4 >= FPAD / 4) return;
    const float* src = in + (size_t)row * FUSEDC;
    float v[4];
#pragma unroll
    for (int e = 0; e < 4; e++) {
        int j = c4 * 4 + e;
        float val;
        if (j < I2) val = src[j];
        else if (j < FQKV) val = 0.f;
        else {
            int p = j - FQKV;
            val = src[I2 + (p >> 1) + (p & 1) * FFINNER];
        }
        v[e] = tf32r(val);
    }
    ((float4*)(out + (size_t)row * FPAD))[c4] = make_float4(v[0], v[1], v[2], v[3]);
}

// ---------------- layernorm (tf32-rounded out) ----------------
__global__ void ln_kernel(const float* __restrict__ x, const float* __restrict__ gamma,
                          float* __restrict__ xn) {
    int row = blockIdx.x;
    const float* xr = x + (size_t)row * DIMX;
    float s = 0.f, s2 = 0.f;
    for (int i = threadIdx.x; i < DIMX; i += 256) { float v = xr[i]; s += v; s2 += v * v; }
    for (int o = 16; o > 0; o >>= 1) {
        s  += __shfl_xor_sync(0xffffffff, s,  o);
        s2 += __shfl_xor_sync(0xffffffff, s2, o);
    }
    __shared__ float sh[16];
    int wid = threadIdx.x >> 5, lane = threadIdx.x & 31;
    if (lane == 0) { sh[wid] = s; sh[8 + wid] = s2; }
    __syncthreads();
    if (threadIdx.x == 0) {
        float S = 0.f, S2 = 0.f;
        for (int w = 0; w < 8; w++) { S += sh[w]; S2 += sh[8 + w]; }
        sh[0] = S; sh[8] = S2;
    }
    __syncthreads();
    float mu = sh[0] * (1.f / DIMX);
    float var = sh[8] * (1.f / DIMX) - mu * mu;
    float inv = rsqrtf(var + 1e-5f);
    float* o = xn + (size_t)row * DIMX;
    for (int i = threadIdx.x; i < DIMX; i += 256)
        o[i] = tf32r((xr[i] - mu) * inv * gamma[i]);
}

// ---------------- LoRA first stage ----------------
__global__ void lora_xa_kernel(const float* __restrict__ xn,
                               const float* __restrict__ aq,
                               const float* __restrict__ ak,
                               const float* __restrict__ av,
                               float* __restrict__ xa) {
    int row = blockIdx.x;
    const float* xr = xn + (size_t)row * DIMX;
    float acc[24];
#pragma unroll
    for (int m = 0; m < 24; m++) acc[m] = 0.f;
    for (int i = threadIdx.x; i < DIMX; i += 256) {
        float v = xr[i];
#pragma unroll
        for (int r = 0; r < 8; r++) {
            acc[r]      += v * aq[i * 8 + r];
            acc[8 + r]  += v * ak[i * 8 + r];
            acc[16 + r] += v * av[i * 8 + r];
        }
    }
    __shared__ float sh[8][24];
    int wid = threadIdx.x >> 5, lane = threadIdx.x & 31;
#pragma unroll
    for (int m = 0; m < 24; m++)
        for (int o = 16; o > 0; o >>= 1)
            acc[m] += __shfl_xor_sync(0xffffffff, acc[m], o);
    if (lane == 0)
#pragma unroll
        for (int m = 0; m < 24; m++) sh[wid][m] = acc[m];
    __syncthreads();
    if (threadIdx.x < 24) {
        float s = 0.f;
        for (int w = 0; w < 8; w++) s += sh[w][threadIdx.x];
        xa[row * 24 + threadIdx.x] = s;
    }
}

// ---------------- qkv prep (F row stride = FQKV) ----------------
__global__ void qkv_prep(const float* __restrict__ F, const float* __restrict__ XA,
                         const float* __restrict__ bq, const float* __restrict__ bk,
                         const float* __restrict__ bv,
                         float* __restrict__ Q, float* __restrict__ Kv, float* __restrict__ V) {
    int row = blockIdx.x;
    int n = row % NSEQ;
    __shared__ float qs[AINNER];
    __shared__ float ks[DHEAD];
    const float* Fr = F + (size_t)row * FQKV;
    const float* xa = XA + row * 24;
    float lq[8], lk[8], lv[8];
#pragma unroll
    for (int r = 0; r < 8; r++) { lq[r] = xa[r]; lk[r] = xa[8 + r]; lv[r] = xa[16 + r]; }

    for (int c = threadIdx.x; c < AINNER; c += 256) {
        float v = Fr[c];
#pragma unroll
        for (int r = 0; r < 8; r++) v += lq[r] * bq[r * AINNER + c];
        qs[c] = v;
    }
    if (threadIdx.x < DHEAD) {
        int c = threadIdx.x;
        float v = Fr[I0 + c];
#pragma unroll
        for (int r = 0; r < 8; r++) v += lk[r] * bk[r * DHEAD + c];
        ks[c] = v;
        float vv = Fr[I1 + c];
#pragma unroll
        for (int r = 0; r < 8; r++) vv += lv[r] * bv[r * DHEAD + c];
        V[(size_t)row * DHEAD + c] = vv;
    }
    __syncthreads();

    const float ln10k_inv32 = 9.2103403719761836f / 32.f;
    const float scale = 0.125f;
    for (int c = threadIdx.x; c < AINNER; c += 256) {
        int h = c >> 6, d = c & 63;
        int fi = d & 31;
        float freq = (float)n * __expf(-(float)fi * ln10k_inv32);
        float cs = cosf(freq), sn = sinf(freq);
        float me = qs[c];
        float partner = (d < 32) ? -qs[h * 64 + d + 32] : qs[h * 64 + d - 32];
        Q[(size_t)row * AINNER + c] = (me * cs + partner * sn) * scale;
    }
    if (threadIdx.x < DHEAD) {
        int d = threadIdx.x;
        int fi = d & 31;
        float freq = (float)n * __expf(-(float)fi * ln10k_inv32);
        float cs = cosf(freq), sn = sinf(freq);
        float me = ks[d];
        float partner = (d < 32) ? -ks[d + 32] : ks[d - 32];
        Kv[(size_t)row * DHEAD + d] = me * cs + partner * sn;
    }
}

// ---------------- causal flash attention (vectorized LDS) ----------------
__global__ __launch_bounds__(512) void attn_kernel(const float* __restrict__ Q,
                                                   const float* __restrict__ Kk,
                                                   const float* __restrict__ V,
                                                   float* __restrict__ O) {
    int row = blockIdx.x;
    int n = row % NSEQ;
    int b = row / NSEQ;
    int wid = threadIdx.x >> 5;
    int lane = threadIdx.x & 31;

    __shared__ float Qs[HEADS][64];
    __shared__ float Ks[32][68];
    __shared__ float Vs[32][68];
    __shared__ float Ps[HEADS][32];

    for (int idx = threadIdx.x; idx < HEADS * DHEAD; idx += 512)
        Qs[idx >> 6][idx & 63] = Q[(size_t)row * AINNER + idx];

    const float* Kb = Kk + (size_t)b * NSEQ * DHEAD;
    const float* Vb = V + (size_t)b * NSEQ * DHEAD;

    float m = -FLT_MAX, l = 0.f, acc0 = 0.f, acc1 = 0.f;

    for (int j0 = 0; j0 <= n; j0 += 32) {
        int cnt = min(32, n + 1 - j0);
        __syncthreads();
        {
            int jj = threadIdx.x >> 4, d4 = (threadIdx.x & 15) * 4;
            float4 kv = make_float4(0, 0, 0, 0), vv = make_float4(0, 0, 0, 0);
            if (jj < cnt) {
                kv = *(const float4*)(Kb + (size_t)(j0 + jj) * DHEAD + d4);
                vv = *(const float4*)(Vb + (size_t)(j0 + jj) * DHEAD + d4);
            }
            *(float4*)&Ks[jj][d4] = kv;
            *(float4*)&Vs[jj][d4] = vv;
        }
        __syncthreads();

        float s = 0.f;
        {
            const float4* q4 = (const float4*)Qs[wid];
            const float4* k4 = (const float4*)Ks[lane];
#pragma unroll
            for (int d4 = 0; d4 < 16; d4++) {
                float4 qa = q4[d4], kb = k4[d4];
                s += qa.x * kb.x + qa.y * kb.y + qa.z * kb.z + qa.w * kb.w;
            }
        }
        if (lane >= cnt) s = -FLT_MAX;
        float smax = s;
        for (int o = 16; o > 0; o >>= 1) smax = fmaxf(smax, __shfl_xor_sync(0xffffffff, smax, o));
        float mnew = fmaxf(m, smax);
        float p = (lane < cnt) ? __expf(s - mnew) : 0.f;
        float ps = p;
        for (int o = 16; o > 0; o >>= 1) ps += __shfl_xor_sync(0xffffffff, ps, o);
        float corr = __expf(m - mnew);
        l = l * corr + ps;
        acc0 *= corr; acc1 *= corr;
        Ps[wid][lane] = p;
        __syncwarp();
        const float4* p4 = (const float4*)Ps[wid];
#pragma unroll
        for (int j4 = 0; j4 < 8; j4++) {
            float4 pj = p4[j4];
            float2 v0 = *(const float2*)&Vs[j4 * 4 + 0][lane * 2];
            float2 v1 = *(const float2*)&Vs[j4 * 4 + 1][lane * 2];
            float2 v2 = *(const float2*)&Vs[j4 * 4 + 2][lane * 2];
            float2 v3 = *(const float2*)&Vs[j4 * 4 + 3][lane * 2];
            acc0 += pj.x * v0.x + pj.y * v1.x + pj.z * v2.x + pj.w * v3.x;
            acc1 += pj.x * v0.y + pj.y * v1.y + pj.z * v2.y + pj.w * v3.y;
        }
        m = mnew;
    }
    float invl = 1.f / l;
    float2 o2 = make_float2(tf32r(acc0 * invl), tf32r(acc1 * invl));
    *(float2*)(O + (size_t)row * AINNER + wid * 64 + lane * 2) = o2;
}

// ---------------- OA[row,8] = OATTN_row @ a_o ----------------
__global__ void lora_oa_kernel(const float* __restrict__ oattn,
                               const float* __restrict__ ao,
                               float* __restrict__ oa) {
    int row = blockIdx.x;
    const float* xr = oattn + (size_t)row * AINNER;
    float acc[8];
#pragma unroll
    for (int r = 0; r < 8; r++) acc[r] = 0.f;
    for (int i = threadIdx.x; i < AINNER; i += 256) {
        float v = xr[i];
#pragma unroll
        for (int r = 0; r < 8; r++) acc[r] += v * ao[i * 8 + r];
    }
    __shared__ float sh[8][8];
    int wid = threadIdx.x >> 5, lane = threadIdx.x & 31;
#pragma unroll
    for (int r = 0; r < 8; r++)
        for (int o = 16; o > 0; o >>= 1)
            acc[r] += __shfl_xor_sync(0xffffffff, acc[r], o);
    if (lane == 0)
#pragma unroll
        for (int r = 0; r < 8; r++) sh[wid][r] = acc[r];
    __syncthreads();
    if (threadIdx.x < 8) {
        float s = 0.f;
        for (int w = 0; w < 8; w++) s += sh[w][threadIdx.x];
        oa[row * 8 + threadIdx.x] = s;
    }
}

// ---------------- out += OA @ b_o ----------------
__global__ void lora_o_add(const float* __restrict__ oa, const float* __restrict__ bo,
                           float* __restrict__ out) {
    int row = blockIdx.y;
    int c = blockIdx.x * 256 + threadIdx.x;
    float s = 0.f;
#pragma unroll
    for (int r = 0; r < 8; r++) s += oa[row * 8 + r] * bo[r * DIMX + c];
    out[(size_t)row * DIMX + c] += s;
}

// ---------------- launch ----------------
extern "C" void kernel_launch(void* const* d_in, const int* in_sizes, int n_in,
                              void* d_out, int out_size) {
    const float* x          = (const float*)d_in[0];
    const float* gamma      = (const float*)d_in[1];
    const float* w_fused    = (const float*)d_in[2];
    const float* w_attn_out = (const float*)d_in[3];
    const float* w_ff_out   = (const float*)d_in[4];
    const float* a_q        = (const float*)d_in[5];
    const float* b_q        = (const float*)d_in[6];
    const float* a_k        = (const float*)d_in[7];
    const float* b_k        = (const float*)d_in[8];
    const float* a_v        = (const float*)d_in[9];
    const float* b_v        = (const float*)d_in[10];
    const float* a_o        = (const float*)d_in[11];
    const float* b_o        = (const float*)d_in[12];
    float* out = (float*)d_out;

    float *XN, *WF, *F, *XA, *Q, *K, *V, *OATTN, *WAO, *H, *WFF, *OA;
    cudaGetSymbolAddress((void**)&XN, g_XN);
    cudaGetSymbolAddress((void**)&WF, g_WF);
    cudaGetSymbolAddress((void**)&F, g_F);
    cudaGetSymbolAddress((void**)&XA, g_XA);
    cudaGetSymbolAddress((void**)&Q, g_Q);
    cudaGetSymbolAddress((void**)&K, g_K);
    cudaGetSymbolAddress((void**)&V, g_V);
    cudaGetSymbolAddress((void**)&OATTN, g_OATTN);
    cudaGetSymbolAddress((void**)&WAO, g_WAO);
    cudaGetSymbolAddress((void**)&H, g_H);
    cudaGetSymbolAddress((void**)&WFF, g_WFF);
    cudaGetSymbolAddress((void**)&OA, g_OA);

    cudaFuncSetAttribute(tf32_gemm, cudaFuncAttributeMaxDynamicSharedMemorySize, GSMEM);

    // weight rounding (+permutation for fused)
    round_pad_perm<<<dim3((FPAD / 4 + 255) / 256, DIMX), 256>>>(w_fused, WF);
    round_pad<<<dim3((DIMX / 4 + 255) / 256, AINNER), 256>>>(w_attn_out, WAO, DIMX / 4, DIMX / 4);
    round_pad<<<dim3((DIMX / 4 + 255) / 256, FFINNER), 256>>>(w_ff_out, WFF, DIMX / 4, DIMX / 4);

    ln_kernel<<<ROWS, 256>>>(x, gamma, XN);
    // fused GEMM: qkv -> F (ldc=FQKV), ff pairs -> H (silu fused in epilogue)
    tf32_gemm<<<dim3(ROWS / 128, FPAD / 128), 256, GSMEM>>>(XN, WF, F, H, FPAD, DIMX, 0, 1);
    lora_xa_kernel<<<ROWS, 256>>>(XN, a_q, a_k, a_v, XA);
    qkv_prep<<<ROWS, 256>>>(F, XA, b_q, b_k, b_v, Q, K, V);
    attn_kernel<<<ROWS, 512>>>(Q, K, V, OATTN);
    tf32_gemm<<<dim3(ROWS / 128, DIMX / 128), 256, GSMEM>>>(OATTN, WAO, out, nullptr, DIMX, AINNER, 0, 0);
    lora_oa_kernel<<<ROWS, 256>>>(OATTN, a_o, OA);
    tf32_gemm<<<dim3(ROWS / 128, DIMX / 128), 256, GSMEM>>>(H, WFF, out, nullptr, DIMX, FFINNER, 1, 0);
    lora_o_add<<<dim3(DIMX / 256, ROWS), 256>>>(OA, b_o, out);
}

// round 7
// speedup vs baseline: 1.3581x; 1.3251x over previous
#include <cuda_runtime.h>
#include <cuda_bf16.h>
#include <math.h>
#include <float.h>
#include <stdint.h>

// ---------------- problem constants ----------------
#define DIMX 2048
#define NSEQ 2048
#define BATCH 2
#define HEADS 16
#define DHEAD 64
#define ROWS (BATCH*NSEQ)          // 4096
#define AINNER 1024
#define FFINNER 8192
#define FUSEDC 17536               // 1024+64+64+2*8192
#define FPAD 17664                 // 138*128 (permuted width)
#define FQKV 1280                  // qkv cols (1152) padded to 128-multiple
#define I0 1024
#define I1 1088
#define I2 1152

// ---------------- scratch (device globals) --------
__device__ float g_XN[(size_t)ROWS*DIMX];
__device__ float g_WF[(size_t)DIMX*FPAD];        // rounded + permuted w_fused
__device__ float g_F[(size_t)ROWS*FQKV];         // qkv part only
__device__ float g_XA[ROWS*24];
__device__ float g_Q[(size_t)ROWS*AINNER];
__device__ float g_K[(size_t)ROWS*DHEAD];
__device__ float g_V[(size_t)ROWS*DHEAD];
__device__ float g_OATTN[(size_t)ROWS*AINNER];
__device__ float g_WAO[(size_t)AINNER*DIMX];
__device__ float g_H[(size_t)ROWS*FFINNER];
__device__ float g_WFF[(size_t)FFINNER*DIMX];
__device__ float g_OA[ROWS*8];

// ---------------- small helpers ----------------
__device__ __forceinline__ float tf32r(float x) {
    uint32_t u;
    asm("cvt.rna.tf32.f32 %0, %1;" : "=r"(u) : "f"(x));
    return __uint_as_float(u);
}
__device__ __forceinline__ uint32_t smem_u32(const void* p) {
    uint32_t a;
    asm("{ .reg .u64 t; cvta.to.shared.u64 t, %1; cvt.u32.u64 %0, t; }" : "=r"(a) : "l"(p));
    return a;
}
__device__ __forceinline__ void cp16(uint32_t saddr, const void* g) {
    asm volatile("cp.async.cg.shared.global [%0], [%1], 16;" :: "r"(saddr), "l"(g) : "memory");
}
__device__ __forceinline__ void mma_tf32(float* d, const uint32_t* a, const uint32_t* b) {
    asm volatile(
        "mma.sync.aligned.m16n8k8.row.col.f32.tf32.tf32.f32 "
        "{%0,%1,%2,%3}, {%4,%5,%6,%7}, {%8,%9}, {%0,%1,%2,%3};"
        : "+f"(d[0]), "+f"(d[1]), "+f"(d[2]), "+f"(d[3])
        : "r"(a[0]), "r"(a[1]), "r"(a[2]), "r"(a[3]), "r"(b[0]), "r"(b[1]));
}

// ================= TF32 GEMM (R4-proven config) =================
#define GSTAGES 3
#define AST 20
#define BST 136
#define AWORDS (128*AST)  // 2560
#define BWORDS (16*BST)   // 2176
#define STW (AWORDS+BWORDS)   // 4736
#define GSMEM (GSTAGES*STW*4) // 56832 bytes

__global__ __launch_bounds__(256) void tf32_gemm(const float* __restrict__ A,
                                                 const float* __restrict__ B,
                                                 float* __restrict__ C,
                                                 float* __restrict__ Ch,
                                                 int N, int K, int accum, int fused) {
    extern __shared__ float smem[];
    const int tid = threadIdx.x;
    const int wid = tid >> 5, lane = tid & 31;
    const int wm = (wid & 3) * 32, wn = (wid >> 2) * 64;
    const int m0 = blockIdx.x * 128, n0 = blockIdx.y * 128;
    const float* Ag = A + (size_t)m0 * K;
    const float* Bg = B + n0;
    const uint32_t sb = smem_u32(smem);

    const int arow = tid >> 2, ak4 = (tid & 3) * 4;
    const int brow = tid >> 5, bn4 = (tid & 31) * 4;
    const int NK = K >> 4;

    auto load_stage = [&](int kt, int s) {
        const uint32_t sa = sb + s * STW * 4;
        const uint32_t sB = sa + AWORDS * 4;
        const float* ag = Ag + kt * 16;
        const float* bg = Bg + (size_t)(kt * 16) * N;
#pragma unroll
        for (int i = 0; i < 2; i++) {
            int r = arow + i * 64;
            cp16(sa + (r * AST + ak4) * 4, ag + (size_t)r * K + ak4);
            int kr = brow + i * 8;
            cp16(sB + (kr * BST + bn4) * 4, bg + (size_t)kr * N + bn4);
        }
    };

    float acc[2][8][4];
#pragma unroll
    for (int mt = 0; mt < 2; mt++)
#pragma unroll
        for (int nt = 0; nt < 8; nt++)
#pragma unroll
            for (int i = 0; i < 4; i++) acc[mt][nt][i] = 0.f;

    load_stage(0, 0);
    asm volatile("cp.async.commit_group;" ::: "memory");
    load_stage(1, 1);
    asm volatile("cp.async.commit_group;" ::: "memory");

#pragma unroll 1
    for (int kt = 0; kt < NK; kt++) {
        asm volatile("cp.async.wait_group 1;" ::: "memory");
        __syncthreads();
        if (kt + 2 < NK) load_stage(kt + 2, (kt + 2) % GSTAGES);
        asm volatile("cp.async.commit_group;" ::: "memory");

        const int s = kt % GSTAGES;
        const float* As = smem + s * STW;
        const float* Bs = As + AWORDS;
#pragma unroll
        for (int c8 = 0; c8 < 2; c8++) {
            const int c = c8 * 8;
            uint32_t a[2][4], b[8][2];
            const int kk = c + (lane & 3);
#pragma unroll
            for (int mt = 0; mt < 2; mt++) {
                int r = wm + mt * 16 + (lane >> 2);
                a[mt][0] = __float_as_uint(As[r * AST + kk]);
                a[mt][1] = __float_as_uint(As[(r + 8) * AST + kk]);
                a[mt][2] = __float_as_uint(As[r * AST + kk + 4]);
                a[mt][3] = __float_as_uint(As[(r + 8) * AST + kk + 4]);
            }
#pragma unroll
            for (int nt = 0; nt < 8; nt++) {
                int n = wn + nt * 8 + (lane >> 2);
                b[nt][0] = __float_as_uint(Bs[kk * BST + n]);
                b[nt][1] = __float_as_uint(Bs[(kk + 4) * BST + n]);
            }
#pragma unroll
            for (int mt = 0; mt < 2; mt++)
#pragma unroll
                for (int nt = 0; nt < 8; nt++)
                    mma_tf32(acc[mt][nt], a[mt], b[nt]);
        }
    }

    // epilogue
    const int rbase = m0 + wm + (lane >> 2);
    const int cbase = n0 + wn + (lane & 3) * 2;
    if (!fused || n0 < FQKV) {
        const int ldc = fused ? FQKV : N;
#pragma unroll
        for (int mt = 0; mt < 2; mt++) {
#pragma unroll
            for (int nt = 0; nt < 8; nt++) {
                int r = rbase + mt * 16;
                int cc = cbase + nt * 8;
                float2* p0 = (float2*)(C + (size_t)r * ldc + cc);
                float2* p1 = (float2*)(C + (size_t)(r + 8) * ldc + cc);
                float2 v0 = make_float2(acc[mt][nt][0], acc[mt][nt][1]);
                float2 v1 = make_float2(acc[mt][nt][2], acc[mt][nt][3]);
                if (accum) {
                    float2 o0 = *p0, o1 = *p1;
                    v0.x += o0.x; v0.y += o0.y; v1.x += o1.x; v1.y += o1.y;
                }
                *p0 = v0; *p1 = v1;
            }
        }
    } else {
#pragma unroll
        for (int mt = 0; mt < 2; mt++) {
#pragma unroll
            for (int nt = 0; nt < 8; nt++) {
                int r = rbase + mt * 16;
                int hc = (cbase + nt * 8 - FQKV) >> 1;
                float x0 = acc[mt][nt][0], gg0 = acc[mt][nt][1];
                float x1 = acc[mt][nt][2], gg1 = acc[mt][nt][3];
                Ch[(size_t)r * FFINNER + hc]       = tf32r(x0 * gg0 / (1.f + __expf(-gg0)));
                Ch[(size_t)(r + 8) * FFINNER + hc] = tf32r(x1 * gg1 / (1.f + __expf(-gg1)));
            }
        }
    }
}

// ---------------- weight rounding (+ column pad) ----------------
__global__ void round_pad(const float* __restrict__ in, float* __restrict__ out,
                          int Nin4, int Nout4) {
    int row = blockIdx.y;
    int c4 = blockIdx.x * 256 + threadIdx.x;
    if (c4 >= Nout4) return;
    float4 v = make_float4(0.f, 0.f, 0.f, 0.f);
    if (c4 < Nin4) {
        v = ((const float4*)(in + (size_t)row * Nin4 * 4))[c4];
        v.x = tf32r(v.x); v.y = tf32r(v.y); v.z = tf32r(v.z); v.w = tf32r(v.w);
    }
    ((float4*)(out + (size_t)row * Nout4 * 4))[c4] = v;
}

// ---------------- w_fused rounding + column permutation ----------------
__global__ void round_pad_perm(const float* __restrict__ in, float* __restrict__ out) {
    int row = blockIdx.y;
    int c4 = blockIdx.x * 256 + threadIdx.x;
    if (c4 >= FPAD / 4) return;
    const float* src = in + (size_t)row * FUSEDC;
    float v[4];
#pragma unroll
    for (int e = 0; e < 4; e++) {
        int j = c4 * 4 + e;
        float val;
        if (j < I2) val = src[j];
        else if (j < FQKV) val = 0.f;
        else {
            int p = j - FQKV;
            val = src[I2 + (p >> 1) + (p & 1) * FFINNER];
        }
        v[e] = tf32r(val);
    }
    ((float4*)(out + (size_t)row * FPAD))[c4] = make_float4(v[0], v[1], v[2], v[3]);
}

// ---------------- layernorm (tf32-rounded out) ----------------
__global__ void ln_kernel(const float* __restrict__ x, const float* __restrict__ gamma,
                          float* __restrict__ xn) {
    int row = blockIdx.x;
    const float* xr = x + (size_t)row * DIMX;
    float s = 0.f, s2 = 0.f;
    for (int i = threadIdx.x; i < DIMX; i += 256) { float v = xr[i]; s += v; s2 += v * v; }
    for (int o = 16; o > 0; o >>= 1) {
        s  += __shfl_xor_sync(0xffffffff, s,  o);
        s2 += __shfl_xor_sync(0xffffffff, s2, o);
    }
    __shared__ float sh[16];
    int wid = threadIdx.x >> 5, lane = threadIdx.x & 31;
    if (lane == 0) { sh[wid] = s; sh[8 + wid] = s2; }
    __syncthreads();
    if (threadIdx.x == 0) {
        float S = 0.f, S2 = 0.f;
        for (int w = 0; w < 8; w++) { S += sh[w]; S2 += sh[8 + w]; }
        sh[0] = S; sh[8] = S2;
    }
    __syncthreads();
    float mu = sh[0] * (1.f / DIMX);
    float var = sh[8] * (1.f / DIMX) - mu * mu;
    float inv = rsqrtf(var + 1e-5f);
    float* o = xn + (size_t)row * DIMX;
    for (int i = threadIdx.x; i < DIMX; i += 256)
        o[i] = tf32r((xr[i] - mu) * inv * gamma[i]);
}

// ---------------- LoRA first stage ----------------
__global__ void lora_xa_kernel(const float* __restrict__ xn,
                               const float* __restrict__ aq,
                               const float* __restrict__ ak,
                               const float* __restrict__ av,
                               float* __restrict__ xa) {
    int row = blockIdx.x;
    const float* xr = xn + (size_t)row * DIMX;
    float acc[24];
#pragma unroll
    for (int m = 0; m < 24; m++) acc[m] = 0.f;
    for (int i = threadIdx.x; i < DIMX; i += 256) {
        float v = xr[i];
#pragma unroll
        for (int r = 0; r < 8; r++) {
            acc[r]      += v * aq[i * 8 + r];
            acc[8 + r]  += v * ak[i * 8 + r];
            acc[16 + r] += v * av[i * 8 + r];
        }
    }
    __shared__ float sh[8][24];
    int wid = threadIdx.x >> 5, lane = threadIdx.x & 31;
#pragma unroll
    for (int m = 0; m < 24; m++)
        for (int o = 16; o > 0; o >>= 1)
            acc[m] += __shfl_xor_sync(0xffffffff, acc[m], o);
    if (lane == 0)
#pragma unroll
        for (int m = 0; m < 24; m++) sh[wid][m] = acc[m];
    __syncthreads();
    if (threadIdx.x < 24) {
        float s = 0.f;
        for (int w = 0; w < 8; w++) s += sh[w][threadIdx.x];
        xa[row * 24 + threadIdx.x] = s;
    }
}

// ---------------- qkv prep (F row stride = FQKV) ----------------
__global__ void qkv_prep(const float* __restrict__ F, const float* __restrict__ XA,
                         const float* __restrict__ bq, const float* __restrict__ bk,
                         const float* __restrict__ bv,
                         float* __restrict__ Q, float* __restrict__ Kv, float* __restrict__ V) {
    int row = blockIdx.x;
    int n = row % NSEQ;
    __shared__ float qs[AINNER];
    __shared__ float ks[DHEAD];
    const float* Fr = F + (size_t)row * FQKV;
    const float* xa = XA + row * 24;
    float lq[8], lk[8], lv[8];
#pragma unroll
    for (int r = 0; r < 8; r++) { lq[r] = xa[r]; lk[r] = xa[8 + r]; lv[r] = xa[16 + r]; }

    for (int c = threadIdx.x; c < AINNER; c += 256) {
        float v = Fr[c];
#pragma unroll
        for (int r = 0; r < 8; r++) v += lq[r] * bq[r * AINNER + c];
        qs[c] = v;
    }
    if (threadIdx.x < DHEAD) {
        int c = threadIdx.x;
        float v = Fr[I0 + c];
#pragma unroll
        for (int r = 0; r < 8; r++) v += lk[r] * bk[r * DHEAD + c];
        ks[c] = v;
        float vv = Fr[I1 + c];
#pragma unroll
        for (int r = 0; r < 8; r++) vv += lv[r] * bv[r * DHEAD + c];
        V[(size_t)row * DHEAD + c] = vv;
    }
    __syncthreads();

    const float ln10k_inv32 = 9.2103403719761836f / 32.f;
    const float scale = 0.125f;
    for (int c = threadIdx.x; c < AINNER; c += 256) {
        int h = c >> 6, d = c & 63;
        int fi = d & 31;
        float freq = (float)n * __expf(-(float)fi * ln10k_inv32);
        float cs = cosf(freq), sn = sinf(freq);
        float me = qs[c];
        float partner = (d < 32) ? -qs[h * 64 + d + 32] : qs[h * 64 + d - 32];
        Q[(size_t)row * AINNER + c] = (me * cs + partner * sn) * scale;
    }
    if (threadIdx.x < DHEAD) {
        int d = threadIdx.x;
        int fi = d & 31;
        float freq = (float)n * __expf(-(float)fi * ln10k_inv32);
        float cs = cosf(freq), sn = sinf(freq);
        float me = ks[d];
        float partner = (d < 32) ? -ks[d + 32] : ks[d - 32];
        Kv[(size_t)row * DHEAD + d] = me * cs + partner * sn;
    }
}

// ================= MMA flash attention =================
// block = (qtile64, head, batch), 128 thr (4 warps x 16 q-rows).
// QK^T: 3-pass tf32 split (near-fp32 logits). PV: 1-pass tf32-RNA.
#define ATTN_SMEM ((64*68*3 + 64*72)*4)   // Qs, Ks, Kd (68-stride) + Vs (72-stride)

__global__ __launch_bounds__(128) void attn_mma(const float* __restrict__ Qg,
                                                const float* __restrict__ Kg,
                                                const float* __restrict__ Vg,
                                                float* __restrict__ O) {
    extern __shared__ float sm[];
    float* Qs = sm;                  // [64][68]
    float* Ks = sm + 64 * 68;        // [64][68] tf32 hi
    float* Kd = sm + 2 * 64 * 68;    // [64][68] residual
    float* Vs = sm + 3 * 64 * 68;    // [64][72] tf32 rna

    const int tid = threadIdx.x, wid = tid >> 5, lane = tid & 31;
    const int gq = lane >> 2, tq = lane & 3;
    const int qt = gridDim.x - 1 - blockIdx.x;   // heavy tiles first
    const int h = blockIdx.y, b = blockIdx.z;
    const int q0 = qt * 64;

    // stage Q tile [64 q x 64 d] for this head
    for (int i = tid; i < 1024; i += 128) {
        int r = i >> 4, d4 = (i & 15) * 4;
        *(float4*)(Qs + r * 68 + d4) =
            *(const float4*)(Qg + (size_t)(b * NSEQ + q0 + r) * AINNER + h * 64 + d4);
    }
    __syncthreads();

    // build Q fragments (hi + residual), rows wid*16..+15
    uint32_t qr[8][4], qd[8][4];
#pragma unroll
    for (int k = 0; k < 8; k++) {
#pragma unroll
        for (int e = 0; e < 4; e++) {
            int rr = wid * 16 + gq + (e & 1) * 8;
            int cc = k * 8 + tq + (e >> 1) * 4;
            float v = Qs[rr * 68 + cc];
            float hi = tf32r(v);
            qr[k][e] = __float_as_uint(hi);
            qd[k][e] = __float_as_uint(tf32r(v - hi));
        }
    }

    float o[8][4];
#pragma unroll
    for (int nt = 0; nt < 8; nt++)
#pragma unroll
        for (int e = 0; e < 4; e++) o[nt][e] = 0.f;
    float m0 = -FLT_MAX, m1 = -FLT_MAX, l0 = 0.f, l1 = 0.f;

    const float* Kb = Kg + (size_t)b * NSEQ * DHEAD;
    const float* Vb = Vg + (size_t)b * NSEQ * DHEAD;

    for (int j0 = 0; j0 <= q0; j0 += 64) {
        __syncthreads();
        // load K (hi+residual) and V (rna) chunks
        for (int i = tid; i < 1024; i += 128) {
            int r = i >> 4, d4 = (i & 15) * 4;
            float4 kv = *(const float4*)(Kb + (size_t)(j0 + r) * DHEAD + d4);
            float h0 = tf32r(kv.x), h1 = tf32r(kv.y), h2 = tf32r(kv.z), h3 = tf32r(kv.w);
            *(float4*)(Ks + r * 68 + d4) = make_float4(h0, h1, h2, h3);
            *(float4*)(Kd + r * 68 + d4) =
                make_float4(tf32r(kv.x - h0), tf32r(kv.y - h1), tf32r(kv.z - h2), tf32r(kv.w - h3));
            float4 vv = *(const float4*)(Vb + (size_t)(j0 + r) * DHEAD + d4);
            *(float4*)(Vs + r * 72 + d4) =
                make_float4(tf32r(vv.x), tf32r(vv.y), tf32r(vv.z), tf32r(vv.w));
        }
        __syncthreads();

        // S = Q @ K^T  (3-pass)
        float s[8][4];
#pragma unroll
        for (int nt = 0; nt < 8; nt++) {
            s[nt][0] = s[nt][1] = s[nt][2] = s[nt][3] = 0.f;
            const float* krow = Ks + (nt * 8 + gq) * 68;
            const float* drow = Kd + (nt * 8 + gq) * 68;
#pragma unroll
            for (int k = 0; k < 8; k++) {
                uint32_t br[2] = { __float_as_uint(krow[k * 8 + tq]),
                                   __float_as_uint(krow[k * 8 + tq + 4]) };
                uint32_t bd[2] = { __float_as_uint(drow[k * 8 + tq]),
                                   __float_as_uint(drow[k * 8 + tq + 4]) };
                mma_tf32(s[nt], qr[k], br);
                mma_tf32(s[nt], qd[k], br);
                mma_tf32(s[nt], qr[k], bd);
            }
        }

        // causal mask (only the diagonal chunk)
        if (j0 == q0) {
            int r0 = wid * 16 + gq, r1 = r0 + 8;
#pragma unroll
            for (int nt = 0; nt < 8; nt++) {
                int jc = nt * 8 + 2 * tq;
                if (jc     > r0) s[nt][0] = -1e30f;
                if (jc + 1 > r0) s[nt][1] = -1e30f;
                if (jc     > r1) s[nt][2] = -1e30f;
                if (jc + 1 > r1) s[nt][3] = -1e30f;
            }
        }

        // online softmax
        float rx0 = -1e30f, rx1 = -1e30f;
#pragma unroll
        for (int nt = 0; nt < 8; nt++) {
            rx0 = fmaxf(rx0, fmaxf(s[nt][0], s[nt][1]));
            rx1 = fmaxf(rx1, fmaxf(s[nt][2], s[nt][3]));
        }
        rx0 = fmaxf(rx0, __shfl_xor_sync(0xffffffff, rx0, 1));
        rx0 = fmaxf(rx0, __shfl_xor_sync(0xffffffff, rx0, 2));
        rx1 = fmaxf(rx1, __shfl_xor_sync(0xffffffff, rx1, 1));
        rx1 = fmaxf(rx1, __shfl_xor_sync(0xffffffff, rx1, 2));
        float mn0 = fmaxf(m0, rx0), mn1 = fmaxf(m1, rx1);
        float c0 = __expf(m0 - mn0), c1 = __expf(m1 - mn1);
        float ps0 = 0.f, ps1 = 0.f;
#pragma unroll
        for (int nt = 0; nt < 8; nt++) {
            s[nt][0] = __expf(s[nt][0] - mn0);
            s[nt][1] = __expf(s[nt][1] - mn0);
            s[nt][2] = __expf(s[nt][2] - mn1);
            s[nt][3] = __expf(s[nt][3] - mn1);
            ps0 += s[nt][0] + s[nt][1];
            ps1 += s[nt][2] + s[nt][3];
        }
        ps0 += __shfl_xor_sync(0xffffffff, ps0, 1);
        ps0 += __shfl_xor_sync(0xffffffff, ps0, 2);
        ps1 += __shfl_xor_sync(0xffffffff, ps1, 1);
        ps1 += __shfl_xor_sync(0xffffffff, ps1, 2);
        l0 = l0 * c0 + ps0;
        l1 = l1 * c1 + ps1;
#pragma unroll
        for (int nt = 0; nt < 8; nt++) {
            o[nt][0] *= c0; o[nt][1] *= c0;
            o[nt][2] *= c1; o[nt][3] *= c1;
        }
        m0 = mn0; m1 = mn1;

        // P: C-layout -> A-layout via quad shuffles, with RNA rounding
        uint32_t ap[8][4];
#pragma unroll
        for (int ks = 0; ks < 8; ks++) {
            int base = lane & ~3;
            int s0 = base + (tq >> 1), s1 = s0 + 2;
            float v00 = __shfl_sync(0xffffffff, s[ks][0], s0);
            float v01 = __shfl_sync(0xffffffff, s[ks][1], s0);
            float v20 = __shfl_sync(0xffffffff, s[ks][2], s0);
            float v21 = __shfl_sync(0xffffffff, s[ks][3], s0);
            float w00 = __shfl_sync(0xffffffff, s[ks][0], s1);
            float w01 = __shfl_sync(0xffffffff, s[ks][1], s1);
            float w20 = __shfl_sync(0xffffffff, s[ks][2], s1);
            float w21 = __shfl_sync(0xffffffff, s[ks][3], s1);
            bool oq = tq & 1;
            ap[ks][0] = __float_as_uint(tf32r(oq ? v01 : v00));
            ap[ks][1] = __float_as_uint(tf32r(oq ? v21 : v20));
            ap[ks][2] = __float_as_uint(tf32r(oq ? w01 : w00));
            ap[ks][3] = __float_as_uint(tf32r(oq ? w21 : w20));
        }

        // O += P @ V
#pragma unroll
        for (int nt = 0; nt < 8; nt++) {
#pragma unroll
            for (int ks = 0; ks < 8; ks++) {
                int vr = ks * 8 + tq;
                int vc = nt * 8 + gq;
                uint32_t bv[2] = { __float_as_uint(Vs[vr * 72 + vc]),
                                   __float_as_uint(Vs[(vr + 4) * 72 + vc]) };
                mma_tf32(o[nt], ap[ks], bv);
            }
        }
    }

    // normalize + store (tf32-rounded, feeds next GEMM)
    float il0 = 1.f / l0, il1 = 1.f / l1;
    int rg0 = b * NSEQ + q0 + wid * 16 + gq;
#pragma unroll
    for (int nt = 0; nt < 8; nt++) {
        int col = h * 64 + nt * 8 + 2 * tq;
        float2 v0 = make_float2(tf32r(o[nt][0] * il0), tf32r(o[nt][1] * il0));
        float2 v1 = make_float2(tf32r(o[nt][2] * il1), tf32r(o[nt][3] * il1));
        *(float2*)(O + (size_t)rg0 * AINNER + col) = v0;
        *(float2*)(O + (size_t)(rg0 + 8) * AINNER + col) = v1;
    }
}

// ---------------- OA[row,8] = OATTN_row @ a_o ----------------
__global__ void lora_oa_kernel(const float* __restrict__ oattn,
                               const float* __restrict__ ao,
                               float* __restrict__ oa) {
    int row = blockIdx.x;
    const float* xr = oattn + (size_t)row * AINNER;
    float acc[8];
#pragma unroll
    for (int r = 0; r < 8; r++) acc[r] = 0.f;
    for (int i = threadIdx.x; i < AINNER; i += 256) {
        float v = xr[i];
#pragma unroll
        for (int r = 0; r < 8; r++) acc[r] += v * ao[i * 8 + r];
    }
    __shared__ float sh[8][8];
    int wid = threadIdx.x >> 5, lane = threadIdx.x & 31;
#pragma unroll
    for (int r = 0; r < 8; r++)
        for (int o = 16; o > 0; o >>= 1)
            acc[r] += __shfl_xor_sync(0xffffffff, acc[r], o);
    if (lane == 0)
#pragma unroll
        for (int r = 0; r < 8; r++) sh[wid][r] = acc[r];
    __syncthreads();
    if (threadIdx.x < 8) {
        float s = 0.f;
        for (int w = 0; w < 8; w++) s += sh[w][threadIdx.x];
        oa[row * 8 + threadIdx.x] = s;
    }
}

// ---------------- out += OA @ b_o ----------------
__global__ void lora_o_add(const float* __restrict__ oa, const float* __restrict__ bo,
                           float* __restrict__ out) {
    int row = blockIdx.y;
    int c = blockIdx.x * 256 + threadIdx.x;
    float s = 0.f;
#pragma unroll
    for (int r = 0; r < 8; r++) s += oa[row * 8 + r] * bo[r * DIMX + c];
    out[(size_t)row * DIMX + c] += s;
}

// ---------------- launch ----------------
extern "C" void kernel_launch(void* const* d_in, const int* in_sizes, int n_in,
                              void* d_out, int out_size) {
    const float* x          = (const float*)d_in[0];
    const float* gamma      = (const float*)d_in[1];
    const float* w_fused    = (const float*)d_in[2];
    const float* w_attn_out = (const float*)d_in[3];
    const float* w_ff_out   = (const float*)d_in[4];
    const float* a_q        = (const float*)d_in[5];
    const float* b_q        = (const float*)d_in[6];
    const float* a_k        = (const float*)d_in[7];
    const float* b_k        = (const float*)d_in[8];
    const float* a_v        = (const float*)d_in[9];
    const float* b_v        = (const float*)d_in[10];
    const float* a_o        = (const float*)d_in[11];
    const float* b_o        = (const float*)d_in[12];
    float* out = (float*)d_out;

    float *XN, *WF, *F, *XA, *Q, *K, *V, *OATTN, *WAO, *H, *WFF, *OA;
    cudaGetSymbolAddress((void**)&XN, g_XN);
    cudaGetSymbolAddress((void**)&WF, g_WF);
    cudaGetSymbolAddress((void**)&F, g_F);
    cudaGetSymbolAddress((void**)&XA, g_XA);
    cudaGetSymbolAddress((void**)&Q, g_Q);
    cudaGetSymbolAddress((void**)&K, g_K);
    cudaGetSymbolAddress((void**)&V, g_V);
    cudaGetSymbolAddress((void**)&OATTN, g_OATTN);
    cudaGetSymbolAddress((void**)&WAO, g_WAO);
    cudaGetSymbolAddress((void**)&H, g_H);
    cudaGetSymbolAddress((void**)&WFF, g_WFF);
    cudaGetSymbolAddress((void**)&OA, g_OA);

    cudaFuncSetAttribute(tf32_gemm, cudaFuncAttributeMaxDynamicSharedMemorySize, GSMEM);
    cudaFuncSetAttribute(attn_mma, cudaFuncAttributeMaxDynamicSharedMemorySize, ATTN_SMEM);

    // weight rounding (+permutation for fused)
    round_pad_perm<<<dim3((FPAD / 4 + 255) / 256, DIMX), 256>>>(w_fused, WF);
    round_pad<<<dim3((DIMX / 4 + 255) / 256, AINNER), 256>>>(w_attn_out, WAO, DIMX / 4, DIMX / 4);
    round_pad<<<dim3((DIMX / 4 + 255) / 256, FFINNER), 256>>>(w_ff_out, WFF, DIMX / 4, DIMX / 4);

    ln_kernel<<<ROWS, 256>>>(x, gamma, XN);
    tf32_gemm<<<dim3(ROWS / 128, FPAD / 128), 256, GSMEM>>>(XN, WF, F, H, FPAD, DIMX, 0, 1);
    lora_xa_kernel<<<ROWS, 256>>>(XN, a_q, a_k, a_v, XA);
    qkv_prep<<<ROWS, 256>>>(F, XA, b_q, b_k, b_v, Q, K, V);
    attn_mma<<<dim3(NSEQ / 64, HEADS, BATCH), 128, ATTN_SMEM>>>(Q, K, V, OATTN);
    tf32_gemm<<<dim3(ROWS / 128, DIMX / 128), 256, GSMEM>>>(OATTN, WAO, out, nullptr, DIMX, AINNER, 0, 0);
    lora_oa_kernel<<<ROWS, 256>>>(OATTN, a_o, OA);
    tf32_gemm<<<dim3(ROWS / 128, DIMX / 128), 256, GSMEM>>>(H, WFF, out, nullptr, DIMX, FFINNER, 1, 0);
    lora_o_add<<<dim3(DIMX / 256, ROWS), 256>>>(OA, b_o, out);
}

// round 8
// speedup vs baseline: 1.3933x; 1.0259x over previous
#include <cuda_runtime.h>
#include <cuda_bf16.h>
#include <math.h>
#include <float.h>
#include <stdint.h>

// ---------------- problem constants ----------------
#define DIMX 2048
#define NSEQ 2048
#define BATCH 2
#define HEADS 16
#define DHEAD 64
#define ROWS (BATCH*NSEQ)          // 4096
#define AINNER 1024
#define FFINNER 8192
#define FUSEDC 17536               // 1024+64+64+2*8192
#define FPAD 17664                 // 138*128 (permuted width)
#define FQKV 1280                  // qkv cols (1152) padded to 128-multiple
#define I0 1024
#define I1 1088
#define I2 1152

// ---------------- scratch (device globals) --------
__device__ float g_XN[(size_t)ROWS*DIMX];
__device__ float g_WF[(size_t)DIMX*FPAD];        // rounded + permuted w_fused
__device__ float g_F[(size_t)ROWS*FQKV];         // qkv part only
__device__ float g_XA[ROWS*24];
__device__ float g_Q[(size_t)ROWS*AINNER];
__device__ float g_K[(size_t)ROWS*DHEAD];
__device__ float g_V[(size_t)ROWS*DHEAD];
__device__ float g_OATTN[(size_t)ROWS*AINNER];
__device__ float g_WAO[(size_t)AINNER*DIMX];
__device__ float g_H[(size_t)ROWS*FFINNER];
__device__ float g_WFF[(size_t)FFINNER*DIMX];
__device__ float g_OA[ROWS*8];

// ---------------- small helpers ----------------
__device__ __forceinline__ float tf32r(float x) {
    uint32_t u;
    asm("cvt.rna.tf32.f32 %0, %1;" : "=r"(u) : "f"(x));
    return __uint_as_float(u);
}
__device__ __forceinline__ uint32_t smem_u32(const void* p) {
    uint32_t a;
    asm("{ .reg .u64 t; cvta.to.shared.u64 t, %1; cvt.u32.u64 %0, t; }" : "=r"(a) : "l"(p));
    return a;
}
__device__ __forceinline__ void cp16(uint32_t saddr, const void* g) {
    asm volatile("cp.async.cg.shared.global [%0], [%1], 16;" :: "r"(saddr), "l"(g) : "memory");
}
__device__ __forceinline__ void mma_tf32(float* d, const uint32_t* a, const uint32_t* b) {
    asm volatile(
        "mma.sync.aligned.m16n8k8.row.col.f32.tf32.tf32.f32 "
        "{%0,%1,%2,%3}, {%4,%5,%6,%7}, {%8,%9}, {%0,%1,%2,%3};"
        : "+f"(d[0]), "+f"(d[1]), "+f"(d[2]), "+f"(d[3])
        : "r"(a[0]), "r"(a[1]), "r"(a[2]), "r"(a[3]), "r"(b[0]), "r"(b[1]));
}

// ================= TF32 GEMM (5-stage deep pipeline) =================
#define GSTAGES 5
#define AST 20
#define BST 136
#define AWORDS (128*AST)  // 2560
#define BWORDS (16*BST)   // 2176
#define STW (AWORDS+BWORDS)   // 4736
#define GSMEM (GSTAGES*STW*4) // 94720 bytes

__global__ __launch_bounds__(256) void tf32_gemm(const float* __restrict__ A,
                                                 const float* __restrict__ B,
                                                 float* __restrict__ C,
                                                 float* __restrict__ Ch,
                                                 int N, int K, int accum, int fused) {
    extern __shared__ float smem[];
    const int tid = threadIdx.x;
    const int wid = tid >> 5, lane = tid & 31;
    const int wm = (wid & 3) * 32, wn = (wid >> 2) * 64;
    const int m0 = blockIdx.x * 128, n0 = blockIdx.y * 128;
    const float* Ag = A + (size_t)m0 * K;
    const float* Bg = B + n0;
    const uint32_t sb = smem_u32(smem);

    const int arow = tid >> 2, ak4 = (tid & 3) * 4;
    const int brow = tid >> 5, bn4 = (tid & 31) * 4;
    const int NK = K >> 4;

    auto load_stage = [&](int kt, int s) {
        const uint32_t sa = sb + s * STW * 4;
        const uint32_t sB = sa + AWORDS * 4;
        const float* ag = Ag + kt * 16;
        const float* bg = Bg + (size_t)(kt * 16) * N;
#pragma unroll
        for (int i = 0; i < 2; i++) {
            int r = arow + i * 64;
            cp16(sa + (r * AST + ak4) * 4, ag + (size_t)r * K + ak4);
            int kr = brow + i * 8;
            cp16(sB + (kr * BST + bn4) * 4, bg + (size_t)kr * N + bn4);
        }
    };

    float acc[2][8][4];
#pragma unroll
    for (int mt = 0; mt < 2; mt++)
#pragma unroll
        for (int nt = 0; nt < 8; nt++)
#pragma unroll
            for (int i = 0; i < 4; i++) acc[mt][nt][i] = 0.f;

    // prologue: fill 4 of 5 stages
#pragma unroll
    for (int p = 0; p < 4; p++) {
        load_stage(p, p);
        asm volatile("cp.async.commit_group;" ::: "memory");
    }

#pragma unroll 1
    for (int kt = 0; kt < NK; kt++) {
        asm volatile("cp.async.wait_group 3;" ::: "memory");
        __syncthreads();
        if (kt + 4 < NK) load_stage(kt + 4, (kt + 4) % GSTAGES);
        asm volatile("cp.async.commit_group;" ::: "memory");

        const int s = kt % GSTAGES;
        const float* As = smem + s * STW;
        const float* Bs = As + AWORDS;
#pragma unroll
        for (int c8 = 0; c8 < 2; c8++) {
            const int c = c8 * 8;
            uint32_t a[2][4], b[8][2];
            const int kk = c + (lane & 3);
#pragma unroll
            for (int mt = 0; mt < 2; mt++) {
                int r = wm + mt * 16 + (lane >> 2);
                a[mt][0] = __float_as_uint(As[r * AST + kk]);
                a[mt][1] = __float_as_uint(As[(r + 8) * AST + kk]);
                a[mt][2] = __float_as_uint(As[r * AST + kk + 4]);
                a[mt][3] = __float_as_uint(As[(r + 8) * AST + kk + 4]);
            }
#pragma unroll
            for (int nt = 0; nt < 8; nt++) {
                int n = wn + nt * 8 + (lane >> 2);
                b[nt][0] = __float_as_uint(Bs[kk * BST + n]);
                b[nt][1] = __float_as_uint(Bs[(kk + 4) * BST + n]);
            }
#pragma unroll
            for (int mt = 0; mt < 2; mt++)
#pragma unroll
                for (int nt = 0; nt < 8; nt++)
                    mma_tf32(acc[mt][nt], a[mt], b[nt]);
        }
    }

    // epilogue
    const int rbase = m0 + wm + (lane >> 2);
    const int cbase = n0 + wn + (lane & 3) * 2;
    if (!fused || n0 < FQKV) {
        const int ldc = fused ? FQKV : N;
#pragma unroll
        for (int mt = 0; mt < 2; mt++) {
#pragma unroll
            for (int nt = 0; nt < 8; nt++) {
                int r = rbase + mt * 16;
                int cc = cbase + nt * 8;
                float2* p0 = (float2*)(C + (size_t)r * ldc + cc);
                float2* p1 = (float2*)(C + (size_t)(r + 8) * ldc + cc);
                float2 v0 = make_float2(acc[mt][nt][0], acc[mt][nt][1]);
                float2 v1 = make_float2(acc[mt][nt][2], acc[mt][nt][3]);
                if (accum) {
                    float2 o0 = *p0, o1 = *p1;
                    v0.x += o0.x; v0.y += o0.y; v1.x += o1.x; v1.y += o1.y;
                }
                *p0 = v0; *p1 = v1;
            }
        }
    } else {
#pragma unroll
        for (int mt = 0; mt < 2; mt++) {
#pragma unroll
            for (int nt = 0; nt < 8; nt++) {
                int r = rbase + mt * 16;
                int hc = (cbase + nt * 8 - FQKV) >> 1;
                float x0 = acc[mt][nt][0], gg0 = acc[mt][nt][1];
                float x1 = acc[mt][nt][2], gg1 = acc[mt][nt][3];
                Ch[(size_t)r * FFINNER + hc]       = tf32r(x0 * gg0 / (1.f + __expf(-gg0)));
                Ch[(size_t)(r + 8) * FFINNER + hc] = tf32r(x1 * gg1 / (1.f + __expf(-gg1)));
            }
        }
    }
}

// ---------------- weight rounding (+ column pad) ----------------
__global__ void round_pad(const float* __restrict__ in, float* __restrict__ out,
                          int Nin4, int Nout4) {
    int row = blockIdx.y;
    int c4 = blockIdx.x * 256 + threadIdx.x;
    if (c4 >= Nout4) return;
    float4 v = make_float4(0.f, 0.f, 0.f, 0.f);
    if (c4 < Nin4) {
        v = ((const float4*)(in + (size_t)row * Nin4 * 4))[c4];
        v.x = tf32r(v.x); v.y = tf32r(v.y); v.z = tf32r(v.z); v.w = tf32r(v.w);
    }
    ((float4*)(out + (size_t)row * Nout4 * 4))[c4] = v;
}

// ---------------- w_fused rounding + column permutation ----------------
__global__ void round_pad_perm(const float* __restrict__ in, float* __restrict__ out) {
    int row = blockIdx.y;
    int c4 = blockIdx.x * 256 + threadIdx.x;
    if (c4 >= FPAD / 4) return;
    const float* src = in + (size_t)row * FUSEDC;
    float v[4];
#pragma unroll
    for (int e = 0; e < 4; e++) {
        int j = c4 * 4 + e;
        float val;
        if (j < I2) val = src[j];
        else if (j < FQKV) val = 0.f;
        else {
            int p = j - FQKV;
            val = src[I2 + (p >> 1) + (p & 1) * FFINNER];
        }
        v[e] = tf32r(val);
    }
    ((float4*)(out + (size_t)row * FPAD))[c4] = make_float4(v[0], v[1], v[2], v[3]);
}

// ---------------- layernorm (tf32-rounded out) ----------------
__global__ void ln_kernel(const float* __restrict__ x, const float* __restrict__ gamma,
                          float* __restrict__ xn) {
    int row = blockIdx.x;
    const float* xr = x + (size_t)row * DIMX;
    float s = 0.f, s2 = 0.f;
    for (int i = threadIdx.x; i < DIMX; i += 256) { float v = xr[i]; s += v; s2 += v * v; }
    for (int o = 16; o > 0; o >>= 1) {
        s  += __shfl_xor_sync(0xffffffff, s,  o);
        s2 += __shfl_xor_sync(0xffffffff, s2, o);
    }
    __shared__ float sh[16];
    int wid = threadIdx.x >> 5, lane = threadIdx.x & 31;
    if (lane == 0) { sh[wid] = s; sh[8 + wid] = s2; }
    __syncthreads();
    if (threadIdx.x == 0) {
        float S = 0.f, S2 = 0.f;
        for (int w = 0; w < 8; w++) { S += sh[w]; S2 += sh[8 + w]; }
        sh[0] = S; sh[8] = S2;
    }
    __syncthreads();
    float mu = sh[0] * (1.f / DIMX);
    float var = sh[8] * (1.f / DIMX) - mu * mu;
    float inv = rsqrtf(var + 1e-5f);
    float* o = xn + (size_t)row * DIMX;
    for (int i = threadIdx.x; i < DIMX; i += 256)
        o[i] = tf32r((xr[i] - mu) * inv * gamma[i]);
}

// ---------------- LoRA first stage ----------------
__global__ void lora_xa_kernel(const float* __restrict__ xn,
                               const float* __restrict__ aq,
                               const float* __restrict__ ak,
                               const float* __restrict__ av,
                               float* __restrict__ xa) {
    int row = blockIdx.x;
    const float* xr = xn + (size_t)row * DIMX;
    float acc[24];
#pragma unroll
    for (int m = 0; m < 24; m++) acc[m] = 0.f;
    for (int i = threadIdx.x; i < DIMX; i += 256) {
        float v = xr[i];
#pragma unroll
        for (int r = 0; r < 8; r++) {
            acc[r]      += v * aq[i * 8 + r];
            acc[8 + r]  += v * ak[i * 8 + r];
            acc[16 + r] += v * av[i * 8 + r];
        }
    }
    __shared__ float sh[8][24];
    int wid = threadIdx.x >> 5, lane = threadIdx.x & 31;
#pragma unroll
    for (int m = 0; m < 24; m++)
        for (int o = 16; o > 0; o >>= 1)
            acc[m] += __shfl_xor_sync(0xffffffff, acc[m], o);
    if (lane == 0)
#pragma unroll
        for (int m = 0; m < 24; m++) sh[wid][m] = acc[m];
    __syncthreads();
    if (threadIdx.x < 24) {
        float s = 0.f;
        for (int w = 0; w < 8; w++) s += sh[w][threadIdx.x];
        xa[row * 24 + threadIdx.x] = s;
    }
}

// ---------------- qkv prep (F row stride = FQKV) ----------------
__global__ void qkv_prep(const float* __restrict__ F, const float* __restrict__ XA,
                         const float* __restrict__ bq, const float* __restrict__ bk,
                         const float* __restrict__ bv,
                         float* __restrict__ Q, float* __restrict__ Kv, float* __restrict__ V) {
    int row = blockIdx.x;
    int n = row % NSEQ;
    __shared__ float qs[AINNER];
    __shared__ float ks[DHEAD];
    const float* Fr = F + (size_t)row * FQKV;
    const float* xa = XA + row * 24;
    float lq[8], lk[8], lv[8];
#pragma unroll
    for (int r = 0; r < 8; r++) { lq[r] = xa[r]; lk[r] = xa[8 + r]; lv[r] = xa[16 + r]; }

    for (int c = threadIdx.x; c < AINNER; c += 256) {
        float v = Fr[c];
#pragma unroll
        for (int r = 0; r < 8; r++) v += lq[r] * bq[r * AINNER + c];
        qs[c] = v;
    }
    if (threadIdx.x < DHEAD) {
        int c = threadIdx.x;
        float v = Fr[I0 + c];
#pragma unroll
        for (int r = 0; r < 8; r++) v += lk[r] * bk[r * DHEAD + c];
        ks[c] = v;
        float vv = Fr[I1 + c];
#pragma unroll
        for (int r = 0; r < 8; r++) vv += lv[r] * bv[r * DHEAD + c];
        V[(size_t)row * DHEAD + c] = vv;
    }
    __syncthreads();

    const float ln10k_inv32 = 9.2103403719761836f / 32.f;
    const float scale = 0.125f;
    for (int c = threadIdx.x; c < AINNER; c += 256) {
        int h = c >> 6, d = c & 63;
        int fi = d & 31;
        float freq = (float)n * __expf(-(float)fi * ln10k_inv32);
        float cs = cosf(freq), sn = sinf(freq);
        float me = qs[c];
        float partner = (d < 32) ? -qs[h * 64 + d + 32] : qs[h * 64 + d - 32];
        Q[(size_t)row * AINNER + c] = (me * cs + partner * sn) * scale;
    }
    if (threadIdx.x < DHEAD) {
        int d = threadIdx.x;
        int fi = d & 31;
        float freq = (float)n * __expf(-(float)fi * ln10k_inv32);
        float cs = cosf(freq), sn = sinf(freq);
        float me = ks[d];
        float partner = (d < 32) ? -ks[d + 32] : ks[d - 32];
        Kv[(size_t)row * DHEAD + d] = me * cs + partner * sn;
    }
}

// ================= MMA flash attention =================
#define ATTN_SMEM ((64*68*3 + 64*72)*4)

__global__ __launch_bounds__(128) void attn_mma(const float* __restrict__ Qg,
                                                const float* __restrict__ Kg,
                                                const float* __restrict__ Vg,
                                                float* __restrict__ O) {
    extern __shared__ float sm[];
    float* Qs = sm;                  // [64][68]
    float* Ks = sm + 64 * 68;        // [64][68] tf32 hi
    float* Kd = sm + 2 * 64 * 68;    // [64][68] residual
    float* Vs = sm + 3 * 64 * 68;    // [64][72] tf32 rna

    const int tid = threadIdx.x, wid = tid >> 5, lane = tid & 31;
    const int gq = lane >> 2, tq = lane & 3;
    const int qt = gridDim.x - 1 - blockIdx.x;
    const int h = blockIdx.y, b = blockIdx.z;
    const int q0 = qt * 64;

    for (int i = tid; i < 1024; i += 128) {
        int r = i >> 4, d4 = (i & 15) * 4;
        *(float4*)(Qs + r * 68 + d4) =
            *(const float4*)(Qg + (size_t)(b * NSEQ + q0 + r) * AINNER + h * 64 + d4);
    }
    __syncthreads();

    uint32_t qr[8][4], qd[8][4];
#pragma unroll
    for (int k = 0; k < 8; k++) {
#pragma unroll
        for (int e = 0; e < 4; e++) {
            int rr = wid * 16 + gq + (e & 1) * 8;
            int cc = k * 8 + tq + (e >> 1) * 4;
            float v = Qs[rr * 68 + cc];
            float hi = tf32r(v);
            qr[k][e] = __float_as_uint(hi);
            qd[k][e] = __float_as_uint(tf32r(v - hi));
        }
    }

    float o[8][4];
#pragma unroll
    for (int nt = 0; nt < 8; nt++)
#pragma unroll
        for (int e = 0; e < 4; e++) o[nt][e] = 0.f;
    float m0 = -FLT_MAX, m1 = -FLT_MAX, l0 = 0.f, l1 = 0.f;

    const float* Kb = Kg + (size_t)b * NSEQ * DHEAD;
    const float* Vb = Vg + (size_t)b * NSEQ * DHEAD;

    for (int j0 = 0; j0 <= q0; j0 += 64) {
        __syncthreads();
        for (int i = tid; i < 1024; i += 128) {
            int r = i >> 4, d4 = (i & 15) * 4;
            float4 kv = *(const float4*)(Kb + (size_t)(j0 + r) * DHEAD + d4);
            float h0 = tf32r(kv.x), h1 = tf32r(kv.y), h2 = tf32r(kv.z), h3 = tf32r(kv.w);
            *(float4*)(Ks + r * 68 + d4) = make_float4(h0, h1, h2, h3);
            *(float4*)(Kd + r * 68 + d4) =
                make_float4(tf32r(kv.x - h0), tf32r(kv.y - h1), tf32r(kv.z - h2), tf32r(kv.w - h3));
            float4 vv = *(const float4*)(Vb + (size_t)(j0 + r) * DHEAD + d4);
            *(float4*)(Vs + r * 72 + d4) =
                make_float4(tf32r(vv.x), tf32r(vv.y), tf32r(vv.z), tf32r(vv.w));
        }
        __syncthreads();

        float s[8][4];
#pragma unroll
        for (int nt = 0; nt < 8; nt++) {
            s[nt][0] = s[nt][1] = s[nt][2] = s[nt][3] = 0.f;
            const float* krow = Ks + (nt * 8 + gq) * 68;
            const float* drow = Kd + (nt * 8 + gq) * 68;
#pragma unroll
            for (int k = 0; k < 8; k++) {
                uint32_t br[2] = { __float_as_uint(krow[k * 8 + tq]),
                                   __float_as_uint(krow[k * 8 + tq + 4]) };
                uint32_t bd[2] = { __float_as_uint(drow[k * 8 + tq]),
                                   __float_as_uint(drow[k * 8 + tq + 4]) };
                mma_tf32(s[nt], qr[k], br);
                mma_tf32(s[nt], qd[k], br);
                mma_tf32(s[nt], qr[k], bd);
            }
        }

        if (j0 == q0) {
            int r0 = wid * 16 + gq, r1 = r0 + 8;
#pragma unroll
            for (int nt = 0; nt < 8; nt++) {
                int jc = nt * 8 + 2 * tq;
                if (jc     > r0) s[nt][0] = -1e30f;
                if (jc + 1 > r0) s[nt][1] = -1e30f;
                if (jc     > r1) s[nt][2] = -1e30f;
                if (jc + 1 > r1) s[nt][3] = -1e30f;
            }
        }

        float rx0 = -1e30f, rx1 = -1e30f;
#pragma unroll
        for (int nt = 0; nt < 8; nt++) {
            rx0 = fmaxf(rx0, fmaxf(s[nt][0], s[nt][1]));
            rx1 = fmaxf(rx1, fmaxf(s[nt][2], s[nt][3]));
        }
        rx0 = fmaxf(rx0, __shfl_xor_sync(0xffffffff, rx0, 1));
        rx0 = fmaxf(rx0, __shfl_xor_sync(0xffffffff, rx0, 2));
        rx1 = fmaxf(rx1, __shfl_xor_sync(0xffffffff, rx1, 1));
        rx1 = fmaxf(rx1, __shfl_xor_sync(0xffffffff, rx1, 2));
        float mn0 = fmaxf(m0, rx0), mn1 = fmaxf(m1, rx1);
        float c0 = __expf(m0 - mn0), c1 = __expf(m1 - mn1);
        float ps0 = 0.f, ps1 = 0.f;
#pragma unroll
        for (int nt = 0; nt < 8; nt++) {
            s[nt][0] = __expf(s[nt][0] - mn0);
            s[nt][1] = __expf(s[nt][1] - mn0);
            s[nt][2] = __expf(s[nt][2] - mn1);
            s[nt][3] = __expf(s[nt][3] - mn1);
            ps0 += s[nt][0] + s[nt][1];
            ps1 += s[nt][2] + s[nt][3];
        }
        ps0 += __shfl_xor_sync(0xffffffff, ps0, 1);
        ps0 += __shfl_xor_sync(0xffffffff, ps0, 2);
        ps1 += __shfl_xor_sync(0xffffffff, ps1, 1);
        ps1 += __shfl_xor_sync(0xffffffff, ps1, 2);
        l0 = l0 * c0 + ps0;
        l1 = l1 * c1 + ps1;
#pragma unroll
        for (int nt = 0; nt < 8; nt++) {
            o[nt][0] *= c0; o[nt][1] *= c0;
            o[nt][2] *= c1; o[nt][3] *= c1;
        }
        m0 = mn0; m1 = mn1;

        uint32_t ap[8][4];
#pragma unroll
        for (int ks = 0; ks < 8; ks++) {
            int base = lane & ~3;
            int s0 = base + (tq >> 1), s1 = s0 + 2;
            float v00 = __shfl_sync(0xffffffff, s[ks][0], s0);
            float v01 = __shfl_sync(0xffffffff, s[ks][1], s0);
            float v20 = __shfl_sync(0xffffffff, s[ks][2], s0);
            float v21 = __shfl_sync(0xffffffff, s[ks][3], s0);
            float w00 = __shfl_sync(0xffffffff, s[ks][0], s1);
            float w01 = __shfl_sync(0xffffffff, s[ks][1], s1);
            float w20 = __shfl_sync(0xffffffff, s[ks][2], s1);
            float w21 = __shfl_sync(0xffffffff, s[ks][3], s1);
            bool oq = tq & 1;
            ap[ks][0] = __float_as_uint(tf32r(oq ? v01 : v00));
            ap[ks][1] = __float_as_uint(tf32r(oq ? v21 : v20));
            ap[ks][2] = __float_as_uint(tf32r(oq ? w01 : w00));
            ap[ks][3] = __float_as_uint(tf32r(oq ? w21 : w20));
        }

#pragma unroll
        for (int nt = 0; nt < 8; nt++) {
#pragma unroll
            for (int ks = 0; ks < 8; ks++) {
                int vr = ks * 8 + tq;
                int vc = nt * 8 + gq;
                uint32_t bv[2] = { __float_as_uint(Vs[vr * 72 + vc]),
                                   __float_as_uint(Vs[(vr + 4) * 72 + vc]) };
                mma_tf32(o[nt], ap[ks], bv);
            }
        }
    }

    float il0 = 1.f / l0, il1 = 1.f / l1;
    int rg0 = b * NSEQ + q0 + wid * 16 + gq;
#pragma unroll
    for (int nt = 0; nt < 8; nt++) {
        int col = h * 64 + nt * 8 + 2 * tq;
        float2 v0 = make_float2(tf32r(o[nt][0] * il0), tf32r(o[nt][1] * il0));
        float2 v1 = make_float2(tf32r(o[nt][2] * il1), tf32r(o[nt][3] * il1));
        *(float2*)(O + (size_t)rg0 * AINNER + col) = v0;
        *(float2*)(O + (size_t)(rg0 + 8) * AINNER + col) = v1;
    }
}

// ---------------- OA[row,8] = OATTN_row @ a_o ----------------
__global__ void lora_oa_kernel(const float* __restrict__ oattn,
                               const float* __restrict__ ao,
                               float* __restrict__ oa) {
    int row = blockIdx.x;
    const float* xr = oattn + (size_t)row * AINNER;
    float acc[8];
#pragma unroll
    for (int r = 0; r < 8; r++) acc[r] = 0.f;
    for (int i = threadIdx.x; i < AINNER; i += 256) {
        float v = xr[i];
#pragma unroll
        for (int r = 0; r < 8; r++) acc[r] += v * ao[i * 8 + r];
    }
    __shared__ float sh[8][8];
    int wid = threadIdx.x >> 5, lane = threadIdx.x & 31;
#pragma unroll
    for (int r = 0; r < 8; r++)
        for (int o = 16; o > 0; o >>= 1)
            acc[r] += __shfl_xor_sync(0xffffffff, acc[r], o);
    if (lane == 0)
#pragma unroll
        for (int r = 0; r < 8; r++) sh[wid][r] = acc[r];
    __syncthreads();
    if (threadIdx.x < 8) {
        float s = 0.f;
        for (int w = 0; w < 8; w++) s += sh[w][threadIdx.x];
        oa[row * 8 + threadIdx.x] = s;
    }
}

// ---------------- out += OA @ b_o ----------------
__global__ void lora_o_add(const float* __restrict__ oa, const float* __restrict__ bo,
                           float* __restrict__ out) {
    int row = blockIdx.y;
    int c = blockIdx.x * 256 + threadIdx.x;
    float s = 0.f;
#pragma unroll
    for (int r = 0; r < 8; r++) s += oa[row * 8 + r] * bo[r * DIMX + c];
    out[(size_t)row * DIMX + c] += s;
}

// ---------------- launch ----------------
extern "C" void kernel_launch(void* const* d_in, const int* in_sizes, int n_in,
                              void* d_out, int out_size) {
    const float* x          = (const float*)d_in[0];
    const float* gamma      = (const float*)d_in[1];
    const float* w_fused    = (const float*)d_in[2];
    const float* w_attn_out = (const float*)d_in[3];
    const float* w_ff_out   = (const float*)d_in[4];
    const float* a_q        = (const float*)d_in[5];
    const float* b_q        = (const float*)d_in[6];
    const float* a_k        = (const float*)d_in[7];
    const float* b_k        = (const float*)d_in[8];
    const float* a_v        = (const float*)d_in[9];
    const float* b_v        = (const float*)d_in[10];
    const float* a_o        = (const float*)d_in[11];
    const float* b_o        = (const float*)d_in[12];
    float* out = (float*)d_out;

    float *XN, *WF, *F, *XA, *Q, *K, *V, *OATTN, *WAO, *H, *WFF, *OA;
    cudaGetSymbolAddress((void**)&XN, g_XN);
    cudaGetSymbolAddress((void**)&WF, g_WF);
    cudaGetSymbolAddress((void**)&F, g_F);
    cudaGetSymbolAddress((void**)&XA, g_XA);
    cudaGetSymbolAddress((void**)&Q, g_Q);
    cudaGetSymbolAddress((void**)&K, g_K);
    cudaGetSymbolAddress((void**)&V, g_V);
    cudaGetSymbolAddress((void**)&OATTN, g_OATTN);
    cudaGetSymbolAddress((void**)&WAO, g_WAO);
    cudaGetSymbolAddress((void**)&H, g_H);
    cudaGetSymbolAddress((void**)&WFF, g_WFF);
    cudaGetSymbolAddress((void**)&OA, g_OA);

    cudaFuncSetAttribute(tf32_gemm, cudaFuncAttributeMaxDynamicSharedMemorySize, GSMEM);
    cudaFuncSetAttribute(attn_mma, cudaFuncAttributeMaxDynamicSharedMemorySize, ATTN_SMEM);

    round_pad_perm<<<dim3((FPAD / 4 + 255) / 256, DIMX), 256>>>(w_fused, WF);
    round_pad<<<dim3((DIMX / 4 + 255) / 256, AINNER), 256>>>(w_attn_out, WAO, DIMX / 4, DIMX / 4);
    round_pad<<<dim3((DIMX / 4 + 255) / 256, FFINNER), 256>>>(w_ff_out, WFF, DIMX / 4, DIMX / 4);

    ln_kernel<<<ROWS, 256>>>(x, gamma, XN);
    tf32_gemm<<<dim3(ROWS / 128, FPAD / 128), 256, GSMEM>>>(XN, WF, F, H, FPAD, DIMX, 0, 1);
    lora_xa_kernel<<<ROWS, 256>>>(XN, a_q, a_k, a_v, XA);
    qkv_prep<<<ROWS, 256>>>(F, XA, b_q, b_k, b_v, Q, K, V);
    attn_mma<<<dim3(NSEQ / 64, HEADS, BATCH), 128, ATTN_SMEM>>>(Q, K, V, OATTN);
    tf32_gemm<<<dim3(ROWS / 128, DIMX / 128), 256, GSMEM>>>(OATTN, WAO, out, nullptr, DIMX, AINNER, 0, 0);
    lora_oa_kernel<<<ROWS, 256>>>(OATTN, a_o, OA);
    tf32_gemm<<<dim3(ROWS / 128, DIMX / 128), 256, GSMEM>>>(H, WFF, out, nullptr, DIMX, FFINNER, 1, 0);
    lora_o_add<<<dim3(DIMX / 256, ROWS), 256>>>(OA, b_o, out);
}

// round 9
// speedup vs baseline: 1.9188x; 1.3772x over previous
#include <cuda_runtime.h>
#include <cuda_fp16.h>
#include <math.h>
#include <float.h>
#include <stdint.h>

// ---------------- problem constants ----------------
#define DIMX 2048
#define NSEQ 2048
#define BATCH 2
#define HEADS 16
#define DHEAD 64
#define ROWS (BATCH*NSEQ)          // 4096
#define AINNER 1024
#define FFINNER 8192
#define FUSEDC 17536               // 1024+64+64+2*8192
#define FPAD 17664                 // 138*128 (permuted width)
#define FQKV 1280                  // qkv cols (1152) padded to 128-multiple
#define I0 1024
#define I1 1088
#define I2 1152

// ---------------- scratch (device globals) --------
__device__ float g_XN[(size_t)ROWS*DIMX];
__device__ __align__(16) __half g_XN16[(size_t)ROWS*DIMX];
__device__ __align__(16) __half g_WF16[(size_t)FPAD*DIMX];     // [n][k] fp16
__device__ float g_F[(size_t)ROWS*FQKV];
__device__ float g_XA[ROWS*24];
__device__ float g_Q[(size_t)ROWS*AINNER];
__device__ float g_K[(size_t)ROWS*DHEAD];
__device__ float g_V[(size_t)ROWS*DHEAD];
__device__ float g_OATTN[(size_t)ROWS*AINNER];
__device__ __align__(16) __half g_OATTN16[(size_t)ROWS*AINNER];
__device__ __align__(16) __half g_WAO16[(size_t)DIMX*AINNER];  // [n=2048][k=1024]
__device__ __align__(16) __half g_H16[(size_t)ROWS*FFINNER];
__device__ __align__(16) __half g_WFF16[(size_t)DIMX*FFINNER]; // [n=2048][k=8192]
__device__ float g_OA[ROWS*8];

// ---------------- small helpers ----------------
__device__ __forceinline__ float tf32r(float x) {
    uint32_t u;
    asm("cvt.rna.tf32.f32 %0, %1;" : "=r"(u) : "f"(x));
    return __uint_as_float(u);
}
__device__ __forceinline__ uint32_t smem_u32(const void* p) {
    uint32_t a;
    asm("{ .reg .u64 t; cvta.to.shared.u64 t, %1; cvt.u32.u64 %0, t; }" : "=r"(a) : "l"(p));
    return a;
}
__device__ __forceinline__ void cp16(uint32_t saddr, const void* g) {
    asm volatile("cp.async.cg.shared.global [%0], [%1], 16;" :: "r"(saddr), "l"(g) : "memory");
}
__device__ __forceinline__ void mma_tf32(float* d, const uint32_t* a, const uint32_t* b) {
    asm volatile(
        "mma.sync.aligned.m16n8k8.row.col.f32.tf32.tf32.f32 "
        "{%0,%1,%2,%3}, {%4,%5,%6,%7}, {%8,%9}, {%0,%1,%2,%3};"
        : "+f"(d[0]), "+f"(d[1]), "+f"(d[2]), "+f"(d[3])
        : "r"(a[0]), "r"(a[1]), "r"(a[2]), "r"(a[3]), "r"(b[0]), "r"(b[1]));
}
__device__ __forceinline__ void mma_f16(float* d, const uint32_t* a, const uint32_t* b) {
    asm volatile(
        "mma.sync.aligned.m16n8k16.row.col.f32.f16.f16.f32 "
        "{%0,%1,%2,%3}, {%4,%5,%6,%7}, {%8,%9}, {%0,%1,%2,%3};"
        : "+f"(d[0]), "+f"(d[1]), "+f"(d[2]), "+f"(d[3])
        : "r"(a[0]), "r"(a[1]), "r"(a[2]), "r"(a[3]), "r"(b[0]), "r"(b[1]));
}

// ================= FP16 GEMM =================
// C[M,N] = A16[M,K] @ B16T[N,K]^T  (+= if accum).
// 128x128x16 CTA tile, 256 thr, 8 warps (4m x 2n), warp 32x64, 5-stage cp.async.
// smem rows: 12 words (24 halves, 16 data + pad) -> conflict-free fragment LDS.
#define HGS 5
#define HROW 12                 // words per 16-half row
#define HSTW (256*HROW)         // A(128 rows)+B(128 rows) = 3072 words/stage
#define HGSMEM (HGS*HSTW*4)     // 61440 bytes

__global__ __launch_bounds__(256, 2) void h_gemm(const __half* __restrict__ A,
                                                 const __half* __restrict__ Bt,
                                                 float* __restrict__ C,
                                                 float* __restrict__ F,
                                                 __half* __restrict__ H16,
                                                 int N, int K, int accum, int fused) {
    extern __shared__ float smemf[];
    uint32_t* sm32 = (uint32_t*)smemf;
    const int tid = threadIdx.x;
    const int wid = tid >> 5, lane = tid & 31;
    const int gq = lane >> 2, tg = lane & 3;
    const int wm = (wid & 3) * 32, wn = (wid >> 2) * 64;
    const int m0 = blockIdx.x * 128, n0 = blockIdx.y * 128;
    const __half* Ag = A + (size_t)m0 * K;
    const __half* Bg = Bt + (size_t)n0 * K;
    const uint32_t sb = smem_u32(smemf);

    const int lrow = tid >> 1, lpart = tid & 1;   // 128 rows x 2 halves-of-row
    const int NK = K >> 4;

    auto load_stage = [&](int kt, int s) {
        const uint32_t sa = sb + s * HSTW * 4;
        const uint32_t sB = sa + 128 * HROW * 4;
        const __half* ag = Ag + (size_t)lrow * K + kt * 16 + lpart * 8;
        const __half* bg = Bg + (size_t)lrow * K + kt * 16 + lpart * 8;
        uint32_t off = (lrow * HROW + lpart * 4) * 4;
        cp16(sa + off, ag);
        cp16(sB + off, bg);
    };

    float acc[2][8][4];
#pragma unroll
    for (int mt = 0; mt < 2; mt++)
#pragma unroll
        for (int nt = 0; nt < 8; nt++)
#pragma unroll
            for (int i = 0; i < 4; i++) acc[mt][nt][i] = 0.f;

#pragma unroll
    for (int p = 0; p < 4; p++) {
        load_stage(p, p);
        asm volatile("cp.async.commit_group;" ::: "memory");
    }

#pragma unroll 1
    for (int kt = 0; kt < NK; kt++) {
        asm volatile("cp.async.wait_group 3;" ::: "memory");
        __syncthreads();
        if (kt + 4 < NK) load_stage(kt + 4, (kt + 4) % HGS);
        asm volatile("cp.async.commit_group;" ::: "memory");

        const int s = kt % HGS;
        const uint32_t* As = sm32 + s * HSTW;
        const uint32_t* Bs = As + 128 * HROW;

        uint32_t a[2][4], b[8][2];
#pragma unroll
        for (int mt = 0; mt < 2; mt++) {
            int r = wm + mt * 16 + gq;
            a[mt][0] = As[r * HROW + tg];
            a[mt][1] = As[(r + 8) * HROW + tg];
            a[mt][2] = As[r * HROW + tg + 4];
            a[mt][3] = As[(r + 8) * HROW + tg + 4];
        }
#pragma unroll
        for (int nt = 0; nt < 8; nt++) {
            int n = wn + nt * 8 + gq;
            b[nt][0] = Bs[n * HROW + tg];
            b[nt][1] = Bs[n * HROW + tg + 4];
        }
#pragma unroll
        for (int mt = 0; mt < 2; mt++)
#pragma unroll
            for (int nt = 0; nt < 8; nt++)
                mma_f16(acc[mt][nt], a[mt], b[nt]);
    }

    // epilogue (C frag layout identical to tf32 path)
    const int rbase = m0 + wm + gq;
    const int cbase = n0 + wn + tg * 2;
    if (!fused || n0 < FQKV) {
        float* Cd = fused ? F : C;
        const int ldc = fused ? FQKV : N;
#pragma unroll
        for (int mt = 0; mt < 2; mt++) {
#pragma unroll
            for (int nt = 0; nt < 8; nt++) {
                int r = rbase + mt * 16;
                int cc = cbase + nt * 8;
                float2* p0 = (float2*)(Cd + (size_t)r * ldc + cc);
                float2* p1 = (float2*)(Cd + (size_t)(r + 8) * ldc + cc);
                float2 v0 = make_float2(acc[mt][nt][0], acc[mt][nt][1]);
                float2 v1 = make_float2(acc[mt][nt][2], acc[mt][nt][3]);
                if (accum) {
                    float2 o0 = *p0, o1 = *p1;
                    v0.x += o0.x; v0.y += o0.y; v1.x += o1.x; v1.y += o1.y;
                }
                *p0 = v0; *p1 = v1;
            }
        }
    } else {
        // ff region: (x, gate) pairs -> H16 = half(x * silu(gate))
#pragma unroll
        for (int mt = 0; mt < 2; mt++) {
#pragma unroll
            for (int nt = 0; nt < 8; nt++) {
                int r = rbase + mt * 16;
                int hc = (cbase + nt * 8 - FQKV) >> 1;
                float x0 = acc[mt][nt][0], gg0 = acc[mt][nt][1];
                float x1 = acc[mt][nt][2], gg1 = acc[mt][nt][3];
                H16[(size_t)r * FFINNER + hc]       = __float2half(x0 * gg0 / (1.f + __expf(-gg0)));
                H16[(size_t)(r + 8) * FFINNER + hc] = __float2half(x1 * gg1 / (1.f + __expf(-gg1)));
            }
        }
    }
}

// ---------------- weight transpose + fp16 convert ----------------
// in fp32 [Kd][Nd] -> out fp16 [Nd][Kd]
__global__ void w_t16(const float* __restrict__ in, __half* __restrict__ out,
                      int Kd, int Nd) {
    __shared__ float t[32][33];
    int k0 = blockIdx.y * 32, n0 = blockIdx.x * 32;
    int tx = threadIdx.x, ty = threadIdx.y;
#pragma unroll
    for (int i = 0; i < 4; i++)
        t[ty + 8 * i][tx] = in[(size_t)(k0 + ty + 8 * i) * Nd + n0 + tx];
    __syncthreads();
#pragma unroll
    for (int i = 0; i < 4; i++)
        out[(size_t)(n0 + ty + 8 * i) * Kd + k0 + tx] = __float2half(t[tx][ty + 8 * i]);
}

// fused weight: transpose + permute + fp16. out [FPAD][DIMX].
__global__ void w_t16_perm(const float* __restrict__ in, __half* __restrict__ out) {
    __shared__ float t[32][33];
    int k0 = blockIdx.y * 32, n0 = blockIdx.x * 32;
    int tx = threadIdx.x, ty = threadIdx.y;
#pragma unroll
    for (int i = 0; i < 4; i++) {
        int k = k0 + ty + 8 * i;
        int j = n0 + tx;
        float val;
        if (j < I2) val = in[(size_t)k * FUSEDC + j];
        else if (j < FQKV) val = 0.f;
        else {
            int p = j - FQKV;
            val = in[(size_t)k * FUSEDC + I2 + (p >> 1) + (p & 1) * FFINNER];
        }
        t[ty + 8 * i][tx] = val;
    }
    __syncthreads();
#pragma unroll
    for (int i = 0; i < 4; i++)
        out[(size_t)(n0 + ty + 8 * i) * DIMX + k0 + tx] = __float2half(t[tx][ty + 8 * i]);
}

// ---------------- layernorm (fp32 + fp16 out) ----------------
__global__ void ln_kernel(const float* __restrict__ x, const float* __restrict__ gamma,
                          float* __restrict__ xn, __half* __restrict__ xn16) {
    int row = blockIdx.x;
    const float* xr = x + (size_t)row * DIMX;
    float s = 0.f, s2 = 0.f;
    for (int i = threadIdx.x; i < DIMX; i += 256) { float v = xr[i]; s += v; s2 += v * v; }
    for (int o = 16; o > 0; o >>= 1) {
        s  += __shfl_xor_sync(0xffffffff, s,  o);
        s2 += __shfl_xor_sync(0xffffffff, s2, o);
    }
    __shared__ float sh[16];
    int wid = threadIdx.x >> 5, lane = threadIdx.x & 31;
    if (lane == 0) { sh[wid] = s; sh[8 + wid] = s2; }
    __syncthreads();
    if (threadIdx.x == 0) {
        float S = 0.f, S2 = 0.f;
        for (int w = 0; w < 8; w++) { S += sh[w]; S2 += sh[8 + w]; }
        sh[0] = S; sh[8] = S2;
    }
    __syncthreads();
    float mu = sh[0] * (1.f / DIMX);
    float var = sh[8] * (1.f / DIMX) - mu * mu;
    float inv = rsqrtf(var + 1e-5f);
    float* o = xn + (size_t)row * DIMX;
    __half* o16 = xn16 + (size_t)row * DIMX;
    for (int i = threadIdx.x; i < DIMX; i += 256) {
        float v = (xr[i] - mu) * inv * gamma[i];
        o[i] = v;
        o16[i] = __float2half(v);
    }
}

// ---------------- LoRA first stage ----------------
__global__ void lora_xa_kernel(const float* __restrict__ xn,
                               const float* __restrict__ aq,
                               const float* __restrict__ ak,
                               const float* __restrict__ av,
                               float* __restrict__ xa) {
    int row = blockIdx.x;
    const float* xr = xn + (size_t)row * DIMX;
    float acc[24];
#pragma unroll
    for (int m = 0; m < 24; m++) acc[m] = 0.f;
    for (int i = threadIdx.x; i < DIMX; i += 256) {
        float v = xr[i];
#pragma unroll
        for (int r = 0; r < 8; r++) {
            acc[r]      += v * aq[i * 8 + r];
            acc[8 + r]  += v * ak[i * 8 + r];
            acc[16 + r] += v * av[i * 8 + r];
        }
    }
    __shared__ float sh[8][24];
    int wid = threadIdx.x >> 5, lane = threadIdx.x & 31;
#pragma unroll
    for (int m = 0; m < 24; m++)
        for (int o = 16; o > 0; o >>= 1)
            acc[m] += __shfl_xor_sync(0xffffffff, acc[m], o);
    if (lane == 0)
#pragma unroll
        for (int m = 0; m < 24; m++) sh[wid][m] = acc[m];
    __syncthreads();
    if (threadIdx.x < 24) {
        float s = 0.f;
        for (int w = 0; w < 8; w++) s += sh[w][threadIdx.x];
        xa[row * 24 + threadIdx.x] = s;
    }
}

// ---------------- qkv prep (F row stride = FQKV) ----------------
__global__ void qkv_prep(const float* __restrict__ F, const float* __restrict__ XA,
                         const float* __restrict__ bq, const float* __restrict__ bk,
                         const float* __restrict__ bv,
                         float* __restrict__ Q, float* __restrict__ Kv, float* __restrict__ V) {
    int row = blockIdx.x;
    int n = row % NSEQ;
    __shared__ float qs[AINNER];
    __shared__ float ks[DHEAD];
    const float* Fr = F + (size_t)row * FQKV;
    const float* xa = XA + row * 24;
    float lq[8], lk[8], lv[8];
#pragma unroll
    for (int r = 0; r < 8; r++) { lq[r] = xa[r]; lk[r] = xa[8 + r]; lv[r] = xa[16 + r]; }

    for (int c = threadIdx.x; c < AINNER; c += 256) {
        float v = Fr[c];
#pragma unroll
        for (int r = 0; r < 8; r++) v += lq[r] * bq[r * AINNER + c];
        qs[c] = v;
    }
    if (threadIdx.x < DHEAD) {
        int c = threadIdx.x;
        float v = Fr[I0 + c];
#pragma unroll
        for (int r = 0; r < 8; r++) v += lk[r] * bk[r * DHEAD + c];
        ks[c] = v;
        float vv = Fr[I1 + c];
#pragma unroll
        for (int r = 0; r < 8; r++) vv += lv[r] * bv[r * DHEAD + c];
        V[(size_t)row * DHEAD + c] = vv;
    }
    __syncthreads();

    const float ln10k_inv32 = 9.2103403719761836f / 32.f;
    const float scale = 0.125f;
    for (int c = threadIdx.x; c < AINNER; c += 256) {
        int h = c >> 6, d = c & 63;
        int fi = d & 31;
        float freq = (float)n * __expf(-(float)fi * ln10k_inv32);
        float cs = cosf(freq), sn = sinf(freq);
        float me = qs[c];
        float partner = (d < 32) ? -qs[h * 64 + d + 32] : qs[h * 64 + d - 32];
        Q[(size_t)row * AINNER + c] = (me * cs + partner * sn) * scale;
    }
    if (threadIdx.x < DHEAD) {
        int d = threadIdx.x;
        int fi = d & 31;
        float freq = (float)n * __expf(-(float)fi * ln10k_inv32);
        float cs = cosf(freq), sn = sinf(freq);
        float me = ks[d];
        float partner = (d < 32) ? -ks[d + 32] : ks[d - 32];
        Kv[(size_t)row * DHEAD + d] = me * cs + partner * sn;
    }
}

// ================= MMA flash attention (unchanged from R7 winner) ========
#define ATTN_SMEM ((64*68*3 + 64*72)*4)

__global__ __launch_bounds__(128) void attn_mma(const float* __restrict__ Qg,
                                                const float* __restrict__ Kg,
                                                const float* __restrict__ Vg,
                                                float* __restrict__ O,
                                                __half* __restrict__ O16) {
    extern __shared__ float sm[];
    float* Qs = sm;
    float* Ks = sm + 64 * 68;
    float* Kd = sm + 2 * 64 * 68;
    float* Vs = sm + 3 * 64 * 68;

    const int tid = threadIdx.x, wid = tid >> 5, lane = tid & 31;
    const int gq = lane >> 2, tq = lane & 3;
    const int qt = gridDim.x - 1 - blockIdx.x;
    const int h = blockIdx.y, b = blockIdx.z;
    const int q0 = qt * 64;

    for (int i = tid; i < 1024; i += 128) {
        int r = i >> 4, d4 = (i & 15) * 4;
        *(float4*)(Qs + r * 68 + d4) =
            *(const float4*)(Qg + (size_t)(b * NSEQ + q0 + r) * AINNER + h * 64 + d4);
    }
    __syncthreads();

    uint32_t qr[8][4], qd[8][4];
#pragma unroll
    for (int k = 0; k < 8; k++) {
#pragma unroll
        for (int e = 0; e < 4; e++) {
            int rr = wid * 16 + gq + (e & 1) * 8;
            int cc = k * 8 + tq + (e >> 1) * 4;
            float v = Qs[rr * 68 + cc];
            float hi = tf32r(v);
            qr[k][e] = __float_as_uint(hi);
            qd[k][e] = __float_as_uint(tf32r(v - hi));
        }
    }

    float o[8][4];
#pragma unroll
    for (int nt = 0; nt < 8; nt++)
#pragma unroll
        for (int e = 0; e < 4; e++) o[nt][e] = 0.f;
    float m0 = -FLT_MAX, m1 = -FLT_MAX, l0 = 0.f, l1 = 0.f;

    const float* Kb = Kg + (size_t)b * NSEQ * DHEAD;
    const float* Vb = Vg + (size_t)b * NSEQ * DHEAD;

    for (int j0 = 0; j0 <= q0; j0 += 64) {
        __syncthreads();
        for (int i = tid; i < 1024; i += 128) {
            int r = i >> 4, d4 = (i & 15) * 4;
            float4 kv = *(const float4*)(Kb + (size_t)(j0 + r) * DHEAD + d4);
            float h0 = tf32r(kv.x), h1 = tf32r(kv.y), h2 = tf32r(kv.z), h3 = tf32r(kv.w);
            *(float4*)(Ks + r * 68 + d4) = make_float4(h0, h1, h2, h3);
            *(float4*)(Kd + r * 68 + d4) =
                make_float4(tf32r(kv.x - h0), tf32r(kv.y - h1), tf32r(kv.z - h2), tf32r(kv.w - h3));
            float4 vv = *(const float4*)(Vb + (size_t)(j0 + r) * DHEAD + d4);
            *(float4*)(Vs + r * 72 + d4) =
                make_float4(tf32r(vv.x), tf32r(vv.y), tf32r(vv.z), tf32r(vv.w));
        }
        __syncthreads();

        float s[8][4];
#pragma unroll
        for (int nt = 0; nt < 8; nt++) {
            s[nt][0] = s[nt][1] = s[nt][2] = s[nt][3] = 0.f;
            const float* krow = Ks + (nt * 8 + gq) * 68;
            const float* drow = Kd + (nt * 8 + gq) * 68;
#pragma unroll
            for (int k = 0; k < 8; k++) {
                uint32_t br[2] = { __float_as_uint(krow[k * 8 + tq]),
                                   __float_as_uint(krow[k * 8 + tq + 4]) };
                uint32_t bd[2] = { __float_as_uint(drow[k * 8 + tq]),
                                   __float_as_uint(drow[k * 8 + tq + 4]) };
                mma_tf32(s[nt], qr[k], br);
                mma_tf32(s[nt], qd[k], br);
                mma_tf32(s[nt], qr[k], bd);
            }
        }

        if (j0 == q0) {
            int r0 = wid * 16 + gq, r1 = r0 + 8;
#pragma unroll
            for (int nt = 0; nt < 8; nt++) {
                int jc = nt * 8 + 2 * tq;
                if (jc     > r0) s[nt][0] = -1e30f;
                if (jc + 1 > r0) s[nt][1] = -1e30f;
                if (jc     > r1) s[nt][2] = -1e30f;
                if (jc + 1 > r1) s[nt][3] = -1e30f;
            }
        }

        float rx0 = -1e30f, rx1 = -1e30f;
#pragma unroll
        for (int nt = 0; nt < 8; nt++) {
            rx0 = fmaxf(rx0, fmaxf(s[nt][0], s[nt][1]));
            rx1 = fmaxf(rx1, fmaxf(s[nt][2], s[nt][3]));
        }
        rx0 = fmaxf(rx0, __shfl_xor_sync(0xffffffff, rx0, 1));
        rx0 = fmaxf(rx0, __shfl_xor_sync(0xffffffff, rx0, 2));
        rx1 = fmaxf(rx1, __shfl_xor_sync(0xffffffff, rx1, 1));
        rx1 = fmaxf(rx1, __shfl_xor_sync(0xffffffff, rx1, 2));
        float mn0 = fmaxf(m0, rx0), mn1 = fmaxf(m1, rx1);
        float c0 = __expf(m0 - mn0), c1 = __expf(m1 - mn1);
        float ps0 = 0.f, ps1 = 0.f;
#pragma unroll
        for (int nt = 0; nt < 8; nt++) {
            s[nt][0] = __expf(s[nt][0] - mn0);
            s[nt][1] = __expf(s[nt][1] - mn0);
            s[nt][2] = __expf(s[nt][2] - mn1);
            s[nt][3] = __expf(s[nt][3] - mn1);
            ps0 += s[nt][0] + s[nt][1];
            ps1 += s[nt][2] + s[nt][3];
        }
        ps0 += __shfl_xor_sync(0xffffffff, ps0, 1);
        ps0 += __shfl_xor_sync(0xffffffff, ps0, 2);
        ps1 += __shfl_xor_sync(0xffffffff, ps1, 1);
        ps1 += __shfl_xor_sync(0xffffffff, ps1, 2);
        l0 = l0 * c0 + ps0;
        l1 = l1 * c1 + ps1;
#pragma unroll
        for (int nt = 0; nt < 8; nt++) {
            o[nt][0] *= c0; o[nt][1] *= c0;
            o[nt][2] *= c1; o[nt][3] *= c1;
        }
        m0 = mn0; m1 = mn1;

        uint32_t ap[8][4];
#pragma unroll
        for (int ks = 0; ks < 8; ks++) {
            int base = lane & ~3;
            int s0 = base + (tq >> 1), s1 = s0 + 2;
            float v00 = __shfl_sync(0xffffffff, s[ks][0], s0);
            float v01 = __shfl_sync(0xffffffff, s[ks][1], s0);
            float v20 = __shfl_sync(0xffffffff, s[ks][2], s0);
            float v21 = __shfl_sync(0xffffffff, s[ks][3], s0);
            float w00 = __shfl_sync(0xffffffff, s[ks][0], s1);
            float w01 = __shfl_sync(0xffffffff, s[ks][1], s1);
            float w20 = __shfl_sync(0xffffffff, s[ks][2], s1);
            float w21 = __shfl_sync(0xffffffff, s[ks][3], s1);
            bool oq = tq & 1;
            ap[ks][0] = __float_as_uint(tf32r(oq ? v01 : v00));
            ap[ks][1] = __float_as_uint(tf32r(oq ? v21 : v20));
            ap[ks][2] = __float_as_uint(tf32r(oq ? w01 : w00));
            ap[ks][3] = __float_as_uint(tf32r(oq ? w21 : w20));
        }

#pragma unroll
        for (int nt = 0; nt < 8; nt++) {
#pragma unroll
            for (int ks = 0; ks < 8; ks++) {
                int vr = ks * 8 + tq;
                int vc = nt * 8 + gq;
                uint32_t bv[2] = { __float_as_uint(Vs[vr * 72 + vc]),
                                   __float_as_uint(Vs[(vr + 4) * 72 + vc]) };
                mma_tf32(o[nt], ap[ks], bv);
            }
        }
    }

    float il0 = 1.f / l0, il1 = 1.f / l1;
    int rg0 = b * NSEQ + q0 + wid * 16 + gq;
#pragma unroll
    for (int nt = 0; nt < 8; nt++) {
        int col = h * 64 + nt * 8 + 2 * tq;
        float a0 = o[nt][0] * il0, a1 = o[nt][1] * il0;
        float a2 = o[nt][2] * il1, a3 = o[nt][3] * il1;
        *(float2*)(O + (size_t)rg0 * AINNER + col) = make_float2(a0, a1);
        *(float2*)(O + (size_t)(rg0 + 8) * AINNER + col) = make_float2(a2, a3);
        *(__half2*)(O16 + (size_t)rg0 * AINNER + col) = __floats2half2_rn(a0, a1);
        *(__half2*)(O16 + (size_t)(rg0 + 8) * AINNER + col) = __floats2half2_rn(a2, a3);
    }
}

// ---------------- OA[row,8] = OATTN_row @ a_o ----------------
__global__ void lora_oa_kernel(const float* __restrict__ oattn,
                               const float* __restrict__ ao,
                               float* __restrict__ oa) {
    int row = blockIdx.x;
    const float* xr = oattn + (size_t)row * AINNER;
    float acc[8];
#pragma unroll
    for (int r = 0; r < 8; r++) acc[r] = 0.f;
    for (int i = threadIdx.x; i < AINNER; i += 256) {
        float v = xr[i];
#pragma unroll
        for (int r = 0; r < 8; r++) acc[r] += v * ao[i * 8 + r];
    }
    __shared__ float sh[8][8];
    int wid = threadIdx.x >> 5, lane = threadIdx.x & 31;
#pragma unroll
    for (int r = 0; r < 8; r++)
        for (int o = 16; o > 0; o >>= 1)
            acc[r] += __shfl_xor_sync(0xffffffff, acc[r], o);
    if (lane == 0)
#pragma unroll
        for (int r = 0; r < 8; r++) sh[wid][r] = acc[r];
    __syncthreads();
    if (threadIdx.x < 8) {
        float s = 0.f;
        for (int w = 0; w < 8; w++) s += sh[w][threadIdx.x];
        oa[row * 8 + threadIdx.x] = s;
    }
}

// ---------------- out += OA @ b_o ----------------
__global__ void lora_o_add(const float* __restrict__ oa, const float* __restrict__ bo,
                           float* __restrict__ out) {
    int row = blockIdx.y;
    int c = blockIdx.x * 256 + threadIdx.x;
    float s = 0.f;
#pragma unroll
    for (int r = 0; r < 8; r++) s += oa[row * 8 + r] * bo[r * DIMX + c];
    out[(size_t)row * DIMX + c] += s;
}

// ---------------- launch ----------------
extern "C" void kernel_launch(void* const* d_in, const int* in_sizes, int n_in,
                              void* d_out, int out_size) {
    const float* x          = (const float*)d_in[0];
    const float* gamma      = (const float*)d_in[1];
    const float* w_fused    = (const float*)d_in[2];
    const float* w_attn_out = (const float*)d_in[3];
    const float* w_ff_out   = (const float*)d_in[4];
    const float* a_q        = (const float*)d_in[5];
    const float* b_q        = (const float*)d_in[6];
    const float* a_k        = (const float*)d_in[7];
    const float* b_k        = (const float*)d_in[8];
    const float* a_v        = (const float*)d_in[9];
    const float* b_v        = (const float*)d_in[10];
    const float* a_o        = (const float*)d_in[11];
    const float* b_o        = (const float*)d_in[12];
    float* out = (float*)d_out;

    float *XN, *F, *XA, *Q, *K, *V, *OATTN, *OA;
    __half *XN16, *WF16, *OATTN16, *WAO16, *H16, *WFF16;
    cudaGetSymbolAddress((void**)&XN, g_XN);
    cudaGetSymbolAddress((void**)&XN16, g_XN16);
    cudaGetSymbolAddress((void**)&WF16, g_WF16);
    cudaGetSymbolAddress((void**)&F, g_F);
    cudaGetSymbolAddress((void**)&XA, g_XA);
    cudaGetSymbolAddress((void**)&Q, g_Q);
    cudaGetSymbolAddress((void**)&K, g_K);
    cudaGetSymbolAddress((void**)&V, g_V);
    cudaGetSymbolAddress((void**)&OATTN, g_OATTN);
    cudaGetSymbolAddress((void**)&OATTN16, g_OATTN16);
    cudaGetSymbolAddress((void**)&WAO16, g_WAO16);
    cudaGetSymbolAddress((void**)&H16, g_H16);
    cudaGetSymbolAddress((void**)&WFF16, g_WFF16);
    cudaGetSymbolAddress((void**)&OA, g_OA);

    cudaFuncSetAttribute(h_gemm, cudaFuncAttributeMaxDynamicSharedMemorySize, HGSMEM);
    cudaFuncSetAttribute(attn_mma, cudaFuncAttributeMaxDynamicSharedMemorySize, ATTN_SMEM);

    // weight transpose + fp16 convert
    w_t16_perm<<<dim3(FPAD / 32, DIMX / 32), dim3(32, 8)>>>(w_fused, WF16);
    w_t16<<<dim3(DIMX / 32, AINNER / 32), dim3(32, 8)>>>(w_attn_out, WAO16, AINNER, DIMX);
    w_t16<<<dim3(DIMX / 32, FFINNER / 32), dim3(32, 8)>>>(w_ff_out, WFF16, FFINNER, DIMX);

    ln_kernel<<<ROWS, 256>>>(x, gamma, XN, XN16);
    h_gemm<<<dim3(ROWS / 128, FPAD / 128), 256, HGSMEM>>>(XN16, WF16, nullptr, F, H16, FPAD, DIMX, 0, 1);
    lora_xa_kernel<<<ROWS, 256>>>(XN, a_q, a_k, a_v, XA);
    qkv_prep<<<ROWS, 256>>>(F, XA, b_q, b_k, b_v, Q, K, V);
    attn_mma<<<dim3(NSEQ / 64, HEADS, BATCH), 128, ATTN_SMEM>>>(Q, K, V, OATTN, OATTN16);
    h_gemm<<<dim3(ROWS / 128, DIMX / 128), 256, HGSMEM>>>(OATTN16, WAO16, out, nullptr, nullptr, DIMX, AINNER, 0, 0);
    lora_oa_kernel<<<ROWS, 256>>>(OATTN, a_o, OA);
    h_gemm<<<dim3(ROWS / 128, DIMX / 128), 256, HGSMEM>>>(H16, WFF16, out, nullptr, nullptr, DIMX, FFINNER, 1, 0);
    lora_o_add<<<dim3(DIMX / 256, ROWS), 256>>>(OA, b_o, out);
}

// round 10
// speedup vs baseline: 1.9574x; 1.0201x over previous
#include <cuda_runtime.h>
#include <cuda_fp16.h>
#include <math.h>
#include <float.h>
#include <stdint.h>

// ---------------- problem constants ----------------
#define DIMX 2048
#define NSEQ 2048
#define BATCH 2
#define HEADS 16
#define DHEAD 64
#define ROWS (BATCH*NSEQ)          // 4096
#define AINNER 1024
#define FFINNER 8192
#define FUSEDC 17536
#define FPAD 17664                 // 138*128 (permuted width)
#define FQKV 1280
#define I0 1024
#define I1 1088
#define I2 1152
#define KC 9216                    // combined K: 1024 (attn) + 8192 (ff)
#define KOFF 1024

// ---------------- scratch (device globals) --------
__device__ float g_XN[(size_t)ROWS*DIMX];
__device__ __align__(16) __half g_XN16[(size_t)ROWS*DIMX];
__device__ __align__(16) __half g_WF16[(size_t)FPAD*DIMX];     // [n][k]
__device__ float g_F[(size_t)ROWS*FQKV];
__device__ float g_XA[ROWS*24];
__device__ float g_Q[(size_t)ROWS*AINNER];
__device__ float g_K[(size_t)ROWS*DHEAD];
__device__ float g_V[(size_t)ROWS*DHEAD];
__device__ float g_OATTN[(size_t)ROWS*AINNER];                 // fp32 (lora_oa)
__device__ __align__(16) __half g_AC16[(size_t)ROWS*KC];       // [attn | ff] fp16
__device__ __align__(16) __half g_WC16[(size_t)DIMX*KC];       // [n][kc]
__device__ float g_OA[ROWS*8];

// ---------------- small helpers ----------------
__device__ __forceinline__ float tf32r(float x) {
    uint32_t u;
    asm("cvt.rna.tf32.f32 %0, %1;" : "=r"(u) : "f"(x));
    return __uint_as_float(u);
}
__device__ __forceinline__ uint32_t smem_u32(const void* p) {
    uint32_t a;
    asm("{ .reg .u64 t; cvta.to.shared.u64 t, %1; cvt.u32.u64 %0, t; }" : "=r"(a) : "l"(p));
    return a;
}
__device__ __forceinline__ void cp16(uint32_t saddr, const void* g) {
    asm volatile("cp.async.cg.shared.global [%0], [%1], 16;" :: "r"(saddr), "l"(g) : "memory");
}
__device__ __forceinline__ void mma_tf32(float* d, const uint32_t* a, const uint32_t* b) {
    asm volatile(
        "mma.sync.aligned.m16n8k8.row.col.f32.tf32.tf32.f32 "
        "{%0,%1,%2,%3}, {%4,%5,%6,%7}, {%8,%9}, {%0,%1,%2,%3};"
        : "+f"(d[0]), "+f"(d[1]), "+f"(d[2]), "+f"(d[3])
        : "r"(a[0]), "r"(a[1]), "r"(a[2]), "r"(a[3]), "r"(b[0]), "r"(b[1]));
}
__device__ __forceinline__ void mma_f16(float* d, const uint32_t* a, const uint32_t* b) {
    asm volatile(
        "mma.sync.aligned.m16n8k16.row.col.f32.f16.f16.f32 "
        "{%0,%1,%2,%3}, {%4,%5,%6,%7}, {%8,%9}, {%0,%1,%2,%3};"
        : "+f"(d[0]), "+f"(d[1]), "+f"(d[2]), "+f"(d[3])
        : "r"(a[0]), "r"(a[1]), "r"(a[2]), "r"(a[3]), "r"(b[0]), "r"(b[1]));
}

// ================= FP16 GEMM, 32-deep K stages =================
// C[M,N] = A16[M,K] @ B16T[N,K]^T. 128x128x32 stage, 256 thr, 8 warps,
// warp 32x64, 4-stage cp.async (lookahead 3).
#define HGS 4
#define HROW 20                 // words per 32-half row (16 data + 4 pad)
#define HSTW (256*HROW)         // 5120 words/stage
#define HGSMEM (HGS*HSTW*4)     // 81920 bytes

__global__ __launch_bounds__(256, 2) void h_gemm(const __half* __restrict__ A,
                                                 const __half* __restrict__ Bt,
                                                 float* __restrict__ C,
                                                 float* __restrict__ F,
                                                 __half* __restrict__ Hc,
                                                 int N, int K, int fused) {
    extern __shared__ float smemf[];
    uint32_t* sm32 = (uint32_t*)smemf;
    const int tid = threadIdx.x;
    const int wid = tid >> 5, lane = tid & 31;
    const int gq = lane >> 2, tg = lane & 3;
    const int wm = (wid & 3) * 32, wn = (wid >> 2) * 64;
    const int m0 = blockIdx.x * 128, n0 = blockIdx.y * 128;
    const __half* Ag = A + (size_t)m0 * K;
    const __half* Bg = Bt + (size_t)n0 * K;
    const uint32_t sb = smem_u32(smemf);

    const int lrow = tid >> 1;            // 0..127
    const int lp = (tid & 1) * 2;         // part base {0,2}
    const int NK = K >> 5;

    auto load_stage = [&](int kt, int s) {
        const uint32_t sa = sb + s * HSTW * 4;
        const uint32_t sB = sa + 128 * HROW * 4;
        const __half* ag = Ag + (size_t)lrow * K + kt * 32;
        const __half* bg = Bg + (size_t)lrow * K + kt * 32;
#pragma unroll
        for (int i = 0; i < 2; i++) {
            int p = lp + i;
            uint32_t off = (lrow * HROW + p * 4) * 4;
            cp16(sa + off, ag + p * 8);
            cp16(sB + off, bg + p * 8);
        }
    };

    float acc[2][8][4];
#pragma unroll
    for (int mt = 0; mt < 2; mt++)
#pragma unroll
        for (int nt = 0; nt < 8; nt++)
#pragma unroll
            for (int i = 0; i < 4; i++) acc[mt][nt][i] = 0.f;

#pragma unroll
    for (int p = 0; p < 3; p++) {
        load_stage(p, p);
        asm volatile("cp.async.commit_group;" ::: "memory");
    }

#pragma unroll 1
    for (int kt = 0; kt < NK; kt++) {
        asm volatile("cp.async.wait_group 2;" ::: "memory");
        __syncthreads();
        if (kt + 3 < NK) load_stage(kt + 3, (kt + 3) & 3);
        asm volatile("cp.async.commit_group;" ::: "memory");

        const int s = kt & 3;
        const uint32_t* As = sm32 + s * HSTW;
        const uint32_t* Bs = As + 128 * HROW;

#pragma unroll
        for (int ks = 0; ks < 2; ks++) {
            uint32_t a[2][4], b[8][2];
#pragma unroll
            for (int mt = 0; mt < 2; mt++) {
                int r = wm + mt * 16 + gq;
                a[mt][0] = As[r * HROW + ks * 8 + tg];
                a[mt][1] = As[(r + 8) * HROW + ks * 8 + tg];
                a[mt][2] = As[r * HROW + ks * 8 + tg + 4];
                a[mt][3] = As[(r + 8) * HROW + ks * 8 + tg + 4];
            }
#pragma unroll
            for (int nt = 0; nt < 8; nt++) {
                int n = wn + nt * 8 + gq;
                b[nt][0] = Bs[n * HROW + ks * 8 + tg];
                b[nt][1] = Bs[n * HROW + ks * 8 + tg + 4];
            }
#pragma unroll
            for (int mt = 0; mt < 2; mt++)
#pragma unroll
                for (int nt = 0; nt < 8; nt++)
                    mma_f16(acc[mt][nt], a[mt], b[nt]);
        }
    }

    // epilogue
    const int rbase = m0 + wm + gq;
    const int cbase = n0 + wn + tg * 2;
    if (!fused) {
#pragma unroll
        for (int mt = 0; mt < 2; mt++) {
#pragma unroll
            for (int nt = 0; nt < 8; nt++) {
                int r = rbase + mt * 16;
                int cc = cbase + nt * 8;
                *(float2*)(C + (size_t)r * N + cc) =
                    make_float2(acc[mt][nt][0], acc[mt][nt][1]);
                *(float2*)(C + (size_t)(r + 8) * N + cc) =
                    make_float2(acc[mt][nt][2], acc[mt][nt][3]);
            }
        }
    } else if (n0 < FQKV) {
#pragma unroll
        for (int mt = 0; mt < 2; mt++) {
#pragma unroll
            for (int nt = 0; nt < 8; nt++) {
                int r = rbase + mt * 16;
                int cc = cbase + nt * 8;
                *(float2*)(F + (size_t)r * FQKV + cc) =
                    make_float2(acc[mt][nt][0], acc[mt][nt][1]);
                *(float2*)(F + (size_t)(r + 8) * FQKV + cc) =
                    make_float2(acc[mt][nt][2], acc[mt][nt][3]);
            }
        }
    } else {
        // ff region: (x, gate) pairs -> AC16[:, KOFF + hc] = half(x * silu(gate))
#pragma unroll
        for (int mt = 0; mt < 2; mt++) {
#pragma unroll
            for (int nt = 0; nt < 8; nt++) {
                int r = rbase + mt * 16;
                int hc = (cbase + nt * 8 - FQKV) >> 1;
                float x0 = acc[mt][nt][0], gg0 = acc[mt][nt][1];
                float x1 = acc[mt][nt][2], gg1 = acc[mt][nt][3];
                Hc[(size_t)r * KC + KOFF + hc]       = __float2half(x0 * gg0 / (1.f + __expf(-gg0)));
                Hc[(size_t)(r + 8) * KC + KOFF + hc] = __float2half(x1 * gg1 / (1.f + __expf(-gg1)));
            }
        }
    }
}

// ---------------- weight transpose + fp16 (strided out) ----------------
__global__ void w_t16s(const float* __restrict__ in, __half* __restrict__ out,
                       int Kd, int Nd, int ostride, int ooff) {
    __shared__ float t[32][33];
    int k0 = blockIdx.y * 32, n0 = blockIdx.x * 32;
    int tx = threadIdx.x, ty = threadIdx.y;
#pragma unroll
    for (int i = 0; i < 4; i++)
        t[ty + 8 * i][tx] = in[(size_t)(k0 + ty + 8 * i) * Nd + n0 + tx];
    __syncthreads();
#pragma unroll
    for (int i = 0; i < 4; i++)
        out[(size_t)(n0 + ty + 8 * i) * ostride + ooff + k0 + tx] = __float2half(t[tx][ty + 8 * i]);
}

// fused weight: transpose + permute + fp16. out [FPAD][DIMX].
__global__ void w_t16_perm(const float* __restrict__ in, __half* __restrict__ out) {
    __shared__ float t[32][33];
    int k0 = blockIdx.y * 32, n0 = blockIdx.x * 32;
    int tx = threadIdx.x, ty = threadIdx.y;
#pragma unroll
    for (int i = 0; i < 4; i++) {
        int k = k0 + ty + 8 * i;
        int j = n0 + tx;
        float val;
        if (j < I2) val = in[(size_t)k * FUSEDC + j];
        else if (j < FQKV) val = 0.f;
        else {
            int p = j - FQKV;
            val = in[(size_t)k * FUSEDC + I2 + (p >> 1) + (p & 1) * FFINNER];
        }
        t[ty + 8 * i][tx] = val;
    }
    __syncthreads();
#pragma unroll
    for (int i = 0; i < 4; i++)
        out[(size_t)(n0 + ty + 8 * i) * DIMX + k0 + tx] = __float2half(t[tx][ty + 8 * i]);
}

// ---------------- layernorm ----------------
__global__ void ln_kernel(const float* __restrict__ x, const float* __restrict__ gamma,
                          float* __restrict__ xn, __half* __restrict__ xn16) {
    int row = blockIdx.x;
    const float* xr = x + (size_t)row * DIMX;
    float s = 0.f, s2 = 0.f;
    for (int i = threadIdx.x; i < DIMX; i += 256) { float v = xr[i]; s += v; s2 += v * v; }
    for (int o = 16; o > 0; o >>= 1) {
        s  += __shfl_xor_sync(0xffffffff, s,  o);
        s2 += __shfl_xor_sync(0xffffffff, s2, o);
    }
    __shared__ float sh[16];
    int wid = threadIdx.x >> 5, lane = threadIdx.x & 31;
    if (lane == 0) { sh[wid] = s; sh[8 + wid] = s2; }
    __syncthreads();
    if (threadIdx.x == 0) {
        float S = 0.f, S2 = 0.f;
        for (int w = 0; w < 8; w++) { S += sh[w]; S2 += sh[8 + w]; }
        sh[0] = S; sh[8] = S2;
    }
    __syncthreads();
    float mu = sh[0] * (1.f / DIMX);
    float var = sh[8] * (1.f / DIMX) - mu * mu;
    float inv = rsqrtf(var + 1e-5f);
    float* o = xn + (size_t)row * DIMX;
    __half* o16 = xn16 + (size_t)row * DIMX;
    for (int i = threadIdx.x; i < DIMX; i += 256) {
        float v = (xr[i] - mu) * inv * gamma[i];
        o[i] = v;
        o16[i] = __float2half(v);
    }
}

// ---------------- LoRA first stage ----------------
__global__ void lora_xa_kernel(const float* __restrict__ xn,
                               const float* __restrict__ aq,
                               const float* __restrict__ ak,
                               const float* __restrict__ av,
                               float* __restrict__ xa) {
    int row = blockIdx.x;
    const float* xr = xn + (size_t)row * DIMX;
    float acc[24];
#pragma unroll
    for (int m = 0; m < 24; m++) acc[m] = 0.f;
    for (int i = threadIdx.x; i < DIMX; i += 256) {
        float v = xr[i];
#pragma unroll
        for (int r = 0; r < 8; r++) {
            acc[r]      += v * aq[i * 8 + r];
            acc[8 + r]  += v * ak[i * 8 + r];
            acc[16 + r] += v * av[i * 8 + r];
        }
    }
    __shared__ float sh[8][24];
    int wid = threadIdx.x >> 5, lane = threadIdx.x & 31;
#pragma unroll
    for (int m = 0; m < 24; m++)
        for (int o = 16; o > 0; o >>= 1)
            acc[m] += __shfl_xor_sync(0xffffffff, acc[m], o);
    if (lane == 0)
#pragma unroll
        for (int m = 0; m < 24; m++) sh[wid][m] = acc[m];
    __syncthreads();
    if (threadIdx.x < 24) {
        float s = 0.f;
        for (int w = 0; w < 8; w++) s += sh[w][threadIdx.x];
        xa[row * 24 + threadIdx.x] = s;
    }
}

// ---------------- qkv prep ----------------
__global__ void qkv_prep(const float* __restrict__ F, const float* __restrict__ XA,
                         const float* __restrict__ bq, const float* __restrict__ bk,
                         const float* __restrict__ bv,
                         float* __restrict__ Q, float* __restrict__ Kv, float* __restrict__ V) {
    int row = blockIdx.x;
    int n = row % NSEQ;
    __shared__ float qs[AINNER];
    __shared__ float ks[DHEAD];
    const float* Fr = F + (size_t)row * FQKV;
    const float* xa = XA + row * 24;
    float lq[8], lk[8], lv[8];
#pragma unroll
    for (int r = 0; r < 8; r++) { lq[r] = xa[r]; lk[r] = xa[8 + r]; lv[r] = xa[16 + r]; }

    for (int c = threadIdx.x; c < AINNER; c += 256) {
        float v = Fr[c];
#pragma unroll
        for (int r = 0; r < 8; r++) v += lq[r] * bq[r * AINNER + c];
        qs[c] = v;
    }
    if (threadIdx.x < DHEAD) {
        int c = threadIdx.x;
        float v = Fr[I0 + c];
#pragma unroll
        for (int r = 0; r < 8; r++) v += lk[r] * bk[r * DHEAD + c];
        ks[c] = v;
        float vv = Fr[I1 + c];
#pragma unroll
        for (int r = 0; r < 8; r++) vv += lv[r] * bv[r * DHEAD + c];
        V[(size_t)row * DHEAD + c] = vv;
    }
    __syncthreads();

    const float ln10k_inv32 = 9.2103403719761836f / 32.f;
    const float scale = 0.125f;
    for (int c = threadIdx.x; c < AINNER; c += 256) {
        int h = c >> 6, d = c & 63;
        int fi = d & 31;
        float freq = (float)n * __expf(-(float)fi * ln10k_inv32);
        float cs = cosf(freq), sn = sinf(freq);
        float me = qs[c];
        float partner = (d < 32) ? -qs[h * 64 + d + 32] : qs[h * 64 + d - 32];
        Q[(size_t)row * AINNER + c] = (me * cs + partner * sn) * scale;
    }
    if (threadIdx.x < DHEAD) {
        int d = threadIdx.x;
        int fi = d & 31;
        float freq = (float)n * __expf(-(float)fi * ln10k_inv32);
        float cs = cosf(freq), sn = sinf(freq);
        float me = ks[d];
        float partner = (d < 32) ? -ks[d + 32] : ks[d - 32];
        Kv[(size_t)row * DHEAD + d] = me * cs + partner * sn;
    }
}

// ================= MMA flash attention =================
#define ATTN_SMEM ((64*68*3 + 64*72)*4)

__global__ __launch_bounds__(128) void attn_mma(const float* __restrict__ Qg,
                                                const float* __restrict__ Kg,
                                                const float* __restrict__ Vg,
                                                float* __restrict__ O,
                                                __half* __restrict__ O16) {
    extern __shared__ float sm[];
    float* Qs = sm;
    float* Ks = sm + 64 * 68;
    float* Kd = sm + 2 * 64 * 68;
    float* Vs = sm + 3 * 64 * 68;

    const int tid = threadIdx.x, wid = tid >> 5, lane = tid & 31;
    const int gq = lane >> 2, tq = lane & 3;
    const int qt = gridDim.x - 1 - blockIdx.x;
    const int h = blockIdx.y, b = blockIdx.z;
    const int q0 = qt * 64;

    for (int i = tid; i < 1024; i += 128) {
        int r = i >> 4, d4 = (i & 15) * 4;
        *(float4*)(Qs + r * 68 + d4) =
            *(const float4*)(Qg + (size_t)(b * NSEQ + q0 + r) * AINNER + h * 64 + d4);
    }
    __syncthreads();

    uint32_t qr[8][4], qd[8][4];
#pragma unroll
    for (int k = 0; k < 8; k++) {
#pragma unroll
        for (int e = 0; e < 4; e++) {
            int rr = wid * 16 + gq + (e & 1) * 8;
            int cc = k * 8 + tq + (e >> 1) * 4;
            float v = Qs[rr * 68 + cc];
            float hi = tf32r(v);
            qr[k][e] = __float_as_uint(hi);
            qd[k][e] = __float_as_uint(tf32r(v - hi));
        }
    }

    float o[8][4];
#pragma unroll
    for (int nt = 0; nt < 8; nt++)
#pragma unroll
        for (int e = 0; e < 4; e++) o[nt][e] = 0.f;
    float m0 = -FLT_MAX, m1 = -FLT_MAX, l0 = 0.f, l1 = 0.f;

    const float* Kb = Kg + (size_t)b * NSEQ * DHEAD;
    const float* Vb = Vg + (size_t)b * NSEQ * DHEAD;

    for (int j0 = 0; j0 <= q0; j0 += 64) {
        __syncthreads();
        for (int i = tid; i < 1024; i += 128) {
            int r = i >> 4, d4 = (i & 15) * 4;
            float4 kv = *(const float4*)(Kb + (size_t)(j0 + r) * DHEAD + d4);
            float h0 = tf32r(kv.x), h1 = tf32r(kv.y), h2 = tf32r(kv.z), h3 = tf32r(kv.w);
            *(float4*)(Ks + r * 68 + d4) = make_float4(h0, h1, h2, h3);
            *(float4*)(Kd + r * 68 + d4) =
                make_float4(tf32r(kv.x - h0), tf32r(kv.y - h1), tf32r(kv.z - h2), tf32r(kv.w - h3));
            float4 vv = *(const float4*)(Vb + (size_t)(j0 + r) * DHEAD + d4);
            *(float4*)(Vs + r * 72 + d4) =
                make_float4(tf32r(vv.x), tf32r(vv.y), tf32r(vv.z), tf32r(vv.w));
        }
        __syncthreads();

        float s[8][4];
#pragma unroll
        for (int nt = 0; nt < 8; nt++) {
            s[nt][0] = s[nt][1] = s[nt][2] = s[nt][3] = 0.f;
            const float* krow = Ks + (nt * 8 + gq) * 68;
            const float* drow = Kd + (nt * 8 + gq) * 68;
#pragma unroll
            for (int k = 0; k < 8; k++) {
                uint32_t br[2] = { __float_as_uint(krow[k * 8 + tq]),
                                   __float_as_uint(krow[k * 8 + tq + 4]) };
                uint32_t bd[2] = { __float_as_uint(drow[k * 8 + tq]),
                                   __float_as_uint(drow[k * 8 + tq + 4]) };
                mma_tf32(s[nt], qr[k], br);
                mma_tf32(s[nt], qd[k], br);
                mma_tf32(s[nt], qr[k], bd);
            }
        }

        if (j0 == q0) {
            int r0 = wid * 16 + gq, r1 = r0 + 8;
#pragma unroll
            for (int nt = 0; nt < 8; nt++) {
                int jc = nt * 8 + 2 * tq;
                if (jc     > r0) s[nt][0] = -1e30f;
                if (jc + 1 > r0) s[nt][1] = -1e30f;
                if (jc     > r1) s[nt][2] = -1e30f;
                if (jc + 1 > r1) s[nt][3] = -1e30f;
            }
        }

        float rx0 = -1e30f, rx1 = -1e30f;
#pragma unroll
        for (int nt = 0; nt < 8; nt++) {
            rx0 = fmaxf(rx0, fmaxf(s[nt][0], s[nt][1]));
            rx1 = fmaxf(rx1, fmaxf(s[nt][2], s[nt][3]));
        }
        rx0 = fmaxf(rx0, __shfl_xor_sync(0xffffffff, rx0, 1));
        rx0 = fmaxf(rx0, __shfl_xor_sync(0xffffffff, rx0, 2));
        rx1 = fmaxf(rx1, __shfl_xor_sync(0xffffffff, rx1, 1));
        rx1 = fmaxf(rx1, __shfl_xor_sync(0xffffffff, rx1, 2));
        float mn0 = fmaxf(m0, rx0), mn1 = fmaxf(m1, rx1);
        float c0 = __expf(m0 - mn0), c1 = __expf(m1 - mn1);
        float ps0 = 0.f, ps1 = 0.f;
#pragma unroll
        for (int nt = 0; nt < 8; nt++) {
            s[nt][0] = __expf(s[nt][0] - mn0);
            s[nt][1] = __expf(s[nt][1] - mn0);
            s[nt][2] = __expf(s[nt][2] - mn1);
            s[nt][3] = __expf(s[nt][3] - mn1);
            ps0 += s[nt][0] + s[nt][1];
            ps1 += s[nt][2] + s[nt][3];
        }
        ps0 += __shfl_xor_sync(0xffffffff, ps0, 1);
        ps0 += __shfl_xor_sync(0xffffffff, ps0, 2);
        ps1 += __shfl_xor_sync(0xffffffff, ps1, 1);
        ps1 += __shfl_xor_sync(0xffffffff, ps1, 2);
        l0 = l0 * c0 + ps0;
        l1 = l1 * c1 + ps1;
#pragma unroll
        for (int nt = 0; nt < 8; nt++) {
            o[nt][0] *= c0; o[nt][1] *= c0;
            o[nt][2] *= c1; o[nt][3] *= c1;
        }
        m0 = mn0; m1 = mn1;

        uint32_t ap[8][4];
#pragma unroll
        for (int ks = 0; ks < 8; ks++) {
            int base = lane & ~3;
            int s0 = base + (tq >> 1), s1 = s0 + 2;
            float v00 = __shfl_sync(0xffffffff, s[ks][0], s0);
            float v01 = __shfl_sync(0xffffffff, s[ks][1], s0);
            float v20 = __shfl_sync(0xffffffff, s[ks][2], s0);
            float v21 = __shfl_sync(0xffffffff, s[ks][3], s0);
            float w00 = __shfl_sync(0xffffffff, s[ks][0], s1);
            float w01 = __shfl_sync(0xffffffff, s[ks][1], s1);
            float w20 = __shfl_sync(0xffffffff, s[ks][2], s1);
            float w21 = __shfl_sync(0xffffffff, s[ks][3], s1);
            bool oq = tq & 1;
            ap[ks][0] = __float_as_uint(tf32r(oq ? v01 : v00));
            ap[ks][1] = __float_as_uint(tf32r(oq ? v21 : v20));
            ap[ks][2] = __float_as_uint(tf32r(oq ? w01 : w00));
            ap[ks][3] = __float_as_uint(tf32r(oq ? w21 : w20));
        }

#pragma unroll
        for (int nt = 0; nt < 8; nt++) {
#pragma unroll
            for (int ks = 0; ks < 8; ks++) {
                int vr = ks * 8 + tq;
                int vc = nt * 8 + gq;
                uint32_t bv[2] = { __float_as_uint(Vs[vr * 72 + vc]),
                                   __float_as_uint(Vs[(vr + 4) * 72 + vc]) };
                mma_tf32(o[nt], ap[ks], bv);
            }
        }
    }

    float il0 = 1.f / l0, il1 = 1.f / l1;
    int rg0 = b * NSEQ + q0 + wid * 16 + gq;
#pragma unroll
    for (int nt = 0; nt < 8; nt++) {
        int col = h * 64 + nt * 8 + 2 * tq;
        float a0 = o[nt][0] * il0, a1 = o[nt][1] * il0;
        float a2 = o[nt][2] * il1, a3 = o[nt][3] * il1;
        *(float2*)(O + (size_t)rg0 * AINNER + col) = make_float2(a0, a1);
        *(float2*)(O + (size_t)(rg0 + 8) * AINNER + col) = make_float2(a2, a3);
        *(__half2*)(O16 + (size_t)rg0 * KC + col) = __floats2half2_rn(a0, a1);
        *(__half2*)(O16 + (size_t)(rg0 + 8) * KC + col) = __floats2half2_rn(a2, a3);
    }
}

// ---------------- OA[row,8] = OATTN_row @ a_o ----------------
__global__ void lora_oa_kernel(const float* __restrict__ oattn,
                               const float* __restrict__ ao,
                               float* __restrict__ oa) {
    int row = blockIdx.x;
    const float* xr = oattn + (size_t)row * AINNER;
    float acc[8];
#pragma unroll
    for (int r = 0; r < 8; r++) acc[r] = 0.f;
    for (int i = threadIdx.x; i < AINNER; i += 256) {
        float v = xr[i];
#pragma unroll
        for (int r = 0; r < 8; r++) acc[r] += v * ao[i * 8 + r];
    }
    __shared__ float sh[8][8];
    int wid = threadIdx.x >> 5, lane = threadIdx.x & 31;
#pragma unroll
    for (int r = 0; r < 8; r++)
        for (int o = 16; o > 0; o >>= 1)
            acc[r] += __shfl_xor_sync(0xffffffff, acc[r], o);
    if (lane == 0)
#pragma unroll
        for (int r = 0; r < 8; r++) sh[wid][r] = acc[r];
    __syncthreads();
    if (threadIdx.x < 8) {
        float s = 0.f;
        for (int w = 0; w < 8; w++) s += sh[w][threadIdx.x];
        oa[row * 8 + threadIdx.x] = s;
    }
}

// ---------------- out += OA @ b_o ----------------
__global__ void lora_o_add(const float* __restrict__ oa, const float* __restrict__ bo,
                           float* __restrict__ out) {
    int row = blockIdx.y;
    int c = blockIdx.x * 256 + threadIdx.x;
    float s = 0.f;
#pragma unroll
    for (int r = 0; r < 8; r++) s += oa[row * 8 + r] * bo[r * DIMX + c];
    out[(size_t)row * DIMX + c] += s;
}

// ---------------- launch ----------------
extern "C" void kernel_launch(void* const* d_in, const int* in_sizes, int n_in,
                              void* d_out, int out_size) {
    const float* x          = (const float*)d_in[0];
    const float* gamma      = (const float*)d_in[1];
    const float* w_fused    = (const float*)d_in[2];
    const float* w_attn_out = (const float*)d_in[3];
    const float* w_ff_out   = (const float*)d_in[4];
    const float* a_q        = (const float*)d_in[5];
    const float* b_q        = (const float*)d_in[6];
    const float* a_k        = (const float*)d_in[7];
    const float* b_k        = (const float*)d_in[8];
    const float* a_v        = (const float*)d_in[9];
    const float* b_v        = (const float*)d_in[10];
    const float* a_o        = (const float*)d_in[11];
    const float* b_o        = (const float*)d_in[12];
    float* out = (float*)d_out;

    float *XN, *F, *XA, *Q, *K, *V, *OATTN, *OA;
    __half *XN16, *WF16, *AC16, *WC16;
    cudaGetSymbolAddress((void**)&XN, g_XN);
    cudaGetSymbolAddress((void**)&XN16, g_XN16);
    cudaGetSymbolAddress((void**)&WF16, g_WF16);
    cudaGetSymbolAddress((void**)&F, g_F);
    cudaGetSymbolAddress((void**)&XA, g_XA);
    cudaGetSymbolAddress((void**)&Q, g_Q);
    cudaGetSymbolAddress((void**)&K, g_K);
    cudaGetSymbolAddress((void**)&V, g_V);
    cudaGetSymbolAddress((void**)&OATTN, g_OATTN);
    cudaGetSymbolAddress((void**)&AC16, g_AC16);
    cudaGetSymbolAddress((void**)&WC16, g_WC16);
    cudaGetSymbolAddress((void**)&OA, g_OA);

    cudaFuncSetAttribute(h_gemm, cudaFuncAttributeMaxDynamicSharedMemorySize, HGSMEM);
    cudaFuncSetAttribute(attn_mma, cudaFuncAttributeMaxDynamicSharedMemorySize, ATTN_SMEM);

    // weight prep
    w_t16_perm<<<dim3(FPAD / 32, DIMX / 32), dim3(32, 8)>>>(w_fused, WF16);
    w_t16s<<<dim3(DIMX / 32, AINNER / 32), dim3(32, 8)>>>(w_attn_out, WC16, AINNER, DIMX, KC, 0);
    w_t16s<<<dim3(DIMX / 32, FFINNER / 32), dim3(32, 8)>>>(w_ff_out, WC16, FFINNER, DIMX, KC, KOFF);

    ln_kernel<<<ROWS, 256>>>(x, gamma, XN, XN16);
    h_gemm<<<dim3(ROWS / 128, FPAD / 128), 256, HGSMEM>>>(XN16, WF16, nullptr, F, AC16, FPAD, DIMX, 1);
    lora_xa_kernel<<<ROWS, 256>>>(XN, a_q, a_k, a_v, XA);
    qkv_prep<<<ROWS, 256>>>(F, XA, b_q, b_k, b_v, Q, K, V);
    attn_mma<<<dim3(NSEQ / 64, HEADS, BATCH), 128, ATTN_SMEM>>>(Q, K, V, OATTN, AC16);
    // combined output GEMM: out = [OATTN | H] @ [WAO ; WFF]
    h_gemm<<<dim3(ROWS / 128, DIMX / 128), 256, HGSMEM>>>(AC16, WC16, out, nullptr, nullptr, DIMX, KC, 0);
    lora_oa_kernel<<<ROWS, 256>>>(OATTN, a_o, OA);
    lora_o_add<<<dim3(DIMX / 256, ROWS), 256>>>(OA, b_o, out);
}

// round 11
// speedup vs baseline: 2.0928x; 1.0691x over previous
#include <cuda_runtime.h>
#include <cuda_fp16.h>
#include <math.h>
#include <float.h>
#include <stdint.h>

// ---------------- problem constants ----------------
#define DIMX 2048
#define NSEQ 2048
#define BATCH 2
#define HEADS 16
#define DHEAD 64
#define ROWS (BATCH*NSEQ)          // 4096
#define AINNER 1024
#define FFINNER 8192
#define FUSEDC 17536
#define FPAD 17664                 // 138*128 (permuted width)
#define FQKV 1280
#define I0 1024
#define I1 1088
#define I2 1152
#define KC 9216                    // combined K: 1024 (attn) + 8192 (ff)
#define KOFF 1024

// ---------------- scratch (device globals) --------
__device__ __align__(16) __half g_XN16[(size_t)ROWS*DIMX];
__device__ __align__(16) __half g_WF16[(size_t)FPAD*DIMX];     // [n][k] (LoRA folded)
__device__ float g_F[(size_t)ROWS*FQKV];
__device__ float g_Q[(size_t)ROWS*AINNER];
__device__ float g_K[(size_t)ROWS*DHEAD];
__device__ float g_V[(size_t)ROWS*DHEAD];
__device__ __align__(16) __half g_AC16[(size_t)ROWS*KC];       // [attn | ff] fp16
__device__ __align__(16) __half g_WC16[(size_t)DIMX*KC];       // [n][kc] (LoRA folded)

// ---------------- small helpers ----------------
__device__ __forceinline__ float tf32r(float x) {
    uint32_t u;
    asm("cvt.rna.tf32.f32 %0, %1;" : "=r"(u) : "f"(x));
    return __uint_as_float(u);
}
__device__ __forceinline__ uint32_t smem_u32(const void* p) {
    uint32_t a;
    asm("{ .reg .u64 t; cvta.to.shared.u64 t, %1; cvt.u32.u64 %0, t; }" : "=r"(a) : "l"(p));
    return a;
}
__device__ __forceinline__ void cp16(uint32_t saddr, const void* g) {
    asm volatile("cp.async.cg.shared.global [%0], [%1], 16;" :: "r"(saddr), "l"(g) : "memory");
}
__device__ __forceinline__ void mma_tf32(float* d, const uint32_t* a, const uint32_t* b) {
    asm volatile(
        "mma.sync.aligned.m16n8k8.row.col.f32.tf32.tf32.f32 "
        "{%0,%1,%2,%3}, {%4,%5,%6,%7}, {%8,%9}, {%0,%1,%2,%3};"
        : "+f"(d[0]), "+f"(d[1]), "+f"(d[2]), "+f"(d[3])
        : "r"(a[0]), "r"(a[1]), "r"(a[2]), "r"(a[3]), "r"(b[0]), "r"(b[1]));
}
__device__ __forceinline__ void mma_f16(float* d, const uint32_t* a, const uint32_t* b) {
    asm volatile(
        "mma.sync.aligned.m16n8k16.row.col.f32.f16.f16.f32 "
        "{%0,%1,%2,%3}, {%4,%5,%6,%7}, {%8,%9}, {%0,%1,%2,%3};"
        : "+f"(d[0]), "+f"(d[1]), "+f"(d[2]), "+f"(d[3])
        : "r"(a[0]), "r"(a[1]), "r"(a[2]), "r"(a[3]), "r"(b[0]), "r"(b[1]));
}

// ================= FP16 GEMM, 32-deep K stages =================
#define HGS 4
#define HROW 20                 // words per 32-half row (16 data + 4 pad)
#define HSTW (256*HROW)         // 5120 words/stage
#define HGSMEM (HGS*HSTW*4)     // 81920 bytes

__global__ __launch_bounds__(256, 2) void h_gemm(const __half* __restrict__ A,
                                                 const __half* __restrict__ Bt,
                                                 float* __restrict__ C,
                                                 float* __restrict__ F,
                                                 __half* __restrict__ Hc,
                                                 int N, int K, int fused) {
    extern __shared__ float smemf[];
    uint32_t* sm32 = (uint32_t*)smemf;
    const int tid = threadIdx.x;
    const int wid = tid >> 5, lane = tid & 31;
    const int gq = lane >> 2, tg = lane & 3;
    const int wm = (wid & 3) * 32, wn = (wid >> 2) * 64;
    const int m0 = blockIdx.x * 128, n0 = blockIdx.y * 128;
    const __half* Ag = A + (size_t)m0 * K;
    const __half* Bg = Bt + (size_t)n0 * K;
    const uint32_t sb = smem_u32(smemf);

    const int lrow = tid >> 1;            // 0..127
    const int lp = (tid & 1) * 2;         // part base {0,2}
    const int NK = K >> 5;

    auto load_stage = [&](int kt, int s) {
        const uint32_t sa = sb + s * HSTW * 4;
        const uint32_t sB = sa + 128 * HROW * 4;
        const __half* ag = Ag + (size_t)lrow * K + kt * 32;
        const __half* bg = Bg + (size_t)lrow * K + kt * 32;
#pragma unroll
        for (int i = 0; i < 2; i++) {
            int p = lp + i;
            uint32_t off = (lrow * HROW + p * 4) * 4;
            cp16(sa + off, ag + p * 8);
            cp16(sB + off, bg + p * 8);
        }
    };

    float acc[2][8][4];
#pragma unroll
    for (int mt = 0; mt < 2; mt++)
#pragma unroll
        for (int nt = 0; nt < 8; nt++)
#pragma unroll
            for (int i = 0; i < 4; i++) acc[mt][nt][i] = 0.f;

#pragma unroll
    for (int p = 0; p < 3; p++) {
        load_stage(p, p);
        asm volatile("cp.async.commit_group;" ::: "memory");
    }

#pragma unroll 1
    for (int kt = 0; kt < NK; kt++) {
        asm volatile("cp.async.wait_group 2;" ::: "memory");
        __syncthreads();
        if (kt + 3 < NK) load_stage(kt + 3, (kt + 3) & 3);
        asm volatile("cp.async.commit_group;" ::: "memory");

        const int s = kt & 3;
        const uint32_t* As = sm32 + s * HSTW;
        const uint32_t* Bs = As + 128 * HROW;

#pragma unroll
        for (int ks = 0; ks < 2; ks++) {
            uint32_t a[2][4], b[8][2];
#pragma unroll
            for (int mt = 0; mt < 2; mt++) {
                int r = wm + mt * 16 + gq;
                a[mt][0] = As[r * HROW + ks * 8 + tg];
                a[mt][1] = As[(r + 8) * HROW + ks * 8 + tg];
                a[mt][2] = As[r * HROW + ks * 8 + tg + 4];
                a[mt][3] = As[(r + 8) * HROW + ks * 8 + tg + 4];
            }
#pragma unroll
            for (int nt = 0; nt < 8; nt++) {
                int n = wn + nt * 8 + gq;
                b[nt][0] = Bs[n * HROW + ks * 8 + tg];
                b[nt][1] = Bs[n * HROW + ks * 8 + tg + 4];
            }
#pragma unroll
            for (int mt = 0; mt < 2; mt++)
#pragma unroll
                for (int nt = 0; nt < 8; nt++)
                    mma_f16(acc[mt][nt], a[mt], b[nt]);
        }
    }

    // epilogue
    const int rbase = m0 + wm + gq;
    const int cbase = n0 + wn + tg * 2;
    if (!fused) {
#pragma unroll
        for (int mt = 0; mt < 2; mt++) {
#pragma unroll
            for (int nt = 0; nt < 8; nt++) {
                int r = rbase + mt * 16;
                int cc = cbase + nt * 8;
                *(float2*)(C + (size_t)r * N + cc) =
                    make_float2(acc[mt][nt][0], acc[mt][nt][1]);
                *(float2*)(C + (size_t)(r + 8) * N + cc) =
                    make_float2(acc[mt][nt][2], acc[mt][nt][3]);
            }
        }
    } else if (n0 < FQKV) {
#pragma unroll
        for (int mt = 0; mt < 2; mt++) {
#pragma unroll
            for (int nt = 0; nt < 8; nt++) {
                int r = rbase + mt * 16;
                int cc = cbase + nt * 8;
                *(float2*)(F + (size_t)r * FQKV + cc) =
                    make_float2(acc[mt][nt][0], acc[mt][nt][1]);
                *(float2*)(F + (size_t)(r + 8) * FQKV + cc) =
                    make_float2(acc[mt][nt][2], acc[mt][nt][3]);
            }
        }
    } else {
        // ff region: (x, gate) pairs -> AC16[:, KOFF + hc] = half(x * silu(gate))
#pragma unroll
        for (int mt = 0; mt < 2; mt++) {
#pragma unroll
            for (int nt = 0; nt < 8; nt++) {
                int r = rbase + mt * 16;
                int hc = (cbase + nt * 8 - FQKV) >> 1;
                float x0 = acc[mt][nt][0], gg0 = acc[mt][nt][1];
                float x1 = acc[mt][nt][2], gg1 = acc[mt][nt][3];
                Hc[(size_t)r * KC + KOFF + hc]       = __float2half(x0 * gg0 / (1.f + __expf(-gg0)));
                Hc[(size_t)(r + 8) * KC + KOFF + hc] = __float2half(x1 * gg1 / (1.f + __expf(-gg1)));
            }
        }
    }
}

// ---------------- weight transpose + fp16 + optional LoRA fold ----------
// in fp32 [Kd][Nd] -> out fp16 [n][ostride] @ col ooff.
// If la != nullptr: val += sum_r la[k*8+r] * lb[r*Nd + n]  (rank 8)
__global__ void w_t16s(const float* __restrict__ in, __half* __restrict__ out,
                       int Kd, int Nd, int ostride, int ooff,
                       const float* __restrict__ la, const float* __restrict__ lb) {
    __shared__ float t[32][33];
    int k0 = blockIdx.y * 32, n0 = blockIdx.x * 32;
    int tx = threadIdx.x, ty = threadIdx.y;
#pragma unroll
    for (int i = 0; i < 4; i++) {
        int k = k0 + ty + 8 * i;
        int n = n0 + tx;
        float val = in[(size_t)k * Nd + n];
        if (la) {
#pragma unroll
            for (int r = 0; r < 8; r++)
                val += la[k * 8 + r] * lb[r * Nd + n];
        }
        t[ty + 8 * i][tx] = val;
    }
    __syncthreads();
#pragma unroll
    for (int i = 0; i < 4; i++)
        out[(size_t)(n0 + ty + 8 * i) * ostride + ooff + k0 + tx] = __float2half(t[tx][ty + 8 * i]);
}

// fused weight: transpose + permute + fp16, with q/k/v LoRA folded.
// out [FPAD][DIMX].
__global__ void w_t16_perm(const float* __restrict__ in, __half* __restrict__ out,
                           const float* __restrict__ aq, const float* __restrict__ bq,
                           const float* __restrict__ ak, const float* __restrict__ bk,
                           const float* __restrict__ av, const float* __restrict__ bv) {
    __shared__ float t[32][33];
    int k0 = blockIdx.y * 32, n0 = blockIdx.x * 32;
    int tx = threadIdx.x, ty = threadIdx.y;
#pragma unroll
    for (int i = 0; i < 4; i++) {
        int k = k0 + ty + 8 * i;
        int j = n0 + tx;
        float val;
        if (j < I0) {
            val = in[(size_t)k * FUSEDC + j];
#pragma unroll
            for (int r = 0; r < 8; r++) val += aq[k * 8 + r] * bq[r * AINNER + j];
        } else if (j < I1) {
            val = in[(size_t)k * FUSEDC + j];
            int d = j - I0;
#pragma unroll
            for (int r = 0; r < 8; r++) val += ak[k * 8 + r] * bk[r * DHEAD + d];
        } else if (j < I2) {
            val = in[(size_t)k * FUSEDC + j];
            int d = j - I1;
#pragma unroll
            for (int r = 0; r < 8; r++) val += av[k * 8 + r] * bv[r * DHEAD + d];
        } else if (j < FQKV) {
            val = 0.f;
        } else {
            int p = j - FQKV;
            val = in[(size_t)k * FUSEDC + I2 + (p >> 1) + (p & 1) * FFINNER];
        }
        t[ty + 8 * i][tx] = val;
    }
    __syncthreads();
#pragma unroll
    for (int i = 0; i < 4; i++)
        out[(size_t)(n0 + ty + 8 * i) * DIMX + k0 + tx] = __float2half(t[tx][ty + 8 * i]);
}

// ---------------- layernorm (fp16 out) ----------------
__global__ void ln_kernel(const float* __restrict__ x, const float* __restrict__ gamma,
                          __half* __restrict__ xn16) {
    int row = blockIdx.x;
    const float* xr = x + (size_t)row * DIMX;
    float s = 0.f, s2 = 0.f;
    for (int i = threadIdx.x; i < DIMX; i += 256) { float v = xr[i]; s += v; s2 += v * v; }
    for (int o = 16; o > 0; o >>= 1) {
        s  += __shfl_xor_sync(0xffffffff, s,  o);
        s2 += __shfl_xor_sync(0xffffffff, s2, o);
    }
    __shared__ float sh[16];
    int wid = threadIdx.x >> 5, lane = threadIdx.x & 31;
    if (lane == 0) { sh[wid] = s; sh[8 + wid] = s2; }
    __syncthreads();
    if (threadIdx.x == 0) {
        float S = 0.f, S2 = 0.f;
        for (int w = 0; w < 8; w++) { S += sh[w]; S2 += sh[8 + w]; }
        sh[0] = S; sh[8] = S2;
    }
    __syncthreads();
    float mu = sh[0] * (1.f / DIMX);
    float var = sh[8] * (1.f / DIMX) - mu * mu;
    float inv = rsqrtf(var + 1e-5f);
    __half* o16 = xn16 + (size_t)row * DIMX;
    for (int i = threadIdx.x; i < DIMX; i += 256)
        o16[i] = __float2half((xr[i] - mu) * inv * gamma[i]);
}

// ---------------- qkv prep (LoRA pre-folded into weights) ----------------
__global__ void qkv_prep(const float* __restrict__ F,
                         float* __restrict__ Q, float* __restrict__ Kv, float* __restrict__ V) {
    int row = blockIdx.x;
    int n = row % NSEQ;
    __shared__ float qs[AINNER];
    __shared__ float ks[DHEAD];
    const float* Fr = F + (size_t)row * FQKV;

    for (int c = threadIdx.x; c < AINNER; c += 256) qs[c] = Fr[c];
    if (threadIdx.x < DHEAD) {
        ks[threadIdx.x] = Fr[I0 + threadIdx.x];
        V[(size_t)row * DHEAD + threadIdx.x] = Fr[I1 + threadIdx.x];
    }
    __syncthreads();

    const float ln10k_inv32 = 9.2103403719761836f / 32.f;
    const float scale = 0.125f;
    for (int c = threadIdx.x; c < AINNER; c += 256) {
        int h = c >> 6, d = c & 63;
        int fi = d & 31;
        float freq = (float)n * __expf(-(float)fi * ln10k_inv32);
        float cs = cosf(freq), sn = sinf(freq);
        float me = qs[c];
        float partner = (d < 32) ? -qs[h * 64 + d + 32] : qs[h * 64 + d - 32];
        Q[(size_t)row * AINNER + c] = (me * cs + partner * sn) * scale;
    }
    if (threadIdx.x < DHEAD) {
        int d = threadIdx.x;
        int fi = d & 31;
        float freq = (float)n * __expf(-(float)fi * ln10k_inv32);
        float cs = cosf(freq), sn = sinf(freq);
        float me = ks[d];
        float partner = (d < 32) ? -ks[d + 32] : ks[d - 32];
        Kv[(size_t)row * DHEAD + d] = me * cs + partner * sn;
    }
}

// ================= MMA flash attention =================
#define ATTN_SMEM ((64*68*3 + 64*72)*4)

__global__ __launch_bounds__(128) void attn_mma(const float* __restrict__ Qg,
                                                const float* __restrict__ Kg,
                                                const float* __restrict__ Vg,
                                                __half* __restrict__ O16) {
    extern __shared__ float sm[];
    float* Qs = sm;
    float* Ks = sm + 64 * 68;
    float* Kd = sm + 2 * 64 * 68;
    float* Vs = sm + 3 * 64 * 68;

    const int tid = threadIdx.x, wid = tid >> 5, lane = tid & 31;
    const int gq = lane >> 2, tq = lane & 3;
    const int qt = gridDim.x - 1 - blockIdx.x;
    const int h = blockIdx.y, b = blockIdx.z;
    const int q0 = qt * 64;

    for (int i = tid; i < 1024; i += 128) {
        int r = i >> 4, d4 = (i & 15) * 4;
        *(float4*)(Qs + r * 68 + d4) =
            *(const float4*)(Qg + (size_t)(b * NSEQ + q0 + r) * AINNER + h * 64 + d4);
    }
    __syncthreads();

    uint32_t qr[8][4], qd[8][4];
#pragma unroll
    for (int k = 0; k < 8; k++) {
#pragma unroll
        for (int e = 0; e < 4; e++) {
            int rr = wid * 16 + gq + (e & 1) * 8;
            int cc = k * 8 + tq + (e >> 1) * 4;
            float v = Qs[rr * 68 + cc];
            float hi = tf32r(v);
            qr[k][e] = __float_as_uint(hi);
            qd[k][e] = __float_as_uint(tf32r(v - hi));
        }
    }

    float o[8][4];
#pragma unroll
    for (int nt = 0; nt < 8; nt++)
#pragma unroll
        for (int e = 0; e < 4; e++) o[nt][e] = 0.f;
    float m0 = -FLT_MAX, m1 = -FLT_MAX, l0 = 0.f, l1 = 0.f;

    const float* Kb = Kg + (size_t)b * NSEQ * DHEAD;
    const float* Vb = Vg + (size_t)b * NSEQ * DHEAD;

    for (int j0 = 0; j0 <= q0; j0 += 64) {
        __syncthreads();
        for (int i = tid; i < 1024; i += 128) {
            int r = i >> 4, d4 = (i & 15) * 4;
            float4 kv = *(const float4*)(Kb + (size_t)(j0 + r) * DHEAD + d4);
            float h0 = tf32r(kv.x), h1 = tf32r(kv.y), h2 = tf32r(kv.z), h3 = tf32r(kv.w);
            *(float4*)(Ks + r * 68 + d4) = make_float4(h0, h1, h2, h3);
            *(float4*)(Kd + r * 68 + d4) =
                make_float4(tf32r(kv.x - h0), tf32r(kv.y - h1), tf32r(kv.z - h2), tf32r(kv.w - h3));
            float4 vv = *(const float4*)(Vb + (size_t)(j0 + r) * DHEAD + d4);
            *(float4*)(Vs + r * 72 + d4) =
                make_float4(tf32r(vv.x), tf32r(vv.y), tf32r(vv.z), tf32r(vv.w));
        }
        __syncthreads();

        float s[8][4];
#pragma unroll
        for (int nt = 0; nt < 8; nt++) {
            s[nt][0] = s[nt][1] = s[nt][2] = s[nt][3] = 0.f;
            const float* krow = Ks + (nt * 8 + gq) * 68;
            const float* drow = Kd + (nt * 8 + gq) * 68;
#pragma unroll
            for (int k = 0; k < 8; k++) {
                uint32_t br[2] = { __float_as_uint(krow[k * 8 + tq]),
                                   __float_as_uint(krow[k * 8 + tq + 4]) };
                uint32_t bd[2] = { __float_as_uint(drow[k * 8 + tq]),
                                   __float_as_uint(drow[k * 8 + tq + 4]) };
                mma_tf32(s[nt], qr[k], br);
                mma_tf32(s[nt], qd[k], br);
                mma_tf32(s[nt], qr[k], bd);
            }
        }

        if (j0 == q0) {
            int r0 = wid * 16 + gq, r1 = r0 + 8;
#pragma unroll
            for (int nt = 0; nt < 8; nt++) {
                int jc = nt * 8 + 2 * tq;
                if (jc     > r0) s[nt][0] = -1e30f;
                if (jc + 1 > r0) s[nt][1] = -1e30f;
                if (jc     > r1) s[nt][2] = -1e30f;
                if (jc + 1 > r1) s[nt][3] = -1e30f;
            }
        }

        float rx0 = -1e30f, rx1 = -1e30f;
#pragma unroll
        for (int nt = 0; nt < 8; nt++) {
            rx0 = fmaxf(rx0, fmaxf(s[nt][0], s[nt][1]));
            rx1 = fmaxf(rx1, fmaxf(s[nt][2], s[nt][3]));
        }
        rx0 = fmaxf(rx0, __shfl_xor_sync(0xffffffff, rx0, 1));
        rx0 = fmaxf(rx0, __shfl_xor_sync(0xffffffff, rx0, 2));
        rx1 = fmaxf(rx1, __shfl_xor_sync(0xffffffff, rx1, 1));
        rx1 = fmaxf(rx1, __shfl_xor_sync(0xffffffff, rx1, 2));
        float mn0 = fmaxf(m0, rx0), mn1 = fmaxf(m1, rx1);
        float c0 = __expf(m0 - mn0), c1 = __expf(m1 - mn1);
        float ps0 = 0.f, ps1 = 0.f;
#pragma unroll
        for (int nt = 0; nt < 8; nt++) {
            s[nt][0] = __expf(s[nt][0] - mn0);
            s[nt][1] = __expf(s[nt][1] - mn0);
            s[nt][2] = __expf(s[nt][2] - mn1);
            s[nt][3] = __expf(s[nt][3] - mn1);
            ps0 += s[nt][0] + s[nt][1];
            ps1 += s[nt][2] + s[nt][3];
        }
        ps0 += __shfl_xor_sync(0xffffffff, ps0, 1);
        ps0 += __shfl_xor_sync(0xffffffff, ps0, 2);
        ps1 += __shfl_xor_sync(0xffffffff, ps1, 1);
        ps1 += __shfl_xor_sync(0xffffffff, ps1, 2);
        l0 = l0 * c0 + ps0;
        l1 = l1 * c1 + ps1;
#pragma unroll
        for (int nt = 0; nt < 8; nt++) {
            o[nt][0] *= c0; o[nt][1] *= c0;
            o[nt][2] *= c1; o[nt][3] *= c1;
        }
        m0 = mn0; m1 = mn1;

        uint32_t ap[8][4];
#pragma unroll
        for (int ks = 0; ks < 8; ks++) {
            int base = lane & ~3;
            int s0 = base + (tq >> 1), s1 = s0 + 2;
            float v00 = __shfl_sync(0xffffffff, s[ks][0], s0);
            float v01 = __shfl_sync(0xffffffff, s[ks][1], s0);
            float v20 = __shfl_sync(0xffffffff, s[ks][2], s0);
            float v21 = __shfl_sync(0xffffffff, s[ks][3], s0);
            float w00 = __shfl_sync(0xffffffff, s[ks][0], s1);
            float w01 = __shfl_sync(0xffffffff, s[ks][1], s1);
            float w20 = __shfl_sync(0xffffffff, s[ks][2], s1);
            float w21 = __shfl_sync(0xffffffff, s[ks][3], s1);
            bool oq = tq & 1;
            ap[ks][0] = __float_as_uint(tf32r(oq ? v01 : v00));
            ap[ks][1] = __float_as_uint(tf32r(oq ? v21 : v20));
            ap[ks][2] = __float_as_uint(tf32r(oq ? w01 : w00));
            ap[ks][3] = __float_as_uint(tf32r(oq ? w21 : w20));
        }

#pragma unroll
        for (int nt = 0; nt < 8; nt++) {
#pragma unroll
            for (int ks = 0; ks < 8; ks++) {
                int vr = ks * 8 + tq;
                int vc = nt * 8 + gq;
                uint32_t bv[2] = { __float_as_uint(Vs[vr * 72 + vc]),
                                   __float_as_uint(Vs[(vr + 4) * 72 + vc]) };
                mma_tf32(o[nt], ap[ks], bv);
            }
        }
    }

    float il0 = 1.f / l0, il1 = 1.f / l1;
    int rg0 = b * NSEQ + q0 + wid * 16 + gq;
#pragma unroll
    for (int nt = 0; nt < 8; nt++) {
        int col = h * 64 + nt * 8 + 2 * tq;
        *(__half2*)(O16 + (size_t)rg0 * KC + col) =
            __floats2half2_rn(o[nt][0] * il0, o[nt][1] * il0);
        *(__half2*)(O16 + (size_t)(rg0 + 8) * KC + col) =
            __floats2half2_rn(o[nt][2] * il1, o[nt][3] * il1);
    }
}

// ---------------- launch ----------------
extern "C" void kernel_launch(void* const* d_in, const int* in_sizes, int n_in,
                              void* d_out, int out_size) {
    const float* x          = (const float*)d_in[0];
    const float* gamma      = (const float*)d_in[1];
    const float* w_fused    = (const float*)d_in[2];
    const float* w_attn_out = (const float*)d_in[3];
    const float* w_ff_out   = (const float*)d_in[4];
    const float* a_q        = (const float*)d_in[5];
    const float* b_q        = (const float*)d_in[6];
    const float* a_k        = (const float*)d_in[7];
    const float* b_k        = (const float*)d_in[8];
    const float* a_v        = (const float*)d_in[9];
    const float* b_v        = (const float*)d_in[10];
    const float* a_o        = (const float*)d_in[11];
    const float* b_o        = (const float*)d_in[12];
    float* out = (float*)d_out;

    float *F, *Q, *K, *V;
    __half *XN16, *WF16, *AC16, *WC16;
    cudaGetSymbolAddress((void**)&XN16, g_XN16);
    cudaGetSymbolAddress((void**)&WF16, g_WF16);
    cudaGetSymbolAddress((void**)&F, g_F);
    cudaGetSymbolAddress((void**)&Q, g_Q);
    cudaGetSymbolAddress((void**)&K, g_K);
    cudaGetSymbolAddress((void**)&V, g_V);
    cudaGetSymbolAddress((void**)&AC16, g_AC16);
    cudaGetSymbolAddress((void**)&WC16, g_WC16);

    cudaFuncSetAttribute(h_gemm, cudaFuncAttributeMaxDynamicSharedMemorySize, HGSMEM);
    cudaFuncSetAttribute(attn_mma, cudaFuncAttributeMaxDynamicSharedMemorySize, ATTN_SMEM);

    // weight prep with LoRA folding
    w_t16_perm<<<dim3(FPAD / 32, DIMX / 32), dim3(32, 8)>>>(w_fused, WF16,
                                                            a_q, b_q, a_k, b_k, a_v, b_v);
    w_t16s<<<dim3(DIMX / 32, AINNER / 32), dim3(32, 8)>>>(w_attn_out, WC16, AINNER, DIMX, KC, 0,
                                                          a_o, b_o);
    w_t16s<<<dim3(DIMX / 32, FFINNER / 32), dim3(32, 8)>>>(w_ff_out, WC16, FFINNER, DIMX, KC, KOFF,
                                                           nullptr, nullptr);

    ln_kernel<<<ROWS, 256>>>(x, gamma, XN16);
    h_gemm<<<dim3(ROWS / 128, FPAD / 128), 256, HGSMEM>>>(XN16, WF16, nullptr, F, AC16, FPAD, DIMX, 1);
    qkv_prep<<<ROWS, 256>>>(F, Q, K, V);
    attn_mma<<<dim3(NSEQ / 64, HEADS, BATCH), 128, ATTN_SMEM>>>(Q, K, V, AC16);
    // combined output GEMM: out = [OATTN | H] @ [WAO+a_o b_o ; WFF]
    h_gemm<<<dim3(ROWS / 128, DIMX / 128), 256, HGSMEM>>>(AC16, WC16, out, nullptr, nullptr, DIMX, KC, 0);
}

// round 12
// speedup vs baseline: 2.1922x; 1.0475x over previous
#include <cuda_runtime.h>
#include <cuda_fp16.h>
#include <math.h>
#include <float.h>
#include <stdint.h>

// ---------------- problem constants ----------------
#define DIMX 2048
#define NSEQ 2048
#define BATCH 2
#define HEADS 16
#define DHEAD 64
#define ROWS (BATCH*NSEQ)          // 4096
#define AINNER 1024
#define FFINNER 8192
#define FUSEDC 17536
#define FPAD 17664                 // 138*128 (permuted width)
#define FQKV 1280
#define I0 1024
#define I1 1088
#define I2 1152
#define KC 9216                    // combined K: 1024 (attn) + 8192 (ff)
#define KOFF 1024

// ---------------- scratch (device globals) --------
__device__ __align__(16) __half g_XN16[(size_t)ROWS*DIMX];
__device__ __align__(16) __half g_WF16[(size_t)FPAD*DIMX];     // [n][k] (LoRA folded)
__device__ float g_F[(size_t)ROWS*FQKV];
__device__ float g_Q[(size_t)ROWS*AINNER];
__device__ float g_K[(size_t)ROWS*DHEAD];
__device__ float g_V[(size_t)ROWS*DHEAD];
__device__ __align__(16) __half g_AC16[(size_t)ROWS*KC];       // [attn | ff] fp16
__device__ __align__(16) __half g_WC16[(size_t)DIMX*KC];       // [n][kc] (LoRA folded)

// ---------------- small helpers ----------------
__device__ __forceinline__ uint32_t smem_u32(const void* p) {
    uint32_t a;
    asm("{ .reg .u64 t; cvta.to.shared.u64 t, %1; cvt.u32.u64 %0, t; }" : "=r"(a) : "l"(p));
    return a;
}
__device__ __forceinline__ void cp16(uint32_t saddr, const void* g) {
    asm volatile("cp.async.cg.shared.global [%0], [%1], 16;" :: "r"(saddr), "l"(g) : "memory");
}
__device__ __forceinline__ void mma_f16(float* d, const uint32_t* a, const uint32_t* b) {
    asm volatile(
        "mma.sync.aligned.m16n8k16.row.col.f32.f16.f16.f32 "
        "{%0,%1,%2,%3}, {%4,%5,%6,%7}, {%8,%9}, {%0,%1,%2,%3};"
        : "+f"(d[0]), "+f"(d[1]), "+f"(d[2]), "+f"(d[3])
        : "r"(a[0]), "r"(a[1]), "r"(a[2]), "r"(a[3]), "r"(b[0]), "r"(b[1]));
}
__device__ __forceinline__ uint32_t pack_h2(float lo, float hi) {
    __half2 h = __floats2half2_rn(lo, hi);
    return *(uint32_t*)&h;
}

// ================= FP16 GEMM, 32-deep K stages (R11 winner, unchanged) ====
#define HGS 4
#define HROW 20
#define HSTW (256*HROW)
#define HGSMEM (HGS*HSTW*4)     // 81920 bytes

__global__ __launch_bounds__(256, 2) void h_gemm(const __half* __restrict__ A,
                                                 const __half* __restrict__ Bt,
                                                 float* __restrict__ C,
                                                 float* __restrict__ F,
                                                 __half* __restrict__ Hc,
                                                 int N, int K, int fused) {
    extern __shared__ float smemf[];
    uint32_t* sm32 = (uint32_t*)smemf;
    const int tid = threadIdx.x;
    const int wid = tid >> 5, lane = tid & 31;
    const int gq = lane >> 2, tg = lane & 3;
    const int wm = (wid & 3) * 32, wn = (wid >> 2) * 64;
    const int m0 = blockIdx.x * 128, n0 = blockIdx.y * 128;
    const __half* Ag = A + (size_t)m0 * K;
    const __half* Bg = Bt + (size_t)n0 * K;
    const uint32_t sb = smem_u32(smemf);

    const int lrow = tid >> 1;
    const int lp = (tid & 1) * 2;
    const int NK = K >> 5;

    auto load_stage = [&](int kt, int s) {
        const uint32_t sa = sb + s * HSTW * 4;
        const uint32_t sB = sa + 128 * HROW * 4;
        const __half* ag = Ag + (size_t)lrow * K + kt * 32;
        const __half* bg = Bg + (size_t)lrow * K + kt * 32;
#pragma unroll
        for (int i = 0; i < 2; i++) {
            int p = lp + i;
            uint32_t off = (lrow * HROW + p * 4) * 4;
            cp16(sa + off, ag + p * 8);
            cp16(sB + off, bg + p * 8);
        }
    };

    float acc[2][8][4];
#pragma unroll
    for (int mt = 0; mt < 2; mt++)
#pragma unroll
        for (int nt = 0; nt < 8; nt++)
#pragma unroll
            for (int i = 0; i < 4; i++) acc[mt][nt][i] = 0.f;

#pragma unroll
    for (int p = 0; p < 3; p++) {
        load_stage(p, p);
        asm volatile("cp.async.commit_group;" ::: "memory");
    }

#pragma unroll 1
    for (int kt = 0; kt < NK; kt++) {
        asm volatile("cp.async.wait_group 2;" ::: "memory");
        __syncthreads();
        if (kt + 3 < NK) load_stage(kt + 3, (kt + 3) & 3);
        asm volatile("cp.async.commit_group;" ::: "memory");

        const int s = kt & 3;
        const uint32_t* As = sm32 + s * HSTW;
        const uint32_t* Bs = As + 128 * HROW;

#pragma unroll
        for (int ks = 0; ks < 2; ks++) {
            uint32_t a[2][4], b[8][2];
#pragma unroll
            for (int mt = 0; mt < 2; mt++) {
                int r = wm + mt * 16 + gq;
                a[mt][0] = As[r * HROW + ks * 8 + tg];
                a[mt][1] = As[(r + 8) * HROW + ks * 8 + tg];
                a[mt][2] = As[r * HROW + ks * 8 + tg + 4];
                a[mt][3] = As[(r + 8) * HROW + ks * 8 + tg + 4];
            }
#pragma unroll
            for (int nt = 0; nt < 8; nt++) {
                int n = wn + nt * 8 + gq;
                b[nt][0] = Bs[n * HROW + ks * 8 + tg];
                b[nt][1] = Bs[n * HROW + ks * 8 + tg + 4];
            }
#pragma unroll
            for (int mt = 0; mt < 2; mt++)
#pragma unroll
                for (int nt = 0; nt < 8; nt++)
                    mma_f16(acc[mt][nt], a[mt], b[nt]);
        }
    }

    const int rbase = m0 + wm + gq;
    const int cbase = n0 + wn + tg * 2;
    if (!fused) {
#pragma unroll
        for (int mt = 0; mt < 2; mt++) {
#pragma unroll
            for (int nt = 0; nt < 8; nt++) {
                int r = rbase + mt * 16;
                int cc = cbase + nt * 8;
                *(float2*)(C + (size_t)r * N + cc) =
                    make_float2(acc[mt][nt][0], acc[mt][nt][1]);
                *(float2*)(C + (size_t)(r + 8) * N + cc) =
                    make_float2(acc[mt][nt][2], acc[mt][nt][3]);
            }
        }
    } else if (n0 < FQKV) {
#pragma unroll
        for (int mt = 0; mt < 2; mt++) {
#pragma unroll
            for (int nt = 0; nt < 8; nt++) {
                int r = rbase + mt * 16;
                int cc = cbase + nt * 8;
                *(float2*)(F + (size_t)r * FQKV + cc) =
                    make_float2(acc[mt][nt][0], acc[mt][nt][1]);
                *(float2*)(F + (size_t)(r + 8) * FQKV + cc) =
                    make_float2(acc[mt][nt][2], acc[mt][nt][3]);
            }
        }
    } else {
#pragma unroll
        for (int mt = 0; mt < 2; mt++) {
#pragma unroll
            for (int nt = 0; nt < 8; nt++) {
                int r = rbase + mt * 16;
                int hc = (cbase + nt * 8 - FQKV) >> 1;
                float x0 = acc[mt][nt][0], gg0 = acc[mt][nt][1];
                float x1 = acc[mt][nt][2], gg1 = acc[mt][nt][3];
                Hc[(size_t)r * KC + KOFF + hc]       = __float2half(x0 * gg0 / (1.f + __expf(-gg0)));
                Hc[(size_t)(r + 8) * KC + KOFF + hc] = __float2half(x1 * gg1 / (1.f + __expf(-gg1)));
            }
        }
    }
}

// ---------------- weight transpose + fp16 + optional LoRA fold ----------
__global__ void w_t16s(const float* __restrict__ in, __half* __restrict__ out,
                       int Kd, int Nd, int ostride, int ooff,
                       const float* __restrict__ la, const float* __restrict__ lb) {
    __shared__ float t[32][33];
    int k0 = blockIdx.y * 32, n0 = blockIdx.x * 32;
    int tx = threadIdx.x, ty = threadIdx.y;
#pragma unroll
    for (int i = 0; i < 4; i++) {
        int k = k0 + ty + 8 * i;
        int n = n0 + tx;
        float val = in[(size_t)k * Nd + n];
        if (la) {
#pragma unroll
            for (int r = 0; r < 8; r++)
                val += la[k * 8 + r] * lb[r * Nd + n];
        }
        t[ty + 8 * i][tx] = val;
    }
    __syncthreads();
#pragma unroll
    for (int i = 0; i < 4; i++)
        out[(size_t)(n0 + ty + 8 * i) * ostride + ooff + k0 + tx] = __float2half(t[tx][ty + 8 * i]);
}

__global__ void w_t16_perm(const float* __restrict__ in, __half* __restrict__ out,
                           const float* __restrict__ aq, const float* __restrict__ bq,
                           const float* __restrict__ ak, const float* __restrict__ bk,
                           const float* __restrict__ av, const float* __restrict__ bv) {
    __shared__ float t[32][33];
    int k0 = blockIdx.y * 32, n0 = blockIdx.x * 32;
    int tx = threadIdx.x, ty = threadIdx.y;
#pragma unroll
    for (int i = 0; i < 4; i++) {
        int k = k0 + ty + 8 * i;
        int j = n0 + tx;
        float val;
        if (j < I0) {
            val = in[(size_t)k * FUSEDC + j];
#pragma unroll
            for (int r = 0; r < 8; r++) val += aq[k * 8 + r] * bq[r * AINNER + j];
        } else if (j < I1) {
            val = in[(size_t)k * FUSEDC + j];
            int d = j - I0;
#pragma unroll
            for (int r = 0; r < 8; r++) val += ak[k * 8 + r] * bk[r * DHEAD + d];
        } else if (j < I2) {
            val = in[(size_t)k * FUSEDC + j];
            int d = j - I1;
#pragma unroll
            for (int r = 0; r < 8; r++) val += av[k * 8 + r] * bv[r * DHEAD + d];
        } else if (j < FQKV) {
            val = 0.f;
        } else {
            int p = j - FQKV;
            val = in[(size_t)k * FUSEDC + I2 + (p >> 1) + (p & 1) * FFINNER];
        }
        t[ty + 8 * i][tx] = val;
    }
    __syncthreads();
#pragma unroll
    for (int i = 0; i < 4; i++)
        out[(size_t)(n0 + ty + 8 * i) * DIMX + k0 + tx] = __float2half(t[tx][ty + 8 * i]);
}

// ---------------- layernorm (fp16 out) ----------------
__global__ void ln_kernel(const float* __restrict__ x, const float* __restrict__ gamma,
                          __half* __restrict__ xn16) {
    int row = blockIdx.x;
    const float* xr = x + (size_t)row * DIMX;
    float s = 0.f, s2 = 0.f;
    for (int i = threadIdx.x; i < DIMX; i += 256) { float v = xr[i]; s += v; s2 += v * v; }
    for (int o = 16; o > 0; o >>= 1) {
        s  += __shfl_xor_sync(0xffffffff, s,  o);
        s2 += __shfl_xor_sync(0xffffffff, s2, o);
    }
    __shared__ float sh[16];
    int wid = threadIdx.x >> 5, lane = threadIdx.x & 31;
    if (lane == 0) { sh[wid] = s; sh[8 + wid] = s2; }
    __syncthreads();
    if (threadIdx.x == 0) {
        float S = 0.f, S2 = 0.f;
        for (int w = 0; w < 8; w++) { S += sh[w]; S2 += sh[8 + w]; }
        sh[0] = S; sh[8] = S2;
    }
    __syncthreads();
    float mu = sh[0] * (1.f / DIMX);
    float var = sh[8] * (1.f / DIMX) - mu * mu;
    float inv = rsqrtf(var + 1e-5f);
    __half* o16 = xn16 + (size_t)row * DIMX;
    for (int i = threadIdx.x; i < DIMX; i += 256)
        o16[i] = __float2half((xr[i] - mu) * inv * gamma[i]);
}

// ---------------- qkv prep (LoRA pre-folded into weights) ----------------
__global__ void qkv_prep(const float* __restrict__ F,
                         float* __restrict__ Q, float* __restrict__ Kv, float* __restrict__ V) {
    int row = blockIdx.x;
    int n = row % NSEQ;
    __shared__ float qs[AINNER];
    __shared__ float ks[DHEAD];
    const float* Fr = F + (size_t)row * FQKV;

    for (int c = threadIdx.x; c < AINNER; c += 256) qs[c] = Fr[c];
    if (threadIdx.x < DHEAD) {
        ks[threadIdx.x] = Fr[I0 + threadIdx.x];
        V[(size_t)row * DHEAD + threadIdx.x] = Fr[I1 + threadIdx.x];
    }
    __syncthreads();

    const float ln10k_inv32 = 9.2103403719761836f / 32.f;
    const float scale = 0.125f;
    for (int c = threadIdx.x; c < AINNER; c += 256) {
        int h = c >> 6, d = c & 63;
        int fi = d & 31;
        float freq = (float)n * __expf(-(float)fi * ln10k_inv32);
        float cs = cosf(freq), sn = sinf(freq);
        float me = qs[c];
        float partner = (d < 32) ? -qs[h * 64 + d + 32] : qs[h * 64 + d - 32];
        Q[(size_t)row * AINNER + c] = (me * cs + partner * sn) * scale;
    }
    if (threadIdx.x < DHEAD) {
        int d = threadIdx.x;
        int fi = d & 31;
        float freq = (float)n * __expf(-(float)fi * ln10k_inv32);
        float cs = cosf(freq), sn = sinf(freq);
        float me = ks[d];
        float partner = (d < 32) ? -ks[d + 32] : ks[d - 32];
        Kv[(size_t)row * DHEAD + d] = me * cs + partner * sn;
    }
}

// ================= fp16 MMA flash attention =================
// smem: QsF[64][68] fp32 | Kh[64][72] fp16 | Kl[64][72] fp16 | Vp[32][144] fp16
// Vp: key-pair packed: word (pair p, d) = half2(V[2p][d], V[2p+1][d]), stride 72 words.
#define QS_W 4352                    // 64*68 floats
#define KROW 36                      // K row stride in words (72 halves)
#define VROW 72                      // V pair-row stride in words
#define ATTN_SMEM ((QS_W + 64*KROW*2 + 32*VROW)*4)   // 45056 B

__global__ __launch_bounds__(128) void attn_mma(const float* __restrict__ Qg,
                                                const float* __restrict__ Kg,
                                                const float* __restrict__ Vg,
                                                __half* __restrict__ O16) {
    extern __shared__ float sm[];
    float* Qs = sm;
    uint32_t* Kh = (uint32_t*)(sm + QS_W);
    uint32_t* Kl = Kh + 64 * KROW;
    uint32_t* Vp = Kl + 64 * KROW;

    const int tid = threadIdx.x, wid = tid >> 5, lane = tid & 31;
    const int gq = lane >> 2, tq = lane & 3;
    const int qt = gridDim.x - 1 - blockIdx.x;
    const int h = blockIdx.y, b = blockIdx.z;
    const int q0 = qt * 64;

    for (int i = tid; i < 1024; i += 128) {
        int r = i >> 4, d4 = (i & 15) * 4;
        *(float4*)(Qs + r * 68 + d4) =
            *(const float4*)(Qg + (size_t)(b * NSEQ + q0 + r) * AINNER + h * 64 + d4);
    }
    __syncthreads();

    // Q fragments: hi + residual, rows wid*16+gq(+8), 4 k16 chunks
    uint32_t qh[4][4], ql[4][4];
#pragma unroll
    for (int c = 0; c < 4; c++) {
#pragma unroll
        for (int e = 0; e < 4; e++) {
            int rr = wid * 16 + gq + (e & 1) * 8;
            int cc = c * 16 + (e >> 1) * 8 + 2 * tq;
            float v0 = Qs[rr * 68 + cc], v1 = Qs[rr * 68 + cc + 1];
            __half h0 = __float2half_rn(v0), h1 = __float2half_rn(v1);
            qh[c][e] = pack_h2(__half2float(h0), 0.f) ;   // placeholder, fixed below
            // pack properly:
            __half2 hh = __halves2half2(h0, h1);
            qh[c][e] = *(uint32_t*)&hh;
            __half l0 = __float2half_rn(v0 - __half2float(h0));
            __half l1 = __float2half_rn(v1 - __half2float(h1));
            __half2 ll = __halves2half2(l0, l1);
            ql[c][e] = *(uint32_t*)&ll;
        }
    }

    float o[8][4];
#pragma unroll
    for (int nt = 0; nt < 8; nt++)
#pragma unroll
        for (int e = 0; e < 4; e++) o[nt][e] = 0.f;
    float m0 = -FLT_MAX, m1 = -FLT_MAX, l0s = 0.f, l1s = 0.f;

    const float* Kb = Kg + (size_t)b * NSEQ * DHEAD;
    const float* Vb = Vg + (size_t)b * NSEQ * DHEAD;

    for (int j0 = 0; j0 <= q0; j0 += 64) {
        __syncthreads();
        // load K (hi/lo fp16) and V (pair-packed fp16)
        for (int i = tid; i < 1024; i += 128) {
            int r = i >> 4, d4 = (i & 15) * 4;
            float4 kv = *(const float4*)(Kb + (size_t)(j0 + r) * DHEAD + d4);
            __half h0 = __float2half_rn(kv.x), h1 = __float2half_rn(kv.y);
            __half h2 = __float2half_rn(kv.z), h3 = __float2half_rn(kv.w);
            __half2 p01 = __halves2half2(h0, h1), p23 = __halves2half2(h2, h3);
            Kh[r * KROW + d4 / 2]     = *(uint32_t*)&p01;
            Kh[r * KROW + d4 / 2 + 1] = *(uint32_t*)&p23;
            __half2 l01 = __halves2half2(__float2half_rn(kv.x - __half2float(h0)),
                                         __float2half_rn(kv.y - __half2float(h1)));
            __half2 l23 = __halves2half2(__float2half_rn(kv.z - __half2float(h2)),
                                         __float2half_rn(kv.w - __half2float(h3)));
            Kl[r * KROW + d4 / 2]     = *(uint32_t*)&l01;
            Kl[r * KROW + d4 / 2 + 1] = *(uint32_t*)&l23;

            float4 vv = *(const float4*)(Vb + (size_t)(j0 + r) * DHEAD + d4);
            __half* vh = (__half*)Vp;
            int p = r >> 1, half_sel = r & 1;
            vh[(p * VROW + d4) * 2 + half_sel]       = __float2half_rn(vv.x);
            vh[(p * VROW + d4 + 1) * 2 + half_sel]   = __float2half_rn(vv.y);
            vh[(p * VROW + d4 + 2) * 2 + half_sel]   = __float2half_rn(vv.z);
            vh[(p * VROW + d4 + 3) * 2 + half_sel]   = __float2half_rn(vv.w);
        }
        __syncthreads();

        // S = Q @ K^T  (3-pass fp16 split)
        float s[8][4];
#pragma unroll
        for (int nt = 0; nt < 8; nt++) {
            s[nt][0] = s[nt][1] = s[nt][2] = s[nt][3] = 0.f;
            const uint32_t* khr = Kh + (nt * 8 + gq) * KROW;
            const uint32_t* klr = Kl + (nt * 8 + gq) * KROW;
#pragma unroll
            for (int c = 0; c < 4; c++) {
                uint32_t bh[2] = { khr[c * 8 + tq], khr[c * 8 + 4 + tq] };
                uint32_t bl[2] = { klr[c * 8 + tq], klr[c * 8 + 4 + tq] };
                mma_f16(s[nt], qh[c], bh);
                mma_f16(s[nt], ql[c], bh);
                mma_f16(s[nt], qh[c], bl);
            }
        }

        // causal mask (diagonal chunk)
        if (j0 == q0) {
            int r0 = wid * 16 + gq, r1 = r0 + 8;
#pragma unroll
            for (int nt = 0; nt < 8; nt++) {
                int jc = nt * 8 + 2 * tq;
                if (jc     > r0) s[nt][0] = -1e30f;
                if (jc + 1 > r0) s[nt][1] = -1e30f;
                if (jc     > r1) s[nt][2] = -1e30f;
                if (jc + 1 > r1) s[nt][3] = -1e30f;
            }
        }

        // online softmax
        float rx0 = -1e30f, rx1 = -1e30f;
#pragma unroll
        for (int nt = 0; nt < 8; nt++) {
            rx0 = fmaxf(rx0, fmaxf(s[nt][0], s[nt][1]));
            rx1 = fmaxf(rx1, fmaxf(s[nt][2], s[nt][3]));
        }
        rx0 = fmaxf(rx0, __shfl_xor_sync(0xffffffff, rx0, 1));
        rx0 = fmaxf(rx0, __shfl_xor_sync(0xffffffff, rx0, 2));
        rx1 = fmaxf(rx1, __shfl_xor_sync(0xffffffff, rx1, 1));
        rx1 = fmaxf(rx1, __shfl_xor_sync(0xffffffff, rx1, 2));
        float mn0 = fmaxf(m0, rx0), mn1 = fmaxf(m1, rx1);
        float c0 = __expf(m0 - mn0), c1 = __expf(m1 - mn1);
        float ps0 = 0.f, ps1 = 0.f;
#pragma unroll
        for (int nt = 0; nt < 8; nt++) {
            s[nt][0] = __expf(s[nt][0] - mn0);
            s[nt][1] = __expf(s[nt][1] - mn0);
            s[nt][2] = __expf(s[nt][2] - mn1);
            s[nt][3] = __expf(s[nt][3] - mn1);
            ps0 += s[nt][0] + s[nt][1];
            ps1 += s[nt][2] + s[nt][3];
        }
        ps0 += __shfl_xor_sync(0xffffffff, ps0, 1);
        ps0 += __shfl_xor_sync(0xffffffff, ps0, 2);
        ps1 += __shfl_xor_sync(0xffffffff, ps1, 1);
        ps1 += __shfl_xor_sync(0xffffffff, ps1, 2);
        l0s = l0s * c0 + ps0;
        l1s = l1s * c1 + ps1;
#pragma unroll
        for (int nt = 0; nt < 8; nt++) {
            o[nt][0] *= c0; o[nt][1] *= c0;
            o[nt][2] *= c1; o[nt][3] *= c1;
        }
        m0 = mn0; m1 = mn1;

        // P A-fragments: identity mapping (no shuffles!) — chunk kc covers
        // keys 16kc..16kc+15 = nt tiles {2kc, 2kc+1}
        uint32_t ap[4][4];
#pragma unroll
        for (int kc = 0; kc < 4; kc++) {
            ap[kc][0] = pack_h2(s[2 * kc][0],     s[2 * kc][1]);
            ap[kc][1] = pack_h2(s[2 * kc][2],     s[2 * kc][3]);
            ap[kc][2] = pack_h2(s[2 * kc + 1][0], s[2 * kc + 1][1]);
            ap[kc][3] = pack_h2(s[2 * kc + 1][2], s[2 * kc + 1][3]);
        }

        // O += P @ V  (fp16 single pass)
#pragma unroll
        for (int nt = 0; nt < 8; nt++) {
            int d = nt * 8 + gq;
#pragma unroll
            for (int kc = 0; kc < 4; kc++) {
                uint32_t bv[2] = { Vp[(kc * 8 + tq) * VROW + d],
                                   Vp[(kc * 8 + 4 + tq) * VROW + d] };
                mma_f16(o[nt], ap[kc], bv);
            }
        }
    }

    float il0 = 1.f / l0s, il1 = 1.f / l1s;
    int rg0 = b * NSEQ + q0 + wid * 16 + gq;
#pragma unroll
    for (int nt = 0; nt < 8; nt++) {
        int col = h * 64 + nt * 8 + 2 * tq;
        *(__half2*)(O16 + (size_t)rg0 * KC + col) =
            __floats2half2_rn(o[nt][0] * il0, o[nt][1] * il0);
        *(__half2*)(O16 + (size_t)(rg0 + 8) * KC + col) =
            __floats2half2_rn(o[nt][2] * il1, o[nt][3] * il1);
    }
}

// ---------------- launch ----------------
extern "C" void kernel_launch(void* const* d_in, const int* in_sizes, int n_in,
                              void* d_out, int out_size) {
    const float* x          = (const float*)d_in[0];
    const float* gamma      = (const float*)d_in[1];
    const float* w_fused    = (const float*)d_in[2];
    const float* w_attn_out = (const float*)d_in[3];
    const float* w_ff_out   = (const float*)d_in[4];
    const float* a_q        = (const float*)d_in[5];
    const float* b_q        = (const float*)d_in[6];
    const float* a_k        = (const float*)d_in[7];
    const float* b_k        = (const float*)d_in[8];
    const float* a_v        = (const float*)d_in[9];
    const float* b_v        = (const float*)d_in[10];
    const float* a_o        = (const float*)d_in[11];
    const float* b_o        = (const float*)d_in[12];
    float* out = (float*)d_out;

    float *F, *Q, *K, *V;
    __half *XN16, *WF16, *AC16, *WC16;
    cudaGetSymbolAddress((void**)&XN16, g_XN16);
    cudaGetSymbolAddress((void**)&WF16, g_WF16);
    cudaGetSymbolAddress((void**)&F, g_F);
    cudaGetSymbolAddress((void**)&Q, g_Q);
    cudaGetSymbolAddress((void**)&K, g_K);
    cudaGetSymbolAddress((void**)&V, g_V);
    cudaGetSymbolAddress((void**)&AC16, g_AC16);
    cudaGetSymbolAddress((void**)&WC16, g_WC16);

    cudaFuncSetAttribute(h_gemm, cudaFuncAttributeMaxDynamicSharedMemorySize, HGSMEM);
    cudaFuncSetAttribute(attn_mma, cudaFuncAttributeMaxDynamicSharedMemorySize, ATTN_SMEM);

    // weight prep with LoRA folding
    w_t16_perm<<<dim3(FPAD / 32, DIMX / 32), dim3(32, 8)>>>(w_fused, WF16,
                                                            a_q, b_q, a_k, b_k, a_v, b_v);
    w_t16s<<<dim3(DIMX / 32, AINNER / 32), dim3(32, 8)>>>(w_attn_out, WC16, AINNER, DIMX, KC, 0,
                                                          a_o, b_o);
    w_t16s<<<dim3(DIMX / 32, FFINNER / 32), dim3(32, 8)>>>(w_ff_out, WC16, FFINNER, DIMX, KC, KOFF,
                                                           nullptr, nullptr);

    ln_kernel<<<ROWS, 256>>>(x, gamma, XN16);
    h_gemm<<<dim3(ROWS / 128, FPAD / 128), 256, HGSMEM>>>(XN16, WF16, nullptr, F, AC16, FPAD, DIMX, 1);
    qkv_prep<<<ROWS, 256>>>(F, Q, K, V);
    attn_mma<<<dim3(NSEQ / 64, HEADS, BATCH), 128, ATTN_SMEM>>>(Q, K, V, AC16);
    h_gemm<<<dim3(ROWS / 128, DIMX / 128), 256, HGSMEM>>>(AC16, WC16, out, nullptr, nullptr, DIMX, KC, 0);
}